// round 9
// baseline (speedup 1.0000x reference)
#include <cuda_runtime.h>
#include <cuda_bf16.h>
#include <math.h>
#include <stdint.h>

#define B_ 8
#define M_ 1024
#define D_ 1024
#define H_ 16
#define F_ 4096
#define NLAYERS 4
#define DK_ 64
#define ROWS (B_*M_)

typedef __nv_bfloat16 bf16;

// ---------------- device scratch ----------------
__device__ float g_x  [ROWS * D_];
__device__ float g_res[ROWS * D_];
__device__ bf16  g_xb [ROWS * D_];
__device__ bf16  g_xs [ROWS * D_];
__device__ bf16  g_qb [ROWS * D_];
__device__ bf16  g_qs [ROWS * D_];
__device__ bf16  g_kb [ROWS * D_];
__device__ bf16  g_ks [ROWS * D_];
__device__ bf16  g_vb [ROWS * D_];
__device__ bf16  g_vs [ROWS * D_];
__device__ bf16  g_ob [ROWS * D_];
__device__ bf16  g_os [ROWS * D_];
__device__ bf16  g_fb [ROWS * F_];
__device__ bf16  g_fs [ROWS * F_];
__device__ bf16 g_wqb[NLAYERS*D_*D_]; __device__ bf16 g_wqs[NLAYERS*D_*D_];
__device__ bf16 g_wkb[NLAYERS*D_*D_]; __device__ bf16 g_wks[NLAYERS*D_*D_];
__device__ bf16 g_wvb[NLAYERS*D_*D_]; __device__ bf16 g_wvs[NLAYERS*D_*D_];
__device__ bf16 g_wob[NLAYERS*D_*D_]; __device__ bf16 g_wos[NLAYERS*D_*D_];
__device__ bf16 g_w1b[NLAYERS*D_*F_]; __device__ bf16 g_w1s[NLAYERS*D_*F_];
__device__ bf16 g_w2b[NLAYERS*F_*D_]; __device__ bf16 g_w2s[NLAYERS*F_*D_];

// ---------------- helpers ----------------
__device__ __forceinline__ uint32_t smem_to_u32(const void* p) {
    uint32_t a;
    asm("{ .reg .u64 t; cvta.to.shared.u64 t, %1; cvt.u32.u64 %0, t; }" : "=r"(a) : "l"(p));
    return a;
}
__device__ __forceinline__ float gelu_exact(float x) {
    return 0.5f * x * (1.0f + erff(x * 0.70710678118654752f));
}
__device__ __forceinline__ void split_bf(float y, bf16& b, bf16& s) {
    b = __float2bfloat16_rn(y);
    s = __float2bfloat16_rn(y - __bfloat162float(b));
}
__device__ __forceinline__ uint32_t pack_bf2(bf16 a, bf16 b) {
    __nv_bfloat162 t(a, b);
    return *reinterpret_cast<uint32_t*>(&t);
}

#define CP_ASYNC16(dst, src) \
    asm volatile("cp.async.cg.shared.global [%0], [%1], 16;" :: "r"(dst), "l"(src))
#define CP_COMMIT() asm volatile("cp.async.commit_group;")
#define CP_WAIT(n)  asm volatile("cp.async.wait_group %0;" :: "n"(n))

#define MMA_BF16(d, a, b) \
    asm volatile("mma.sync.aligned.m16n8k16.row.col.f32.bf16.bf16.f32 " \
        "{%0,%1,%2,%3}, {%4,%5,%6,%7}, {%8,%9}, {%0,%1,%2,%3};" \
        : "+f"((d)[0]), "+f"((d)[1]), "+f"((d)[2]), "+f"((d)[3]) \
        : "r"((a)[0]), "r"((a)[1]), "r"((a)[2]), "r"((a)[3]), \
          "r"((b)[0]), "r"((b)[1]))

#define LDSM_X4_T(r0, r1, r2, r3, addr) \
    asm volatile("ldmatrix.sync.aligned.m8n8.x4.trans.shared.b16 {%0,%1,%2,%3}, [%4];" \
        : "=r"(r0), "=r"(r1), "=r"(r2), "=r"(r3) : "r"(addr))

// ---------------- 3xBF16 GEMM: CTA 128x256, warp tile 64x64 ----------------
#define CHUNK 32
#define RSU   20                      // u32 per row (64B data + 16B pad)
#define A_U32 (128 * RSU)             // 2560
#define B_U32 (256 * RSU)             // 5120
#define STG_U32 (2 * A_U32 + 2 * B_U32)   // 15360 u32 = 61440 B
#define OFF_AB 0
#define OFF_AS (A_U32)
#define OFF_BB (2 * A_U32)
#define OFF_BS (2 * A_U32 + B_U32)
#define GSMEM_BYTES (2 * STG_U32 * 4)     // 122880

template<bool GELU, bool WPLAIN, bool WSPLIT>
__global__ __launch_bounds__(256, 1) void gemm_mma(
    const bf16* __restrict__ Ab, const bf16* __restrict__ As,
    const bf16* __restrict__ Bb, const bf16* __restrict__ Bs,
    const float* __restrict__ bias,
    float* __restrict__ Cp, bf16* __restrict__ Cb, bf16* __restrict__ Cs,
    int K, int N)
{
    extern __shared__ uint32_t smem[];
    const int tid  = threadIdx.x;
    const int wid  = tid >> 5;
    const int lane = tid & 31;
    const int m0 = blockIdx.y * 128;
    const int n0 = blockIdx.x * 256;
    const int wm = wid & 1;          // 64-row slab (2)
    const int wn = wid >> 1;         // 64-col slab (4)
    const uint32_t sbase = smem_to_u32(smem);

    float acc[4][8][4];
#pragma unroll
    for (int i = 0; i < 4; i++)
#pragma unroll
        for (int j = 0; j < 8; j++)
#pragma unroll
            for (int r = 0; r < 4; r++) acc[i][j][r] = 0.0f;

    const int nch = K / CHUNK;

    auto load_stage = [&](int stage, int kc) {
        const uint32_t st = sbase + (uint32_t)stage * STG_U32 * 4;
#pragma unroll
        for (int t = 0; t < 2; t++) {       // A: 512 segs
            const int seg = tid + t * 256;
            const int row = seg >> 2, q = seg & 3;
            const uint32_t soff = (uint32_t)row * 80 + q * 16;
            const size_t aofg = (size_t)(m0 + row) * K + kc + q * 8;
            CP_ASYNC16(st + OFF_AB * 4 + soff, Ab + aofg);
            CP_ASYNC16(st + OFF_AS * 4 + soff, As + aofg);
        }
#pragma unroll
        for (int t = 0; t < 4; t++) {       // B: 1024 segs
            const int seg = tid + t * 256;
            const int row = seg >> 2, q = seg & 3;
            const uint32_t soff = (uint32_t)row * 80 + q * 16;
            const size_t bofg = (size_t)(n0 + row) * K + kc + q * 8;
            CP_ASYNC16(st + OFF_BB * 4 + soff, Bb + bofg);
            CP_ASYNC16(st + OFF_BS * 4 + soff, Bs + bofg);
        }
    };

    load_stage(0, 0);
    CP_COMMIT();

    const int lr = lane >> 2;
    const int lc = lane & 3;

    for (int c = 0; c < nch; c++) {
        if (c + 1 < nch) {
            load_stage((c + 1) & 1, (c + 1) * CHUNK);
            CP_COMMIT();
            CP_WAIT(1);
        } else {
            CP_WAIT(0);
        }
        __syncthreads();

        const uint32_t* sAb = smem + (size_t)(c & 1) * STG_U32 + OFF_AB;
        const uint32_t* sAs = smem + (size_t)(c & 1) * STG_U32 + OFF_AS;
        const uint32_t* sBb = smem + (size_t)(c & 1) * STG_U32 + OFF_BB;
        const uint32_t* sBs = smem + (size_t)(c & 1) * STG_U32 + OFF_BS;

#pragma unroll
        for (int ks = 0; ks < 2; ks++) {
            const int kc = ks * 8;
            uint32_t bfb[8][2], bfs[8][2];
#pragma unroll
            for (int j = 0; j < 8; j++) {
                const int base = (wn * 64 + j * 8 + lr) * RSU + kc + lc;
                bfb[j][0] = sBb[base];
                bfb[j][1] = sBb[base + 4];
                bfs[j][0] = sBs[base];
                bfs[j][1] = sBs[base + 4];
            }
            uint32_t afb[4][4], afs[4][4];
#pragma unroll
            for (int i = 0; i < 4; i++) {
                const int base = (wm * 64 + i * 16 + lr) * RSU + kc + lc;
                afb[i][0] = sAb[base];
                afb[i][1] = sAb[base + 8 * RSU];
                afb[i][2] = sAb[base + 4];
                afb[i][3] = sAb[base + 8 * RSU + 4];
                afs[i][0] = sAs[base];
                afs[i][1] = sAs[base + 8 * RSU];
                afs[i][2] = sAs[base + 4];
                afs[i][3] = sAs[base + 8 * RSU + 4];
            }
            // term-major ordering: consecutive MMAs independent
#pragma unroll
            for (int i = 0; i < 4; i++)
#pragma unroll
                for (int j = 0; j < 8; j++)
                    MMA_BF16(acc[i][j], afb[i], bfb[j]);
#pragma unroll
            for (int i = 0; i < 4; i++)
#pragma unroll
                for (int j = 0; j < 8; j++)
                    MMA_BF16(acc[i][j], afb[i], bfs[j]);
#pragma unroll
            for (int i = 0; i < 4; i++)
#pragma unroll
                for (int j = 0; j < 8; j++)
                    MMA_BF16(acc[i][j], afs[i], bfb[j]);
        }
        __syncthreads();
    }

#pragma unroll
    for (int i = 0; i < 4; i++) {
#pragma unroll
        for (int j = 0; j < 8; j++) {
            const int gr = m0 + wm * 64 + i * 16 + lr;
            const int gc = n0 + wn * 64 + j * 8 + lc * 2;
            const float b0 = bias[gc], b1 = bias[gc + 1];
#pragma unroll
            for (int half = 0; half < 2; half++) {
                const int row = gr + half * 8;
                float y0 = acc[i][j][half * 2 + 0] + b0;
                float y1 = acc[i][j][half * 2 + 1] + b1;
                if (GELU) { y0 = gelu_exact(y0); y1 = gelu_exact(y1); }
                const size_t o = (size_t)row * N + gc;
                if (WPLAIN) *(float2*)&Cp[o] = make_float2(y0, y1);
                if (WSPLIT) {
                    bf16 hb0, hs0, hb1, hs1;
                    split_bf(y0, hb0, hs0);
                    split_bf(y1, hb1, hs1);
                    *(__nv_bfloat162*)&Cb[o] = __nv_bfloat162(hb0, hb1);
                    *(__nv_bfloat162*)&Cs[o] = __nv_bfloat162(hs0, hs1);
                }
            }
        }
    }
}

// ---------------- MMA flash attention (unchanged from R8) -----------------
#define AT_SMEM 111104

__global__ __launch_bounds__(256) void flash_mma(
    const bf16* __restrict__ qb, const bf16* __restrict__ qs,
    const bf16* __restrict__ kbp, const bf16* __restrict__ ksp,
    const bf16* __restrict__ vbp, const bf16* __restrict__ vsp,
    const float* __restrict__ w,
    bf16* __restrict__ ob, bf16* __restrict__ os)
{
    extern __shared__ uint32_t smem[];
    const uint32_t sb = smem_to_u32(smem);
    const int tid = threadIdx.x, wid = tid >> 5, lane = tid & 31;
    const int lr = lane >> 2, lc = lane & 3;
    const int bidx = blockIdx.y >> 4;
    const int h    = blockIdx.y & 15;
    const int q0   = blockIdx.x * 128;
    const int hoff = h * DK_;
    const size_t bm = (size_t)bidx * M_;

#pragma unroll
    for (int t = 0; t < 4; t++) {
        const int seg = tid + t * 256;
        const int row = seg >> 3, q8 = seg & 7;
        const size_t src = (bm + q0 + row) * D_ + hoff + q8 * 8;
        const uint32_t d = sb + (uint32_t)row * 144 + q8 * 16;
        CP_ASYNC16(d,         qb + src);
        CP_ASYNC16(d + 18432, qs + src);
    }
    auto load_kv = [&](int st, int kb0) {
#pragma unroll
        for (int t = 0; t < 2; t++) {
            const int seg = tid + t * 256;
            const int row = seg >> 3, q8 = seg & 7;
            const size_t src = (bm + kb0 + row) * D_ + hoff + q8 * 8;
            const uint32_t dk = sb + 36864 + st * 18432 + (uint32_t)row * 144 + q8 * 16;
            const uint32_t dv = sb + 73728 + st * 18432 + (uint32_t)row * 144 + q8 * 16;
            CP_ASYNC16(dk,        kbp + src);
            CP_ASYNC16(dk + 9216, ksp + src);
            CP_ASYNC16(dv,        vbp + src);
            CP_ASYNC16(dv + 9216, vsp + src);
        }
        if (tid < 16)
            CP_ASYNC16(sb + 110592 + st * 256 + tid * 16, w + bm + kb0 + tid * 4);
    };
    load_kv(0, 0);
    CP_COMMIT();

    uint32_t aqb[4][4], aqs[4][4];
    float oa[8][4];
    float m0v = -1e30f, m1v = -1e30f, l0 = 0.0f, l1 = 0.0f;
#pragma unroll
    for (int j = 0; j < 8; j++)
#pragma unroll
        for (int r = 0; r < 4; r++) oa[j][r] = 0.0f;

    for (int kb = 0; kb < 16; kb++) {
        const int st = kb & 1;
        if (kb + 1 < 16) {
            load_kv((kb + 1) & 1, (kb + 1) * 64);
            CP_COMMIT();
            CP_WAIT(1);
        } else {
            CP_WAIT(0);
        }
        __syncthreads();

        if (kb == 0) {
#pragma unroll
            for (int ks = 0; ks < 4; ks++) {
                const int base = (wid * 16 + lr) * 36 + ks * 8 + lc;
                aqb[ks][0] = smem[base];
                aqb[ks][1] = smem[base + 288];
                aqb[ks][2] = smem[base + 4];
                aqb[ks][3] = smem[base + 292];
                aqs[ks][0] = smem[base + 4608];
                aqs[ks][1] = smem[base + 4608 + 288];
                aqs[ks][2] = smem[base + 4608 + 4];
                aqs[ks][3] = smem[base + 4608 + 292];
            }
        }

        const uint32_t* skb = smem + 9216 + st * 4608;
        const uint32_t* sks = skb + 2304;
        float s_[8][4];
#pragma unroll
        for (int j = 0; j < 8; j++)
#pragma unroll
            for (int r = 0; r < 4; r++) s_[j][r] = 0.0f;

#pragma unroll
        for (int ks = 0; ks < 4; ks++) {
            uint32_t kfb[8][2], kfs[8][2];
#pragma unroll
            for (int j = 0; j < 8; j++) {
                const int base = (j * 8 + lr) * 36 + ks * 8 + lc;
                kfb[j][0] = skb[base];
                kfb[j][1] = skb[base + 4];
                kfs[j][0] = sks[base];
                kfs[j][1] = sks[base + 4];
            }
#pragma unroll
            for (int j = 0; j < 8; j++) {
                MMA_BF16(s_[j], aqb[ks], kfb[j]);
                MMA_BF16(s_[j], aqb[ks], kfs[j]);
                MMA_BF16(s_[j], aqs[ks], kfb[j]);
            }
        }

        const float* sw = (const float*)smem + 27648 + st * 64;
        float rmax0 = -1e30f, rmax1 = -1e30f;
        float x[8][4];
#pragma unroll
        for (int j = 0; j < 8; j++) {
            const float2 wp = *(const float2*)(sw + j * 8 + 2 * lc);
            x[j][0] = s_[j][0] * 0.125f + wp.x;
            x[j][1] = s_[j][1] * 0.125f + wp.y;
            x[j][2] = s_[j][2] * 0.125f + wp.x;
            x[j][3] = s_[j][3] * 0.125f + wp.y;
            rmax0 = fmaxf(rmax0, fmaxf(x[j][0], x[j][1]));
            rmax1 = fmaxf(rmax1, fmaxf(x[j][2], x[j][3]));
        }
        rmax0 = fmaxf(rmax0, __shfl_xor_sync(0xffffffffu, rmax0, 1));
        rmax0 = fmaxf(rmax0, __shfl_xor_sync(0xffffffffu, rmax0, 2));
        rmax1 = fmaxf(rmax1, __shfl_xor_sync(0xffffffffu, rmax1, 1));
        rmax1 = fmaxf(rmax1, __shfl_xor_sync(0xffffffffu, rmax1, 2));
        const float mn0 = fmaxf(m0v, rmax0);
        const float mn1 = fmaxf(m1v, rmax1);
        const float c0 = __expf(m0v - mn0);
        const float c1 = __expf(m1v - mn1);
        float rs0 = 0.0f, rs1 = 0.0f;
        uint32_t pb01[8], pb23[8], ps01[8], ps23[8];
#pragma unroll
        for (int j = 0; j < 8; j++) {
            const float p0 = __expf(x[j][0] - mn0);
            const float p1 = __expf(x[j][1] - mn0);
            const float p2 = __expf(x[j][2] - mn1);
            const float p3 = __expf(x[j][3] - mn1);
            rs0 += p0 + p1;
            rs1 += p2 + p3;
            bf16 b0, sv0, b1, sv1, b2, sv2, b3, sv3;
            split_bf(p0, b0, sv0); split_bf(p1, b1, sv1);
            split_bf(p2, b2, sv2); split_bf(p3, b3, sv3);
            pb01[j] = pack_bf2(b0, b1);
            pb23[j] = pack_bf2(b2, b3);
            ps01[j] = pack_bf2(sv0, sv1);
            ps23[j] = pack_bf2(sv2, sv3);
        }
        rs0 += __shfl_xor_sync(0xffffffffu, rs0, 1);
        rs0 += __shfl_xor_sync(0xffffffffu, rs0, 2);
        rs1 += __shfl_xor_sync(0xffffffffu, rs1, 1);
        rs1 += __shfl_xor_sync(0xffffffffu, rs1, 2);
        l0 = l0 * c0 + rs0;
        l1 = l1 * c1 + rs1;
        m0v = mn0; m1v = mn1;
#pragma unroll
        for (int j = 0; j < 8; j++) {
            oa[j][0] *= c0; oa[j][1] *= c0;
            oa[j][2] *= c1; oa[j][3] *= c1;
        }

        const uint32_t vbase = sb + 73728 + st * 18432;
        const int lgrp = lane >> 3, l8 = lane & 7;
#pragma unroll
        for (int kp = 0; kp < 4; kp++) {
            const uint32_t apb[4] = { pb01[2*kp], pb23[2*kp], pb01[2*kp+1], pb23[2*kp+1] };
            const uint32_t aps[4] = { ps01[2*kp], ps23[2*kp], ps01[2*kp+1], ps23[2*kp+1] };
            const int vrow = kp * 16 + (lgrp & 1) * 8 + l8;
            const uint32_t va = vbase + (uint32_t)vrow * 144 + (lgrp >> 1) * 16;
            uint32_t vfb[8][2], vfs[8][2];
#pragma unroll
            for (int jn = 0; jn < 4; jn++) {
                LDSM_X4_T(vfb[2*jn][0], vfb[2*jn][1], vfb[2*jn+1][0], vfb[2*jn+1][1], va + jn * 32);
                LDSM_X4_T(vfs[2*jn][0], vfs[2*jn][1], vfs[2*jn+1][0], vfs[2*jn+1][1], va + 9216 + jn * 32);
            }
#pragma unroll
            for (int j2 = 0; j2 < 8; j2++) {
                MMA_BF16(oa[j2], apb, vfb[j2]);
                MMA_BF16(oa[j2], apb, vfs[j2]);
                MMA_BF16(oa[j2], aps, vfb[j2]);
            }
        }
        __syncthreads();
    }

    const float i0 = 1.0f / l0;
    const float i1 = 1.0f / l1;
    const int r0g = q0 + wid * 16 + lr;
#pragma unroll
    for (int j2 = 0; j2 < 8; j2++) {
        const size_t o0 = (bm + r0g) * D_ + hoff + j2 * 8 + 2 * lc;
        const size_t o1 = o0 + 8 * D_;
        bf16 hb0, hs0, hb1, hs1;
        split_bf(oa[j2][0] * i0, hb0, hs0);
        split_bf(oa[j2][1] * i0, hb1, hs1);
        *(__nv_bfloat162*)&ob[o0] = __nv_bfloat162(hb0, hb1);
        *(__nv_bfloat162*)&os[o0] = __nv_bfloat162(hs0, hs1);
        split_bf(oa[j2][2] * i1, hb0, hs0);
        split_bf(oa[j2][3] * i1, hb1, hs1);
        *(__nv_bfloat162*)&ob[o1] = __nv_bfloat162(hb0, hb1);
        *(__nv_bfloat162*)&os[o1] = __nv_bfloat162(hs0, hs1);
    }
}

// ---------------- weight split + transpose ----------------
__global__ __launch_bounds__(256) void wsplit_t(
    const float* __restrict__ W, bf16* __restrict__ Tb, bf16* __restrict__ Ts,
    int K, int N)
{
    __shared__ float t[32][33];
    const int n0 = blockIdx.x * 32, k0 = blockIdx.y * 32;
    const size_t zoff = (size_t)blockIdx.z * K * N;
    const int tx = threadIdx.x, ty = threadIdx.y;
#pragma unroll
    for (int r = ty; r < 32; r += 8)
        t[r][tx] = W[zoff + (size_t)(k0 + r) * N + n0 + tx];
    __syncthreads();
#pragma unroll
    for (int r = ty; r < 32; r += 8) {
        const float v = t[tx][r];
        const size_t o = zoff + (size_t)(n0 + r) * K + k0 + tx;
        bf16 hb, hs;
        split_bf(v, hb, hs);
        Tb[o] = hb;
        Ts[o] = hs;
    }
}

__global__ __launch_bounds__(1024) void split_x(
    const float* __restrict__ e, float* __restrict__ x,
    bf16* __restrict__ xb, bf16* __restrict__ xs)
{
    const size_t i = (size_t)blockIdx.x * 1024 + threadIdx.x;
    const float v = e[i];
    x[i] = v;
    bf16 hb, hs;
    split_bf(v, hb, hs);
    xb[i] = hb;
    xs[i] = hs;
}

// ---------------- residual + LayerNorm (+bf16 split out) ------------------
__device__ __forceinline__ float block_sum256(float val, float* red) {
    const int lane = threadIdx.x & 31;
    const int wid  = threadIdx.x >> 5;
#pragma unroll
    for (int o = 16; o > 0; o >>= 1) val += __shfl_xor_sync(0xffffffffu, val, o);
    if (lane == 0) red[wid] = val;
    __syncthreads();
    float t = (threadIdx.x < 8) ? red[threadIdx.x] : 0.0f;
    if (wid == 0) {
#pragma unroll
        for (int o = 4; o > 0; o >>= 1) t += __shfl_xor_sync(0xffffffffu, t, o);
        if (lane == 0) red[0] = t;
    }
    __syncthreads();
    float r = red[0];
    __syncthreads();
    return r;
}

__global__ __launch_bounds__(256) void add_ln(
    const float* __restrict__ xin, const float* __restrict__ del,
    const float* __restrict__ g, const float* __restrict__ be,
    float* __restrict__ xout, bf16* __restrict__ xb, bf16* __restrict__ xs)
{
    __shared__ float red[8];
    const int row = blockIdx.x;
    const int tid = threadIdx.x;
    const float* xr = xin + (size_t)row * D_;
    const float* dr = del + (size_t)row * D_;

    float v[4];
    float s = 0.0f;
#pragma unroll
    for (int u = 0; u < 4; u++) {
        v[u] = xr[tid + u * 256] + dr[tid + u * 256];
        s += v[u];
    }
    const float mu = block_sum256(s, red) * (1.0f / D_);
    float qs = 0.0f;
#pragma unroll
    for (int u = 0; u < 4; u++) {
        const float d = v[u] - mu;
        qs += d * d;
    }
    const float var = block_sum256(qs, red) * (1.0f / D_);
    const float rstd = rsqrtf(var + 1e-5f);
#pragma unroll
    for (int u = 0; u < 4; u++) {
        const int c = tid + u * 256;
        const size_t o = (size_t)row * D_ + c;
        const float y = (v[u] - mu) * rstd * g[c] + be[c];
        xout[o] = y;
        bf16 hb, hs;
        split_bf(y, hb, hs);
        xb[o] = hb;
        xs[o] = hs;
    }
}

// ---------------- host driver ----------------
extern "C" void kernel_launch(void* const* d_in, const int* in_sizes, int n_in,
                              void* d_out, int out_size) {
    const float* embeds  = (const float*)d_in[0];
    const float* weights = (const float*)d_in[1];
    const float* Wq = (const float*)d_in[2];
    const float* bq = (const float*)d_in[3];
    const float* Wk = (const float*)d_in[4];
    const float* bk = (const float*)d_in[5];
    const float* Wv = (const float*)d_in[6];
    const float* bv = (const float*)d_in[7];
    const float* Wo = (const float*)d_in[8];
    const float* bo = (const float*)d_in[9];
    const float* W1 = (const float*)d_in[10];
    const float* b1 = (const float*)d_in[11];
    const float* W2 = (const float*)d_in[12];
    const float* b2 = (const float*)d_in[13];
    const float* g1 = (const float*)d_in[14];
    const float* be1= (const float*)d_in[15];
    const float* g2 = (const float*)d_in[16];
    const float* be2= (const float*)d_in[17];

    float *px, *pres;
    bf16 *pxb,*pxs,*pqb,*pqs,*pkb,*pks,*pvb,*pvs,*pob,*pos,*pfb,*pfs;
    bf16 *pwqb,*pwqs,*pwkb,*pwks,*pwvb,*pwvs,*pwob,*pwos,*pw1b,*pw1s,*pw2b,*pw2s;
    cudaGetSymbolAddress((void**)&px,  g_x);
    cudaGetSymbolAddress((void**)&pres,g_res);
    cudaGetSymbolAddress((void**)&pxb, g_xb);
    cudaGetSymbolAddress((void**)&pxs, g_xs);
    cudaGetSymbolAddress((void**)&pqb, g_qb);
    cudaGetSymbolAddress((void**)&pqs, g_qs);
    cudaGetSymbolAddress((void**)&pkb, g_kb);
    cudaGetSymbolAddress((void**)&pks, g_ks);
    cudaGetSymbolAddress((void**)&pvb, g_vb);
    cudaGetSymbolAddress((void**)&pvs, g_vs);
    cudaGetSymbolAddress((void**)&pob, g_ob);
    cudaGetSymbolAddress((void**)&pos, g_os);
    cudaGetSymbolAddress((void**)&pfb, g_fb);
    cudaGetSymbolAddress((void**)&pfs, g_fs);
    cudaGetSymbolAddress((void**)&pwqb,g_wqb); cudaGetSymbolAddress((void**)&pwqs,g_wqs);
    cudaGetSymbolAddress((void**)&pwkb,g_wkb); cudaGetSymbolAddress((void**)&pwks,g_wks);
    cudaGetSymbolAddress((void**)&pwvb,g_wvb); cudaGetSymbolAddress((void**)&pwvs,g_wvs);
    cudaGetSymbolAddress((void**)&pwob,g_wob); cudaGetSymbolAddress((void**)&pwos,g_wos);
    cudaGetSymbolAddress((void**)&pw1b,g_w1b); cudaGetSymbolAddress((void**)&pw1s,g_w1s);
    cudaGetSymbolAddress((void**)&pw2b,g_w2b); cudaGetSymbolAddress((void**)&pw2s,g_w2s);

    cudaFuncSetAttribute(gemm_mma<false, true, false>,
                         cudaFuncAttributeMaxDynamicSharedMemorySize, GSMEM_BYTES);
    cudaFuncSetAttribute(gemm_mma<true, false, true>,
                         cudaFuncAttributeMaxDynamicSharedMemorySize, GSMEM_BYTES);
    cudaFuncSetAttribute(gemm_mma<false, false, true>,
                         cudaFuncAttributeMaxDynamicSharedMemorySize, GSMEM_BYTES);
    cudaFuncSetAttribute(flash_mma,
                         cudaFuncAttributeMaxDynamicSharedMemorySize, AT_SMEM);

    wsplit_t<<<dim3(D_/32, D_/32, NLAYERS), dim3(32, 8)>>>(Wq, pwqb, pwqs, D_, D_);
    wsplit_t<<<dim3(D_/32, D_/32, NLAYERS), dim3(32, 8)>>>(Wk, pwkb, pwks, D_, D_);
    wsplit_t<<<dim3(D_/32, D_/32, NLAYERS), dim3(32, 8)>>>(Wv, pwvb, pwvs, D_, D_);
    split_x<<<ROWS * D_ / 1024, 1024>>>(embeds, px, pxb, pxs);

    const dim3 gD(D_ / 256, ROWS / 128);   // (4, 64)
    const dim3 gF(F_ / 256, ROWS / 128);   // (16, 64)
    const dim3 gA(M_ / 128, B_ * H_);      // (8, 128)

    for (int l = 0; l < NLAYERS; l++) {
        gemm_mma<false, false, true><<<gD, 256, GSMEM_BYTES>>>(
            pxb, pxs, pwqb + (size_t)l*D_*D_, pwqs + (size_t)l*D_*D_,
            bq + (size_t)l*D_, nullptr, pqb, pqs, D_, D_);
        gemm_mma<false, false, true><<<gD, 256, GSMEM_BYTES>>>(
            pxb, pxs, pwkb + (size_t)l*D_*D_, pwks + (size_t)l*D_*D_,
            bk + (size_t)l*D_, nullptr, pkb, pks, D_, D_);
        gemm_mma<false, false, true><<<gD, 256, GSMEM_BYTES>>>(
            pxb, pxs, pwvb + (size_t)l*D_*D_, pwvs + (size_t)l*D_*D_,
            bv + (size_t)l*D_, nullptr, pvb, pvs, D_, D_);

        if (l == 0) {
            wsplit_t<<<dim3(D_/32, D_/32, NLAYERS), dim3(32, 8)>>>(Wo, pwob, pwos, D_, D_);
            wsplit_t<<<dim3(F_/32, D_/32, NLAYERS), dim3(32, 8)>>>(W1, pw1b, pw1s, D_, F_);
            wsplit_t<<<dim3(D_/32, F_/32, NLAYERS), dim3(32, 8)>>>(W2, pw2b, pw2s, F_, D_);
        }

        flash_mma<<<gA, 256, AT_SMEM>>>(pqb, pqs, pkb, pks, pvb, pvs,
                                        weights, pob, pos);

        gemm_mma<false, true, false><<<gD, 256, GSMEM_BYTES>>>(
            pob, pos, pwob + (size_t)l*D_*D_, pwos + (size_t)l*D_*D_,
            bo + (size_t)l*D_, pres, nullptr, nullptr, D_, D_);
        add_ln<<<ROWS, 256>>>(px, pres, g1 + (size_t)l*D_, be1 + (size_t)l*D_,
                              px, pxb, pxs);

        gemm_mma<true, false, true><<<gF, 256, GSMEM_BYTES>>>(
            pxb, pxs, pw1b + (size_t)l*D_*F_, pw1s + (size_t)l*D_*F_,
            b1 + (size_t)l*F_, nullptr, pfb, pfs, D_, F_);
        gemm_mma<false, true, false><<<gD, 256, GSMEM_BYTES>>>(
            pfb, pfs, pw2b + (size_t)l*F_*D_, pw2s + (size_t)l*F_*D_,
            b2 + (size_t)l*D_, pres, nullptr, nullptr, F_, D_);
        add_ln<<<ROWS, 256>>>(px, pres, g2 + (size_t)l*D_, be2 + (size_t)l*D_,
                              px, pxb, pxs);
    }

    cudaMemcpyAsync(d_out, px, sizeof(float) * (size_t)ROWS * D_,
                    cudaMemcpyDeviceToDevice);
}

// round 10
// speedup vs baseline: 1.0475x; 1.0475x over previous
#include <cuda_runtime.h>
#include <cuda_bf16.h>
#include <math.h>
#include <stdint.h>

#define B_ 8
#define M_ 1024
#define D_ 1024
#define H_ 16
#define F_ 4096
#define NLAYERS 4
#define DK_ 64
#define ROWS (B_*M_)
#define QS_ (3*D_)   // fused qkv row stride

typedef __nv_bfloat16 bf16;

// ---------------- device scratch ----------------
__device__ float g_x   [ROWS * D_];
__device__ float g_res [ROWS * D_];
__device__ float g_bqkv[NLAYERS * QS_];
__device__ bf16  g_xb  [ROWS * D_];
__device__ bf16  g_xs  [ROWS * D_];
__device__ bf16  g_qkvb[ROWS * QS_];
__device__ bf16  g_qkvs[ROWS * QS_];
__device__ bf16  g_ob  [ROWS * D_];
__device__ bf16  g_os  [ROWS * D_];
__device__ bf16  g_fb  [ROWS * F_];
__device__ bf16  g_fs  [ROWS * F_];
__device__ bf16 g_wqkvb[NLAYERS*3*D_*D_]; __device__ bf16 g_wqkvs[NLAYERS*3*D_*D_];
__device__ bf16 g_wob[NLAYERS*D_*D_];     __device__ bf16 g_wos[NLAYERS*D_*D_];
__device__ bf16 g_w1b[NLAYERS*D_*F_];     __device__ bf16 g_w1s[NLAYERS*D_*F_];
__device__ bf16 g_w2b[NLAYERS*F_*D_];     __device__ bf16 g_w2s[NLAYERS*F_*D_];

// ---------------- helpers ----------------
__device__ __forceinline__ uint32_t smem_to_u32(const void* p) {
    uint32_t a;
    asm("{ .reg .u64 t; cvta.to.shared.u64 t, %1; cvt.u32.u64 %0, t; }" : "=r"(a) : "l"(p));
    return a;
}
__device__ __forceinline__ float gelu_exact(float x) {
    return 0.5f * x * (1.0f + erff(x * 0.70710678118654752f));
}
__device__ __forceinline__ void split_bf(float y, bf16& b, bf16& s) {
    b = __float2bfloat16_rn(y);
    s = __float2bfloat16_rn(y - __bfloat162float(b));
}
__device__ __forceinline__ uint32_t pack_bf2(bf16 a, bf16 b) {
    __nv_bfloat162 t(a, b);
    return *reinterpret_cast<uint32_t*>(&t);
}

#define CP_ASYNC16(dst, src) \
    asm volatile("cp.async.cg.shared.global [%0], [%1], 16;" :: "r"(dst), "l"(src))
#define CP_COMMIT() asm volatile("cp.async.commit_group;")
#define CP_WAIT(n)  asm volatile("cp.async.wait_group %0;" :: "n"(n))

#define MMA_BF16(d, a, b) \
    asm volatile("mma.sync.aligned.m16n8k16.row.col.f32.bf16.bf16.f32 " \
        "{%0,%1,%2,%3}, {%4,%5,%6,%7}, {%8,%9}, {%0,%1,%2,%3};" \
        : "+f"((d)[0]), "+f"((d)[1]), "+f"((d)[2]), "+f"((d)[3]) \
        : "r"((a)[0]), "r"((a)[1]), "r"((a)[2]), "r"((a)[3]), \
          "r"((b)[0]), "r"((b)[1]))

#define LDSM_X4_T(r0, r1, r2, r3, addr) \
    asm volatile("ldmatrix.sync.aligned.m8n8.x4.trans.shared.b16 {%0,%1,%2,%3}, [%4];" \
        : "=r"(r0), "=r"(r1), "=r"(r2), "=r"(r3) : "r"(addr))

// ---------------- 3xBF16 GEMM (R8 config: 128x128, 2 CTA/SM) --------------
#define CHUNK 32
#define RSU   20
#define ARR_U32 (128 * RSU)
#define STG_U32 (4 * ARR_U32)
#define GSMEM_BYTES (2 * STG_U32 * 4)

template<bool GELU, bool WPLAIN, bool WSPLIT>
__global__ __launch_bounds__(256, 2) void gemm_mma(
    const bf16* __restrict__ Ab, const bf16* __restrict__ As,
    const bf16* __restrict__ Bb, const bf16* __restrict__ Bs,
    const float* __restrict__ bias,
    float* __restrict__ Cp, bf16* __restrict__ Cb, bf16* __restrict__ Cs,
    int K, int N)
{
    extern __shared__ uint32_t smem[];
    const int tid  = threadIdx.x;
    const int wid  = tid >> 5;
    const int lane = tid & 31;
    const int m0 = blockIdx.y * 128;
    const int n0 = blockIdx.x * 128;
    const int wm = wid & 1;
    const int wn = wid >> 1;
    const uint32_t sbase = smem_to_u32(smem);

    float acc[4][4][4];
#pragma unroll
    for (int i = 0; i < 4; i++)
#pragma unroll
        for (int j = 0; j < 4; j++)
#pragma unroll
            for (int r = 0; r < 4; r++) acc[i][j][r] = 0.0f;

    const int nch = K / CHUNK;

    auto load_stage = [&](int stage, int kc) {
        const uint32_t st = sbase + (uint32_t)stage * STG_U32 * 4;
#pragma unroll
        for (int t = 0; t < 2; t++) {
            const int seg = tid + t * 256;
            const int row = seg >> 2;
            const int q   = seg & 3;
            const uint32_t soff = (uint32_t)row * 80 + q * 16;
            const size_t  aofg = (size_t)(m0 + row) * K + kc + q * 8;
            const size_t  bofg = (size_t)(n0 + row) * K + kc + q * 8;
            CP_ASYNC16(st + 0 * ARR_U32 * 4 + soff, Ab + aofg);
            CP_ASYNC16(st + 1 * ARR_U32 * 4 + soff, As + aofg);
            CP_ASYNC16(st + 2 * ARR_U32 * 4 + soff, Bb + bofg);
            CP_ASYNC16(st + 3 * ARR_U32 * 4 + soff, Bs + bofg);
        }
    };

    load_stage(0, 0);
    CP_COMMIT();

    const int lr = lane >> 2;
    const int lc = lane & 3;

    for (int c = 0; c < nch; c++) {
        if (c + 1 < nch) {
            load_stage((c + 1) & 1, (c + 1) * CHUNK);
            CP_COMMIT();
            CP_WAIT(1);
        } else {
            CP_WAIT(0);
        }
        __syncthreads();

        const uint32_t* sAb = smem + (size_t)(c & 1) * STG_U32;
        const uint32_t* sAs = sAb + ARR_U32;
        const uint32_t* sBb = sAb + 2 * ARR_U32;
        const uint32_t* sBs = sAb + 3 * ARR_U32;

#pragma unroll
        for (int ks = 0; ks < 2; ks++) {
            const int kc = ks * 8;
            uint32_t afb[4][4], afs[4][4];
#pragma unroll
            for (int i = 0; i < 4; i++) {
                const int base = (wm * 64 + i * 16 + lr) * RSU + kc + lc;
                afb[i][0] = sAb[base];
                afb[i][1] = sAb[base + 8 * RSU];
                afb[i][2] = sAb[base + 4];
                afb[i][3] = sAb[base + 8 * RSU + 4];
                afs[i][0] = sAs[base];
                afs[i][1] = sAs[base + 8 * RSU];
                afs[i][2] = sAs[base + 4];
                afs[i][3] = sAs[base + 8 * RSU + 4];
            }
            uint32_t bfb[4][2], bfs[4][2];
#pragma unroll
            for (int j = 0; j < 4; j++) {
                const int base = (wn * 32 + j * 8 + lr) * RSU + kc + lc;
                bfb[j][0] = sBb[base];
                bfb[j][1] = sBb[base + 4];
                bfs[j][0] = sBs[base];
                bfs[j][1] = sBs[base + 4];
            }
#pragma unroll
            for (int i = 0; i < 4; i++)
#pragma unroll
                for (int j = 0; j < 4; j++) {
                    MMA_BF16(acc[i][j], afb[i], bfb[j]);
                    MMA_BF16(acc[i][j], afb[i], bfs[j]);
                    MMA_BF16(acc[i][j], afs[i], bfb[j]);
                }
        }
        __syncthreads();
    }

#pragma unroll
    for (int i = 0; i < 4; i++) {
#pragma unroll
        for (int j = 0; j < 4; j++) {
            const int gr = m0 + wm * 64 + i * 16 + lr;
            const int gc = n0 + wn * 32 + j * 8 + lc * 2;
            const float b0 = bias[gc], b1 = bias[gc + 1];
#pragma unroll
            for (int half = 0; half < 2; half++) {
                const int row = gr + half * 8;
                float y0 = acc[i][j][half * 2 + 0] + b0;
                float y1 = acc[i][j][half * 2 + 1] + b1;
                if (GELU) { y0 = gelu_exact(y0); y1 = gelu_exact(y1); }
                const size_t o = (size_t)row * N + gc;
                if (WPLAIN) *(float2*)&Cp[o] = make_float2(y0, y1);
                if (WSPLIT) {
                    bf16 hb0, hs0, hb1, hs1;
                    split_bf(y0, hb0, hs0);
                    split_bf(y1, hb1, hs1);
                    *(__nv_bfloat162*)&Cb[o] = __nv_bfloat162(hb0, hb1);
                    *(__nv_bfloat162*)&Cs[o] = __nv_bfloat162(hs0, hs1);
                }
            }
        }
    }
}

// ---------------- MMA flash attention, 2 CTA/SM ---------------------------
// smem: K st: st*18432 (Kb+0,Ks+9216); V st: 36864+st*18432; w: 73728+st*256.
// Q staged through K area once, extracted to regs, then overwritten.
#define AT_SMEM 74240

__global__ __launch_bounds__(256, 2) void flash_mma(
    const bf16* __restrict__ qkvb, const bf16* __restrict__ qkvs,
    const float* __restrict__ w,
    bf16* __restrict__ ob, bf16* __restrict__ os)
{
    extern __shared__ uint32_t smem[];
    const uint32_t sb = smem_to_u32(smem);
    const int tid = threadIdx.x, wid = tid >> 5, lane = tid & 31;
    const int lr = lane >> 2, lc = lane & 3;
    const int bidx = blockIdx.y >> 4;
    const int h    = blockIdx.y & 15;
    const int q0   = blockIdx.x * 128;
    const int hq = h * DK_;
    const int hk = D_ + h * DK_;
    const int hv = 2 * D_ + h * DK_;
    const size_t bm = (size_t)bidx * M_;

    // ---- Q via K-stage area, extract frags, then release ----
#pragma unroll
    for (int t = 0; t < 4; t++) {
        const int seg = tid + t * 256;
        const int row = seg >> 3, q8 = seg & 7;
        const size_t src = (bm + q0 + row) * QS_ + hq + q8 * 8;
        const uint32_t d = sb + (uint32_t)row * 144 + q8 * 16;
        CP_ASYNC16(d,         qkvb + src);
        CP_ASYNC16(d + 18432, qkvs + src);
    }
    CP_COMMIT();
    CP_WAIT(0);
    __syncthreads();

    uint32_t aqb[4][4], aqs[4][4];
#pragma unroll
    for (int ks = 0; ks < 4; ks++) {
        const int base = (wid * 16 + lr) * 36 + ks * 8 + lc;
        aqb[ks][0] = smem[base];
        aqb[ks][1] = smem[base + 288];
        aqb[ks][2] = smem[base + 4];
        aqb[ks][3] = smem[base + 292];
        aqs[ks][0] = smem[base + 4608];
        aqs[ks][1] = smem[base + 4608 + 288];
        aqs[ks][2] = smem[base + 4608 + 4];
        aqs[ks][3] = smem[base + 4608 + 292];
    }
    __syncthreads();

    auto load_kv = [&](int st, int kb0) {
#pragma unroll
        for (int t = 0; t < 2; t++) {
            const int seg = tid + t * 256;
            const int row = seg >> 3, q8 = seg & 7;
            const size_t srck = (bm + kb0 + row) * QS_ + hk + q8 * 8;
            const size_t srcv = (bm + kb0 + row) * QS_ + hv + q8 * 8;
            const uint32_t dk = sb + st * 18432 + (uint32_t)row * 144 + q8 * 16;
            const uint32_t dv = sb + 36864 + st * 18432 + (uint32_t)row * 144 + q8 * 16;
            CP_ASYNC16(dk,        qkvb + srck);
            CP_ASYNC16(dk + 9216, qkvs + srck);
            CP_ASYNC16(dv,        qkvb + srcv);
            CP_ASYNC16(dv + 9216, qkvs + srcv);
        }
        if (tid < 16)
            CP_ASYNC16(sb + 73728 + st * 256 + tid * 16, w + bm + kb0 + tid * 4);
    };
    load_kv(0, 0);
    CP_COMMIT();

    float oa[8][4];
    float m0v = -1e30f, m1v = -1e30f, l0 = 0.0f, l1 = 0.0f;
#pragma unroll
    for (int j = 0; j < 8; j++)
#pragma unroll
        for (int r = 0; r < 4; r++) oa[j][r] = 0.0f;

    for (int kb = 0; kb < 16; kb++) {
        const int st = kb & 1;
        if (kb + 1 < 16) {
            load_kv((kb + 1) & 1, (kb + 1) * 64);
            CP_COMMIT();
            CP_WAIT(1);
        } else {
            CP_WAIT(0);
        }
        __syncthreads();

        const uint32_t* skb = smem + st * 4608;
        const uint32_t* sks = skb + 2304;
        float s_[8][4];
#pragma unroll
        for (int j = 0; j < 8; j++)
#pragma unroll
            for (int r = 0; r < 4; r++) s_[j][r] = 0.0f;

#pragma unroll
        for (int ks = 0; ks < 4; ks++) {
            uint32_t kfb[8][2], kfs[8][2];
#pragma unroll
            for (int j = 0; j < 8; j++) {
                const int base = (j * 8 + lr) * 36 + ks * 8 + lc;
                kfb[j][0] = skb[base];
                kfb[j][1] = skb[base + 4];
                kfs[j][0] = sks[base];
                kfs[j][1] = sks[base + 4];
            }
#pragma unroll
            for (int j = 0; j < 8; j++) {
                MMA_BF16(s_[j], aqb[ks], kfb[j]);
                MMA_BF16(s_[j], aqb[ks], kfs[j]);
                MMA_BF16(s_[j], aqs[ks], kfb[j]);
            }
        }

        const float* sw = (const float*)smem + 18432 + st * 64;
        float rmax0 = -1e30f, rmax1 = -1e30f;
        float x[8][4];
#pragma unroll
        for (int j = 0; j < 8; j++) {
            const float2 wp = *(const float2*)(sw + j * 8 + 2 * lc);
            x[j][0] = s_[j][0] * 0.125f + wp.x;
            x[j][1] = s_[j][1] * 0.125f + wp.y;
            x[j][2] = s_[j][2] * 0.125f + wp.x;
            x[j][3] = s_[j][3] * 0.125f + wp.y;
            rmax0 = fmaxf(rmax0, fmaxf(x[j][0], x[j][1]));
            rmax1 = fmaxf(rmax1, fmaxf(x[j][2], x[j][3]));
        }
        rmax0 = fmaxf(rmax0, __shfl_xor_sync(0xffffffffu, rmax0, 1));
        rmax0 = fmaxf(rmax0, __shfl_xor_sync(0xffffffffu, rmax0, 2));
        rmax1 = fmaxf(rmax1, __shfl_xor_sync(0xffffffffu, rmax1, 1));
        rmax1 = fmaxf(rmax1, __shfl_xor_sync(0xffffffffu, rmax1, 2));
        const float mn0 = fmaxf(m0v, rmax0);
        const float mn1 = fmaxf(m1v, rmax1);
        const float c0 = __expf(m0v - mn0);
        const float c1 = __expf(m1v - mn1);
        float rs0 = 0.0f, rs1 = 0.0f;
        uint32_t pb01[8], pb23[8], ps01[8], ps23[8];
#pragma unroll
        for (int j = 0; j < 8; j++) {
            const float p0 = __expf(x[j][0] - mn0);
            const float p1 = __expf(x[j][1] - mn0);
            const float p2 = __expf(x[j][2] - mn1);
            const float p3 = __expf(x[j][3] - mn1);
            rs0 += p0 + p1;
            rs1 += p2 + p3;
            bf16 b0, sv0, b1, sv1, b2, sv2, b3, sv3;
            split_bf(p0, b0, sv0); split_bf(p1, b1, sv1);
            split_bf(p2, b2, sv2); split_bf(p3, b3, sv3);
            pb01[j] = pack_bf2(b0, b1);
            pb23[j] = pack_bf2(b2, b3);
            ps01[j] = pack_bf2(sv0, sv1);
            ps23[j] = pack_bf2(sv2, sv3);
        }
        rs0 += __shfl_xor_sync(0xffffffffu, rs0, 1);
        rs0 += __shfl_xor_sync(0xffffffffu, rs0, 2);
        rs1 += __shfl_xor_sync(0xffffffffu, rs1, 1);
        rs1 += __shfl_xor_sync(0xffffffffu, rs1, 2);
        l0 = l0 * c0 + rs0;
        l1 = l1 * c1 + rs1;
        m0v = mn0; m1v = mn1;
#pragma unroll
        for (int j = 0; j < 8; j++) {
            oa[j][0] *= c0; oa[j][1] *= c0;
            oa[j][2] *= c1; oa[j][3] *= c1;
        }

        const uint32_t vbase = sb + 36864 + st * 18432;
        const int lgrp = lane >> 3, l8 = lane & 7;
#pragma unroll
        for (int kp = 0; kp < 4; kp++) {
            const uint32_t apb[4] = { pb01[2*kp], pb23[2*kp], pb01[2*kp+1], pb23[2*kp+1] };
            const uint32_t aps[4] = { ps01[2*kp], ps23[2*kp], ps01[2*kp+1], ps23[2*kp+1] };
            const int vrow = kp * 16 + (lgrp & 1) * 8 + l8;
            const uint32_t va = vbase + (uint32_t)vrow * 144 + (lgrp >> 1) * 16;
            uint32_t vfb[8][2], vfs[8][2];
#pragma unroll
            for (int jn = 0; jn < 4; jn++) {
                LDSM_X4_T(vfb[2*jn][0], vfb[2*jn][1], vfb[2*jn+1][0], vfb[2*jn+1][1], va + jn * 32);
                LDSM_X4_T(vfs[2*jn][0], vfs[2*jn][1], vfs[2*jn+1][0], vfs[2*jn+1][1], va + 9216 + jn * 32);
            }
#pragma unroll
            for (int j2 = 0; j2 < 8; j2++) {
                MMA_BF16(oa[j2], apb, vfb[j2]);
                MMA_BF16(oa[j2], apb, vfs[j2]);
                MMA_BF16(oa[j2], aps, vfb[j2]);
            }
        }
        __syncthreads();
    }

    const float i0 = 1.0f / l0;
    const float i1 = 1.0f / l1;
    const int r0g = q0 + wid * 16 + lr;
#pragma unroll
    for (int j2 = 0; j2 < 8; j2++) {
        const size_t o0 = (bm + r0g) * D_ + h * DK_ + j2 * 8 + 2 * lc;
        const size_t o1 = o0 + 8 * D_;
        bf16 hb0, hs0, hb1, hs1;
        split_bf(oa[j2][0] * i0, hb0, hs0);
        split_bf(oa[j2][1] * i0, hb1, hs1);
        *(__nv_bfloat162*)&ob[o0] = __nv_bfloat162(hb0, hb1);
        *(__nv_bfloat162*)&os[o0] = __nv_bfloat162(hs0, hs1);
        split_bf(oa[j2][2] * i1, hb0, hs0);
        split_bf(oa[j2][3] * i1, hb1, hs1);
        *(__nv_bfloat162*)&ob[o1] = __nv_bfloat162(hb0, hb1);
        *(__nv_bfloat162*)&os[o1] = __nv_bfloat162(hs0, hs1);
    }
}

// ---------------- weight split + transpose (layer-stride aware) -----------
__global__ __launch_bounds__(256) void wsplit_t(
    const float* __restrict__ W, bf16* __restrict__ Tb, bf16* __restrict__ Ts,
    int K, int N, long out_ls)
{
    __shared__ float t[32][33];
    const int n0 = blockIdx.x * 32, k0 = blockIdx.y * 32;
    const size_t zin  = (size_t)blockIdx.z * K * N;
    const size_t zout = (size_t)blockIdx.z * out_ls;
    const int tx = threadIdx.x, ty = threadIdx.y;
#pragma unroll
    for (int r = ty; r < 32; r += 8)
        t[r][tx] = W[zin + (size_t)(k0 + r) * N + n0 + tx];
    __syncthreads();
#pragma unroll
    for (int r = ty; r < 32; r += 8) {
        const float v = t[tx][r];
        const size_t o = zout + (size_t)(n0 + r) * K + k0 + tx;
        bf16 hb, hs;
        split_bf(v, hb, hs);
        Tb[o] = hb;
        Ts[o] = hs;
    }
}

__global__ __launch_bounds__(256) void catbias(
    const float* __restrict__ bq, const float* __restrict__ bk,
    const float* __restrict__ bv, float* __restrict__ out)
{
    const int i = blockIdx.x * 256 + threadIdx.x;   // NLAYERS*3072
    const int l = i / QS_, c = i % QS_;
    float v;
    if (c < D_)          v = bq[l * D_ + c];
    else if (c < 2 * D_) v = bk[l * D_ + c - D_];
    else                 v = bv[l * D_ + c - 2 * D_];
    out[i] = v;
}

__global__ __launch_bounds__(1024) void split_x(
    const float* __restrict__ e, float* __restrict__ x,
    bf16* __restrict__ xb, bf16* __restrict__ xs)
{
    const size_t i = (size_t)blockIdx.x * 1024 + threadIdx.x;
    const float v = e[i];
    x[i] = v;
    bf16 hb, hs;
    split_bf(v, hb, hs);
    xb[i] = hb;
    xs[i] = hs;
}

// ---------------- residual + LayerNorm (+bf16 split out) ------------------
__device__ __forceinline__ float block_sum256(float val, float* red) {
    const int lane = threadIdx.x & 31;
    const int wid  = threadIdx.x >> 5;
#pragma unroll
    for (int o = 16; o > 0; o >>= 1) val += __shfl_xor_sync(0xffffffffu, val, o);
    if (lane == 0) red[wid] = val;
    __syncthreads();
    float t = (threadIdx.x < 8) ? red[threadIdx.x] : 0.0f;
    if (wid == 0) {
#pragma unroll
        for (int o = 4; o > 0; o >>= 1) t += __shfl_xor_sync(0xffffffffu, t, o);
        if (lane == 0) red[0] = t;
    }
    __syncthreads();
    float r = red[0];
    __syncthreads();
    return r;
}

__global__ __launch_bounds__(256) void add_ln(
    const float* __restrict__ xin, const float* __restrict__ del,
    const float* __restrict__ g, const float* __restrict__ be,
    float* __restrict__ xout, bf16* __restrict__ xb, bf16* __restrict__ xs)
{
    __shared__ float red[8];
    const int row = blockIdx.x;
    const int tid = threadIdx.x;
    const float* xr = xin + (size_t)row * D_;
    const float* dr = del + (size_t)row * D_;

    float v[4];
    float s = 0.0f;
#pragma unroll
    for (int u = 0; u < 4; u++) {
        v[u] = xr[tid + u * 256] + dr[tid + u * 256];
        s += v[u];
    }
    const float mu = block_sum256(s, red) * (1.0f / D_);
    float qs = 0.0f;
#pragma unroll
    for (int u = 0; u < 4; u++) {
        const float d = v[u] - mu;
        qs += d * d;
    }
    const float var = block_sum256(qs, red) * (1.0f / D_);
    const float rstd = rsqrtf(var + 1e-5f);
#pragma unroll
    for (int u = 0; u < 4; u++) {
        const int c = tid + u * 256;
        const size_t o = (size_t)row * D_ + c;
        const float y = (v[u] - mu) * rstd * g[c] + be[c];
        xout[o] = y;
        bf16 hb, hs;
        split_bf(y, hb, hs);
        xb[o] = hb;
        xs[o] = hs;
    }
}

// ---------------- host driver ----------------
extern "C" void kernel_launch(void* const* d_in, const int* in_sizes, int n_in,
                              void* d_out, int out_size) {
    const float* embeds  = (const float*)d_in[0];
    const float* weights = (const float*)d_in[1];
    const float* Wq = (const float*)d_in[2];
    const float* bq = (const float*)d_in[3];
    const float* Wk = (const float*)d_in[4];
    const float* bk = (const float*)d_in[5];
    const float* Wv = (const float*)d_in[6];
    const float* bv = (const float*)d_in[7];
    const float* Wo = (const float*)d_in[8];
    const float* bo = (const float*)d_in[9];
    const float* W1 = (const float*)d_in[10];
    const float* b1 = (const float*)d_in[11];
    const float* W2 = (const float*)d_in[12];
    const float* b2 = (const float*)d_in[13];
    const float* g1 = (const float*)d_in[14];
    const float* be1= (const float*)d_in[15];
    const float* g2 = (const float*)d_in[16];
    const float* be2= (const float*)d_in[17];

    float *px, *pres, *pbqkv;
    bf16 *pxb,*pxs,*pqkvb,*pqkvs,*pob,*pos,*pfb,*pfs;
    bf16 *pwqkvb,*pwqkvs,*pwob,*pwos,*pw1b,*pw1s,*pw2b,*pw2s;
    cudaGetSymbolAddress((void**)&px,   g_x);
    cudaGetSymbolAddress((void**)&pres, g_res);
    cudaGetSymbolAddress((void**)&pbqkv,g_bqkv);
    cudaGetSymbolAddress((void**)&pxb,  g_xb);
    cudaGetSymbolAddress((void**)&pxs,  g_xs);
    cudaGetSymbolAddress((void**)&pqkvb,g_qkvb);
    cudaGetSymbolAddress((void**)&pqkvs,g_qkvs);
    cudaGetSymbolAddress((void**)&pob,  g_ob);
    cudaGetSymbolAddress((void**)&pos,  g_os);
    cudaGetSymbolAddress((void**)&pfb,  g_fb);
    cudaGetSymbolAddress((void**)&pfs,  g_fs);
    cudaGetSymbolAddress((void**)&pwqkvb,g_wqkvb); cudaGetSymbolAddress((void**)&pwqkvs,g_wqkvs);
    cudaGetSymbolAddress((void**)&pwob,g_wob); cudaGetSymbolAddress((void**)&pwos,g_wos);
    cudaGetSymbolAddress((void**)&pw1b,g_w1b); cudaGetSymbolAddress((void**)&pw1s,g_w1s);
    cudaGetSymbolAddress((void**)&pw2b,g_w2b); cudaGetSymbolAddress((void**)&pw2s,g_w2s);

    cudaFuncSetAttribute(gemm_mma<false, true, false>,
                         cudaFuncAttributeMaxDynamicSharedMemorySize, GSMEM_BYTES);
    cudaFuncSetAttribute(gemm_mma<true, false, true>,
                         cudaFuncAttributeMaxDynamicSharedMemorySize, GSMEM_BYTES);
    cudaFuncSetAttribute(gemm_mma<false, false, true>,
                         cudaFuncAttributeMaxDynamicSharedMemorySize, GSMEM_BYTES);
    cudaFuncSetAttribute(flash_mma,
                         cudaFuncAttributeMaxDynamicSharedMemorySize, AT_SMEM);

    const long ls3 = (long)3 * D_ * D_;
    wsplit_t<<<dim3(D_/32, D_/32, NLAYERS), dim3(32, 8)>>>(Wq, pwqkvb,            pwqkvs,            D_, D_, ls3);
    wsplit_t<<<dim3(D_/32, D_/32, NLAYERS), dim3(32, 8)>>>(Wk, pwqkvb + D_*D_,    pwqkvs + D_*D_,    D_, D_, ls3);
    wsplit_t<<<dim3(D_/32, D_/32, NLAYERS), dim3(32, 8)>>>(Wv, pwqkvb + 2*D_*D_,  pwqkvs + 2*D_*D_,  D_, D_, ls3);
    wsplit_t<<<dim3(D_/32, D_/32, NLAYERS), dim3(32, 8)>>>(Wo, pwob, pwos, D_, D_, (long)D_*D_);
    wsplit_t<<<dim3(F_/32, D_/32, NLAYERS), dim3(32, 8)>>>(W1, pw1b, pw1s, D_, F_, (long)D_*F_);
    wsplit_t<<<dim3(D_/32, F_/32, NLAYERS), dim3(32, 8)>>>(W2, pw2b, pw2s, F_, D_, (long)F_*D_);
    catbias<<<NLAYERS * QS_ / 256, 256>>>(bq, bk, bv, pbqkv);
    split_x<<<ROWS * D_ / 1024, 1024>>>(embeds, px, pxb, pxs);

    const dim3 gQKV(QS_ / 128, ROWS / 128);  // (24, 64)
    const dim3 gD(D_ / 128, ROWS / 128);     // (8, 64)
    const dim3 gF(F_ / 128, ROWS / 128);     // (32, 64)
    const dim3 gA(M_ / 128, B_ * H_);        // (8, 128)

    for (int l = 0; l < NLAYERS; l++) {
        gemm_mma<false, false, true><<<gQKV, 256, GSMEM_BYTES>>>(
            pxb, pxs, pwqkvb + (size_t)l*ls3, pwqkvs + (size_t)l*ls3,
            pbqkv + (size_t)l*QS_, nullptr, pqkvb, pqkvs, D_, QS_);

        flash_mma<<<gA, 256, AT_SMEM>>>(pqkvb, pqkvs, weights, pob, pos);

        gemm_mma<false, true, false><<<gD, 256, GSMEM_BYTES>>>(
            pob, pos, pwob + (size_t)l*D_*D_, pwos + (size_t)l*D_*D_,
            bo + (size_t)l*D_, pres, nullptr, nullptr, D_, D_);
        add_ln<<<ROWS, 256>>>(px, pres, g1 + (size_t)l*D_, be1 + (size_t)l*D_,
                              px, pxb, pxs);

        gemm_mma<true, false, true><<<gF, 256, GSMEM_BYTES>>>(
            pxb, pxs, pw1b + (size_t)l*D_*F_, pw1s + (size_t)l*D_*F_,
            b1 + (size_t)l*F_, nullptr, pfb, pfs, D_, F_);
        gemm_mma<false, true, false><<<gD, 256, GSMEM_BYTES>>>(
            pfb, pfs, pw2b + (size_t)l*F_*D_, pw2s + (size_t)l*F_*D_,
            b2 + (size_t)l*D_, pres, nullptr, nullptr, F_, D_);
        add_ln<<<ROWS, 256>>>(px, pres, g2 + (size_t)l*D_, be2 + (size_t)l*D_,
                              px, pxb, pxs);
    }

    cudaMemcpyAsync(d_out, px, sizeof(float) * (size_t)ROWS * D_,
                    cudaMemcpyDeviceToDevice);
}

// round 11
// speedup vs baseline: 1.3710x; 1.3089x over previous
#include <cuda_runtime.h>
#include <cuda_bf16.h>
#include <cuda_fp16.h>
#include <math.h>
#include <stdint.h>

#define B_ 8
#define M_ 1024
#define D_ 1024
#define H_ 16
#define F_ 4096
#define NLAYERS 4
#define DK_ 64
#define ROWS (B_*M_)
#define QS_ (3*D_)
#define WSCALE 64.0f
#define INVWS  0.015625f

typedef __nv_bfloat16 bf16;
typedef __half fp16;

// ---------------- device scratch ----------------
__device__ float g_x   [ROWS * D_];
__device__ float g_res [ROWS * D_];
__device__ float g_bqkv[NLAYERS * QS_];
__device__ fp16  g_xh  [ROWS * D_];
__device__ fp16  g_xl  [ROWS * D_];
__device__ bf16  g_qkvb[ROWS * QS_];
__device__ bf16  g_qkvs[ROWS * QS_];
__device__ fp16  g_oh  [ROWS * D_];
__device__ fp16  g_ol  [ROWS * D_];
__device__ fp16  g_fh  [ROWS * F_];
__device__ fp16  g_fl  [ROWS * F_];
__device__ fp16 g_wqkv[NLAYERS*3*D_*D_];
__device__ fp16 g_wo  [NLAYERS*D_*D_];
__device__ fp16 g_w1  [NLAYERS*D_*F_];
__device__ fp16 g_w2  [NLAYERS*F_*D_];

// ---------------- helpers ----------------
__device__ __forceinline__ uint32_t smem_to_u32(const void* p) {
    uint32_t a;
    asm("{ .reg .u64 t; cvta.to.shared.u64 t, %1; cvt.u32.u64 %0, t; }" : "=r"(a) : "l"(p));
    return a;
}
__device__ __forceinline__ float gelu_exact(float x) {
    return 0.5f * x * (1.0f + erff(x * 0.70710678118654752f));
}
__device__ __forceinline__ void split_bf(float y, bf16& b, bf16& s) {
    b = __float2bfloat16_rn(y);
    s = __float2bfloat16_rn(y - __bfloat162float(b));
}
__device__ __forceinline__ void split_h(float y, fp16& h, fp16& l) {
    h = __float2half_rn(y);
    l = __float2half_rn(y - __half2float(h));
}
__device__ __forceinline__ uint32_t pack_bf2(bf16 a, bf16 b) {
    __nv_bfloat162 t(a, b);
    return *reinterpret_cast<uint32_t*>(&t);
}

#define CP_ASYNC16(dst, src) \
    asm volatile("cp.async.cg.shared.global [%0], [%1], 16;" :: "r"(dst), "l"(src))
#define CP_COMMIT() asm volatile("cp.async.commit_group;")
#define CP_WAIT(n)  asm volatile("cp.async.wait_group %0;" :: "n"(n))

#define MMA_F16(d, a, b) \
    asm volatile("mma.sync.aligned.m16n8k16.row.col.f32.f16.f16.f32 " \
        "{%0,%1,%2,%3}, {%4,%5,%6,%7}, {%8,%9}, {%0,%1,%2,%3};" \
        : "+f"((d)[0]), "+f"((d)[1]), "+f"((d)[2]), "+f"((d)[3]) \
        : "r"((a)[0]), "r"((a)[1]), "r"((a)[2]), "r"((a)[3]), \
          "r"((b)[0]), "r"((b)[1]))

#define MMA_BF16(d, a, b) \
    asm volatile("mma.sync.aligned.m16n8k16.row.col.f32.bf16.bf16.f32 " \
        "{%0,%1,%2,%3}, {%4,%5,%6,%7}, {%8,%9}, {%0,%1,%2,%3};" \
        : "+f"((d)[0]), "+f"((d)[1]), "+f"((d)[2]), "+f"((d)[3]) \
        : "r"((a)[0]), "r"((a)[1]), "r"((a)[2]), "r"((a)[3]), \
          "r"((b)[0]), "r"((b)[1]))

#define LDSM_X4_T(r0, r1, r2, r3, addr) \
    asm volatile("ldmatrix.sync.aligned.m8n8.x4.trans.shared.b16 {%0,%1,%2,%3}, [%4];" \
        : "=r"(r0), "=r"(r1), "=r"(r2), "=r"(r3) : "r"(addr))

// ---------------- 2xFP16 GEMM: C = (Ah+Al)·Bh /64 + bias -------------------
#define CHUNK 32
#define RSU   20
#define ARR_U32 (128 * RSU)
#define STG3_U32 (3 * ARR_U32)
#define GSMEM_BYTES (2 * STG3_U32 * 4)   // 61440

template<bool GELU, bool WPLAIN, bool WH, bool WB>
__global__ __launch_bounds__(256, 2) void gemm_mma(
    const fp16* __restrict__ Ah, const fp16* __restrict__ Al,
    const fp16* __restrict__ Bh,
    const float* __restrict__ bias,
    float* __restrict__ Cp, fp16* __restrict__ Ch, fp16* __restrict__ Cl,
    bf16* __restrict__ Cbb, bf16* __restrict__ Cbs,
    int K, int N)
{
    extern __shared__ uint32_t smem[];
    const int tid  = threadIdx.x;
    const int wid  = tid >> 5;
    const int lane = tid & 31;
    const int m0 = blockIdx.y * 128;
    const int n0 = blockIdx.x * 128;
    const int wm = wid & 1;
    const int wn = wid >> 1;
    const uint32_t sbase = smem_to_u32(smem);

    float acc[4][4][4];
#pragma unroll
    for (int i = 0; i < 4; i++)
#pragma unroll
        for (int j = 0; j < 4; j++)
#pragma unroll
            for (int r = 0; r < 4; r++) acc[i][j][r] = 0.0f;

    const int nch = K / CHUNK;

    auto load_stage = [&](int stage, int kc) {
        const uint32_t st = sbase + (uint32_t)stage * STG3_U32 * 4;
#pragma unroll
        for (int t = 0; t < 2; t++) {
            const int seg = tid + t * 256;
            const int row = seg >> 2;
            const int q   = seg & 3;
            const uint32_t soff = (uint32_t)row * 80 + q * 16;
            const size_t  aofg = (size_t)(m0 + row) * K + kc + q * 8;
            const size_t  bofg = (size_t)(n0 + row) * K + kc + q * 8;
            CP_ASYNC16(st + soff,                   Ah + aofg);
            CP_ASYNC16(st + ARR_U32 * 4 + soff,     Al + aofg);
            CP_ASYNC16(st + 2 * ARR_U32 * 4 + soff, Bh + bofg);
        }
    };

    load_stage(0, 0);
    CP_COMMIT();

    const int lr = lane >> 2;
    const int lc = lane & 3;

    for (int c = 0; c < nch; c++) {
        if (c + 1 < nch) {
            load_stage((c + 1) & 1, (c + 1) * CHUNK);
            CP_COMMIT();
            CP_WAIT(1);
        } else {
            CP_WAIT(0);
        }
        __syncthreads();

        const uint32_t* sAh = smem + (size_t)(c & 1) * STG3_U32;
        const uint32_t* sAl = sAh + ARR_U32;
        const uint32_t* sBh = sAh + 2 * ARR_U32;

#pragma unroll
        for (int ks = 0; ks < 2; ks++) {
            const int kc = ks * 8;
            uint32_t ah[4][4], al[4][4];
#pragma unroll
            for (int i = 0; i < 4; i++) {
                const int base = (wm * 64 + i * 16 + lr) * RSU + kc + lc;
                ah[i][0] = sAh[base];
                ah[i][1] = sAh[base + 8 * RSU];
                ah[i][2] = sAh[base + 4];
                ah[i][3] = sAh[base + 8 * RSU + 4];
                al[i][0] = sAl[base];
                al[i][1] = sAl[base + 8 * RSU];
                al[i][2] = sAl[base + 4];
                al[i][3] = sAl[base + 8 * RSU + 4];
            }
            uint32_t bh[4][2];
#pragma unroll
            for (int j = 0; j < 4; j++) {
                const int base = (wn * 32 + j * 8 + lr) * RSU + kc + lc;
                bh[j][0] = sBh[base];
                bh[j][1] = sBh[base + 4];
            }
#pragma unroll
            for (int i = 0; i < 4; i++)
#pragma unroll
                for (int j = 0; j < 4; j++) {
                    MMA_F16(acc[i][j], ah[i], bh[j]);
                    MMA_F16(acc[i][j], al[i], bh[j]);
                }
        }
        __syncthreads();
    }

#pragma unroll
    for (int i = 0; i < 4; i++) {
#pragma unroll
        for (int j = 0; j < 4; j++) {
            const int gr = m0 + wm * 64 + i * 16 + lr;
            const int gc = n0 + wn * 32 + j * 8 + lc * 2;
            const float b0 = bias[gc], b1 = bias[gc + 1];
#pragma unroll
            for (int half = 0; half < 2; half++) {
                const int row = gr + half * 8;
                float y0 = acc[i][j][half * 2 + 0] * INVWS + b0;
                float y1 = acc[i][j][half * 2 + 1] * INVWS + b1;
                if (GELU) { y0 = gelu_exact(y0); y1 = gelu_exact(y1); }
                const size_t o = (size_t)row * N + gc;
                if (WPLAIN) *(float2*)&Cp[o] = make_float2(y0, y1);
                if (WH) {
                    fp16 h0, l0_, h1, l1_;
                    split_h(y0, h0, l0_);
                    split_h(y1, h1, l1_);
                    *(__half2*)&Ch[o] = __half2(h0, h1);
                    *(__half2*)&Cl[o] = __half2(l0_, l1_);
                }
                if (WB) {
                    bf16 hb0, hs0, hb1, hs1;
                    split_bf(y0, hb0, hs0);
                    split_bf(y1, hb1, hs1);
                    *(__nv_bfloat162*)&Cbb[o] = __nv_bfloat162(hb0, hb1);
                    *(__nv_bfloat162*)&Cbs[o] = __nv_bfloat162(hs0, hs1);
                }
            }
        }
    }
}

// ---------------- MMA flash attention (bf16 3-term, fp16 split out) -------
#define AT_SMEM 74240

__global__ __launch_bounds__(256, 2) void flash_mma(
    const bf16* __restrict__ qkvb, const bf16* __restrict__ qkvs,
    const float* __restrict__ w,
    fp16* __restrict__ oh, fp16* __restrict__ ol)
{
    extern __shared__ uint32_t smem[];
    const uint32_t sb = smem_to_u32(smem);
    const int tid = threadIdx.x, wid = tid >> 5, lane = tid & 31;
    const int lr = lane >> 2, lc = lane & 3;
    const int bidx = blockIdx.y >> 4;
    const int h    = blockIdx.y & 15;
    const int q0   = blockIdx.x * 128;
    const int hq = h * DK_;
    const int hk = D_ + h * DK_;
    const int hv = 2 * D_ + h * DK_;
    const size_t bm = (size_t)bidx * M_;

#pragma unroll
    for (int t = 0; t < 4; t++) {
        const int seg = tid + t * 256;
        const int row = seg >> 3, q8 = seg & 7;
        const size_t src = (bm + q0 + row) * QS_ + hq + q8 * 8;
        const uint32_t d = sb + (uint32_t)row * 144 + q8 * 16;
        CP_ASYNC16(d,         qkvb + src);
        CP_ASYNC16(d + 18432, qkvs + src);
    }
    CP_COMMIT();
    CP_WAIT(0);
    __syncthreads();

    uint32_t aqb[4][4], aqs[4][4];
#pragma unroll
    for (int ks = 0; ks < 4; ks++) {
        const int base = (wid * 16 + lr) * 36 + ks * 8 + lc;
        aqb[ks][0] = smem[base];
        aqb[ks][1] = smem[base + 288];
        aqb[ks][2] = smem[base + 4];
        aqb[ks][3] = smem[base + 292];
        aqs[ks][0] = smem[base + 4608];
        aqs[ks][1] = smem[base + 4608 + 288];
        aqs[ks][2] = smem[base + 4608 + 4];
        aqs[ks][3] = smem[base + 4608 + 292];
    }
    __syncthreads();

    auto load_kv = [&](int st, int kb0) {
#pragma unroll
        for (int t = 0; t < 2; t++) {
            const int seg = tid + t * 256;
            const int row = seg >> 3, q8 = seg & 7;
            const size_t srck = (bm + kb0 + row) * QS_ + hk + q8 * 8;
            const size_t srcv = (bm + kb0 + row) * QS_ + hv + q8 * 8;
            const uint32_t dk = sb + st * 18432 + (uint32_t)row * 144 + q8 * 16;
            const uint32_t dv = sb + 36864 + st * 18432 + (uint32_t)row * 144 + q8 * 16;
            CP_ASYNC16(dk,        qkvb + srck);
            CP_ASYNC16(dk + 9216, qkvs + srck);
            CP_ASYNC16(dv,        qkvb + srcv);
            CP_ASYNC16(dv + 9216, qkvs + srcv);
        }
        if (tid < 16)
            CP_ASYNC16(sb + 73728 + st * 256 + tid * 16, w + bm + kb0 + tid * 4);
    };
    load_kv(0, 0);
    CP_COMMIT();

    float oa[8][4];
    float m0v = -1e30f, m1v = -1e30f, l0 = 0.0f, l1 = 0.0f;
#pragma unroll
    for (int j = 0; j < 8; j++)
#pragma unroll
        for (int r = 0; r < 4; r++) oa[j][r] = 0.0f;

    for (int kb = 0; kb < 16; kb++) {
        const int st = kb & 1;
        if (kb + 1 < 16) {
            load_kv((kb + 1) & 1, (kb + 1) * 64);
            CP_COMMIT();
            CP_WAIT(1);
        } else {
            CP_WAIT(0);
        }
        __syncthreads();

        const uint32_t* skb = smem + st * 4608;
        const uint32_t* sks = skb + 2304;
        float s_[8][4];
#pragma unroll
        for (int j = 0; j < 8; j++)
#pragma unroll
            for (int r = 0; r < 4; r++) s_[j][r] = 0.0f;

#pragma unroll
        for (int ks = 0; ks < 4; ks++) {
            uint32_t kfb[8][2], kfs[8][2];
#pragma unroll
            for (int j = 0; j < 8; j++) {
                const int base = (j * 8 + lr) * 36 + ks * 8 + lc;
                kfb[j][0] = skb[base];
                kfb[j][1] = skb[base + 4];
                kfs[j][0] = sks[base];
                kfs[j][1] = sks[base + 4];
            }
#pragma unroll
            for (int j = 0; j < 8; j++) {
                MMA_BF16(s_[j], aqb[ks], kfb[j]);
                MMA_BF16(s_[j], aqb[ks], kfs[j]);
                MMA_BF16(s_[j], aqs[ks], kfb[j]);
            }
        }

        const float* sw = (const float*)smem + 18432 + st * 64;
        float rmax0 = -1e30f, rmax1 = -1e30f;
        float x[8][4];
#pragma unroll
        for (int j = 0; j < 8; j++) {
            const float2 wp = *(const float2*)(sw + j * 8 + 2 * lc);
            x[j][0] = s_[j][0] * 0.125f + wp.x;
            x[j][1] = s_[j][1] * 0.125f + wp.y;
            x[j][2] = s_[j][2] * 0.125f + wp.x;
            x[j][3] = s_[j][3] * 0.125f + wp.y;
            rmax0 = fmaxf(rmax0, fmaxf(x[j][0], x[j][1]));
            rmax1 = fmaxf(rmax1, fmaxf(x[j][2], x[j][3]));
        }
        rmax0 = fmaxf(rmax0, __shfl_xor_sync(0xffffffffu, rmax0, 1));
        rmax0 = fmaxf(rmax0, __shfl_xor_sync(0xffffffffu, rmax0, 2));
        rmax1 = fmaxf(rmax1, __shfl_xor_sync(0xffffffffu, rmax1, 1));
        rmax1 = fmaxf(rmax1, __shfl_xor_sync(0xffffffffu, rmax1, 2));
        const float mn0 = fmaxf(m0v, rmax0);
        const float mn1 = fmaxf(m1v, rmax1);
        const float c0 = __expf(m0v - mn0);
        const float c1 = __expf(m1v - mn1);
        float rs0 = 0.0f, rs1 = 0.0f;
        uint32_t pb01[8], pb23[8], ps01[8], ps23[8];
#pragma unroll
        for (int j = 0; j < 8; j++) {
            const float p0 = __expf(x[j][0] - mn0);
            const float p1 = __expf(x[j][1] - mn0);
            const float p2 = __expf(x[j][2] - mn1);
            const float p3 = __expf(x[j][3] - mn1);
            rs0 += p0 + p1;
            rs1 += p2 + p3;
            bf16 b0, sv0, b1, sv1, b2, sv2, b3, sv3;
            split_bf(p0, b0, sv0); split_bf(p1, b1, sv1);
            split_bf(p2, b2, sv2); split_bf(p3, b3, sv3);
            pb01[j] = pack_bf2(b0, b1);
            pb23[j] = pack_bf2(b2, b3);
            ps01[j] = pack_bf2(sv0, sv1);
            ps23[j] = pack_bf2(sv2, sv3);
        }
        rs0 += __shfl_xor_sync(0xffffffffu, rs0, 1);
        rs0 += __shfl_xor_sync(0xffffffffu, rs0, 2);
        rs1 += __shfl_xor_sync(0xffffffffu, rs1, 1);
        rs1 += __shfl_xor_sync(0xffffffffu, rs1, 2);
        l0 = l0 * c0 + rs0;
        l1 = l1 * c1 + rs1;
        m0v = mn0; m1v = mn1;
#pragma unroll
        for (int j = 0; j < 8; j++) {
            oa[j][0] *= c0; oa[j][1] *= c0;
            oa[j][2] *= c1; oa[j][3] *= c1;
        }

        const uint32_t vbase = sb + 36864 + st * 18432;
        const int lgrp = lane >> 3, l8 = lane & 7;
#pragma unroll
        for (int kp = 0; kp < 4; kp++) {
            const uint32_t apb[4] = { pb01[2*kp], pb23[2*kp], pb01[2*kp+1], pb23[2*kp+1] };
            const uint32_t aps[4] = { ps01[2*kp], ps23[2*kp], ps01[2*kp+1], ps23[2*kp+1] };
            const int vrow = kp * 16 + (lgrp & 1) * 8 + l8;
            const uint32_t va = vbase + (uint32_t)vrow * 144 + (lgrp >> 1) * 16;
            uint32_t vfb[8][2], vfs[8][2];
#pragma unroll
            for (int jn = 0; jn < 4; jn++) {
                LDSM_X4_T(vfb[2*jn][0], vfb[2*jn][1], vfb[2*jn+1][0], vfb[2*jn+1][1], va + jn * 32);
                LDSM_X4_T(vfs[2*jn][0], vfs[2*jn][1], vfs[2*jn+1][0], vfs[2*jn+1][1], va + 9216 + jn * 32);
            }
#pragma unroll
            for (int j2 = 0; j2 < 8; j2++) {
                MMA_BF16(oa[j2], apb, vfb[j2]);
                MMA_BF16(oa[j2], apb, vfs[j2]);
                MMA_BF16(oa[j2], aps, vfb[j2]);
            }
        }
        __syncthreads();
    }

    const float i0 = 1.0f / l0;
    const float i1 = 1.0f / l1;
    const int r0g = q0 + wid * 16 + lr;
#pragma unroll
    for (int j2 = 0; j2 < 8; j2++) {
        const size_t o0 = (bm + r0g) * D_ + h * DK_ + j2 * 8 + 2 * lc;
        const size_t o1 = o0 + 8 * D_;
        fp16 h0, l0_, h1, l1_;
        split_h(oa[j2][0] * i0, h0, l0_);
        split_h(oa[j2][1] * i0, h1, l1_);
        *(__half2*)&oh[o0] = __half2(h0, h1);
        *(__half2*)&ol[o0] = __half2(l0_, l1_);
        split_h(oa[j2][2] * i1, h0, l0_);
        split_h(oa[j2][3] * i1, h1, l1_);
        *(__half2*)&oh[o1] = __half2(h0, h1);
        *(__half2*)&ol[o1] = __half2(l0_, l1_);
    }
}

// ---------------- weight prep: T[z][N][K] = fp16(64 * W[z][K][N]) ---------
__global__ __launch_bounds__(256) void wprep(
    const float* __restrict__ W, fp16* __restrict__ T,
    int K, int N, long out_ls)
{
    __shared__ float t[32][33];
    const int n0 = blockIdx.x * 32, k0 = blockIdx.y * 32;
    const size_t zin  = (size_t)blockIdx.z * K * N;
    const size_t zout = (size_t)blockIdx.z * out_ls;
    const int tx = threadIdx.x, ty = threadIdx.y;
#pragma unroll
    for (int r = ty; r < 32; r += 8)
        t[r][tx] = W[zin + (size_t)(k0 + r) * N + n0 + tx];
    __syncthreads();
#pragma unroll
    for (int r = ty; r < 32; r += 8)
        T[zout + (size_t)(n0 + r) * K + k0 + tx] =
            __float2half_rn(t[tx][r] * WSCALE);
}

__global__ __launch_bounds__(256) void catbias(
    const float* __restrict__ bq, const float* __restrict__ bk,
    const float* __restrict__ bv, float* __restrict__ out)
{
    const int i = blockIdx.x * 256 + threadIdx.x;
    const int l = i / QS_, c = i % QS_;
    float v;
    if (c < D_)          v = bq[l * D_ + c];
    else if (c < 2 * D_) v = bk[l * D_ + c - D_];
    else                 v = bv[l * D_ + c - 2 * D_];
    out[i] = v;
}

__global__ __launch_bounds__(1024) void split_x(
    const float* __restrict__ e, float* __restrict__ x,
    fp16* __restrict__ xh, fp16* __restrict__ xl)
{
    const size_t i = (size_t)blockIdx.x * 1024 + threadIdx.x;
    const float v = e[i];
    x[i] = v;
    fp16 h, l;
    split_h(v, h, l);
    xh[i] = h;
    xl[i] = l;
}

// ---------------- residual + LayerNorm (+fp16 split out) ------------------
__device__ __forceinline__ float block_sum256(float val, float* red) {
    const int lane = threadIdx.x & 31;
    const int wid  = threadIdx.x >> 5;
#pragma unroll
    for (int o = 16; o > 0; o >>= 1) val += __shfl_xor_sync(0xffffffffu, val, o);
    if (lane == 0) red[wid] = val;
    __syncthreads();
    float t = (threadIdx.x < 8) ? red[threadIdx.x] : 0.0f;
    if (wid == 0) {
#pragma unroll
        for (int o = 4; o > 0; o >>= 1) t += __shfl_xor_sync(0xffffffffu, t, o);
        if (lane == 0) red[0] = t;
    }
    __syncthreads();
    float r = red[0];
    __syncthreads();
    return r;
}

__global__ __launch_bounds__(256) void add_ln(
    const float* __restrict__ xin, const float* __restrict__ del,
    const float* __restrict__ g, const float* __restrict__ be,
    float* __restrict__ xout, fp16* __restrict__ xh, fp16* __restrict__ xl)
{
    __shared__ float red[8];
    const int row = blockIdx.x;
    const int c = threadIdx.x * 4;
    const size_t ro = (size_t)row * D_;

    const float4 xv = *(const float4*)&xin[ro + c];
    const float4 dv = *(const float4*)&del[ro + c];
    float v[4] = { xv.x + dv.x, xv.y + dv.y, xv.z + dv.z, xv.w + dv.w };
    const float mu = block_sum256(v[0] + v[1] + v[2] + v[3], red) * (1.0f / D_);
    float qs = 0.0f;
#pragma unroll
    for (int u = 0; u < 4; u++) {
        const float d = v[u] - mu;
        qs += d * d;
    }
    const float var = block_sum256(qs, red) * (1.0f / D_);
    const float rstd = rsqrtf(var + 1e-5f);

    const float4 gv = *(const float4*)&g[c];
    const float4 bv = *(const float4*)&be[c];
    float y[4];
    y[0] = (v[0] - mu) * rstd * gv.x + bv.x;
    y[1] = (v[1] - mu) * rstd * gv.y + bv.y;
    y[2] = (v[2] - mu) * rstd * gv.z + bv.z;
    y[3] = (v[3] - mu) * rstd * gv.w + bv.w;
    *(float4*)&xout[ro + c] = make_float4(y[0], y[1], y[2], y[3]);
    fp16 h0, l0, h1, l1;
    split_h(y[0], h0, l0); split_h(y[1], h1, l1);
    *(__half2*)&xh[ro + c] = __half2(h0, h1);
    *(__half2*)&xl[ro + c] = __half2(l0, l1);
    split_h(y[2], h0, l0); split_h(y[3], h1, l1);
    *(__half2*)&xh[ro + c + 2] = __half2(h0, h1);
    *(__half2*)&xl[ro + c + 2] = __half2(l0, l1);
}

// ---------------- host driver ----------------
extern "C" void kernel_launch(void* const* d_in, const int* in_sizes, int n_in,
                              void* d_out, int out_size) {
    const float* embeds  = (const float*)d_in[0];
    const float* weights = (const float*)d_in[1];
    const float* Wq = (const float*)d_in[2];
    const float* bq = (const float*)d_in[3];
    const float* Wk = (const float*)d_in[4];
    const float* bk = (const float*)d_in[5];
    const float* Wv = (const float*)d_in[6];
    const float* bv = (const float*)d_in[7];
    const float* Wo = (const float*)d_in[8];
    const float* bo = (const float*)d_in[9];
    const float* W1 = (const float*)d_in[10];
    const float* b1 = (const float*)d_in[11];
    const float* W2 = (const float*)d_in[12];
    const float* b2 = (const float*)d_in[13];
    const float* g1 = (const float*)d_in[14];
    const float* be1= (const float*)d_in[15];
    const float* g2 = (const float*)d_in[16];
    const float* be2= (const float*)d_in[17];

    float *px, *pres, *pbqkv;
    fp16 *pxh,*pxl,*poh,*pol,*pfh,*pfl,*pwqkv,*pwo,*pw1,*pw2;
    bf16 *pqkvb,*pqkvs;
    cudaGetSymbolAddress((void**)&px,   g_x);
    cudaGetSymbolAddress((void**)&pres, g_res);
    cudaGetSymbolAddress((void**)&pbqkv,g_bqkv);
    cudaGetSymbolAddress((void**)&pxh,  g_xh);
    cudaGetSymbolAddress((void**)&pxl,  g_xl);
    cudaGetSymbolAddress((void**)&pqkvb,g_qkvb);
    cudaGetSymbolAddress((void**)&pqkvs,g_qkvs);
    cudaGetSymbolAddress((void**)&poh,  g_oh);
    cudaGetSymbolAddress((void**)&pol,  g_ol);
    cudaGetSymbolAddress((void**)&pfh,  g_fh);
    cudaGetSymbolAddress((void**)&pfl,  g_fl);
    cudaGetSymbolAddress((void**)&pwqkv,g_wqkv);
    cudaGetSymbolAddress((void**)&pwo,  g_wo);
    cudaGetSymbolAddress((void**)&pw1,  g_w1);
    cudaGetSymbolAddress((void**)&pw2,  g_w2);

    cudaFuncSetAttribute(gemm_mma<false, false, false, true>,
                         cudaFuncAttributeMaxDynamicSharedMemorySize, GSMEM_BYTES);
    cudaFuncSetAttribute(gemm_mma<false, true, false, false>,
                         cudaFuncAttributeMaxDynamicSharedMemorySize, GSMEM_BYTES);
    cudaFuncSetAttribute(gemm_mma<true, false, true, false>,
                         cudaFuncAttributeMaxDynamicSharedMemorySize, GSMEM_BYTES);
    cudaFuncSetAttribute(flash_mma,
                         cudaFuncAttributeMaxDynamicSharedMemorySize, AT_SMEM);

    const long ls3 = (long)3 * D_ * D_;
    wprep<<<dim3(D_/32, D_/32, NLAYERS), dim3(32, 8)>>>(Wq, pwqkv,           D_, D_, ls3);
    wprep<<<dim3(D_/32, D_/32, NLAYERS), dim3(32, 8)>>>(Wk, pwqkv + D_*D_,   D_, D_, ls3);
    wprep<<<dim3(D_/32, D_/32, NLAYERS), dim3(32, 8)>>>(Wv, pwqkv + 2*D_*D_, D_, D_, ls3);
    wprep<<<dim3(D_/32, D_/32, NLAYERS), dim3(32, 8)>>>(Wo, pwo, D_, D_, (long)D_*D_);
    wprep<<<dim3(F_/32, D_/32, NLAYERS), dim3(32, 8)>>>(W1, pw1, D_, F_, (long)D_*F_);
    wprep<<<dim3(D_/32, F_/32, NLAYERS), dim3(32, 8)>>>(W2, pw2, F_, D_, (long)F_*D_);
    catbias<<<NLAYERS * QS_ / 256, 256>>>(bq, bk, bv, pbqkv);
    split_x<<<ROWS * D_ / 1024, 1024>>>(embeds, px, pxh, pxl);

    const dim3 gQKV(QS_ / 128, ROWS / 128);  // (24, 64)
    const dim3 gD(D_ / 128, ROWS / 128);     // (8, 64)
    const dim3 gF(F_ / 128, ROWS / 128);     // (32, 64)
    const dim3 gA(M_ / 128, B_ * H_);        // (8, 128)

    for (int l = 0; l < NLAYERS; l++) {
        gemm_mma<false, false, false, true><<<gQKV, 256, GSMEM_BYTES>>>(
            pxh, pxl, pwqkv + (size_t)l*ls3, pbqkv + (size_t)l*QS_,
            nullptr, nullptr, nullptr, pqkvb, pqkvs, D_, QS_);

        flash_mma<<<gA, 256, AT_SMEM>>>(pqkvb, pqkvs, weights, poh, pol);

        gemm_mma<false, true, false, false><<<gD, 256, GSMEM_BYTES>>>(
            poh, pol, pwo + (size_t)l*D_*D_, bo + (size_t)l*D_,
            pres, nullptr, nullptr, nullptr, nullptr, D_, D_);
        add_ln<<<ROWS, 256>>>(px, pres, g1 + (size_t)l*D_, be1 + (size_t)l*D_,
                              px, pxh, pxl);

        gemm_mma<true, false, true, false><<<gF, 256, GSMEM_BYTES>>>(
            pxh, pxl, pw1 + (size_t)l*D_*F_, b1 + (size_t)l*F_,
            nullptr, pfh, pfl, nullptr, nullptr, D_, F_);
        gemm_mma<false, true, false, false><<<gD, 256, GSMEM_BYTES>>>(
            pfh, pfl, pw2 + (size_t)l*F_*D_, b2 + (size_t)l*D_,
            pres, nullptr, nullptr, nullptr, nullptr, F_, D_);
        add_ln<<<ROWS, 256>>>(px, pres, g2 + (size_t)l*D_, be2 + (size_t)l*D_,
                              px, pxh, pxl);
    }

    cudaMemcpyAsync(d_out, px, sizeof(float) * (size_t)ROWS * D_,
                    cudaMemcpyDeviceToDevice);
}

// round 12
// speedup vs baseline: 1.4762x; 1.0767x over previous
#include <cuda_runtime.h>
#include <cuda_bf16.h>
#include <cuda_fp16.h>
#include <math.h>
#include <stdint.h>

#define B_ 8
#define M_ 1024
#define D_ 1024
#define H_ 16
#define F_ 4096
#define NLAYERS 4
#define DK_ 64
#define ROWS (B_*M_)
#define QS_ (3*D_)
#define WSCALE 64.0f
#define INVWS  0.015625f

typedef __nv_bfloat16 bf16;
typedef __half fp16;

// ---------------- device scratch ----------------
__device__ float g_x   [ROWS * D_];
__device__ float g_res [ROWS * D_];
__device__ float g_bqkv[NLAYERS * QS_];
__device__ fp16  g_xh  [ROWS * D_];
__device__ fp16  g_xl  [ROWS * D_];
__device__ bf16  g_qkvb[ROWS * QS_];
__device__ bf16  g_qkvs[ROWS * QS_];
__device__ fp16  g_oh  [ROWS * D_];
__device__ fp16  g_ol  [ROWS * D_];
__device__ fp16  g_fh  [ROWS * F_];
__device__ fp16  g_fl  [ROWS * F_];
__device__ fp16 g_wqkv[NLAYERS*3*D_*D_];
__device__ fp16 g_wo  [NLAYERS*D_*D_];
__device__ fp16 g_w1  [NLAYERS*D_*F_];
__device__ fp16 g_w2  [NLAYERS*F_*D_];

// ---------------- helpers ----------------
__device__ __forceinline__ uint32_t smem_to_u32(const void* p) {
    uint32_t a;
    asm("{ .reg .u64 t; cvta.to.shared.u64 t, %1; cvt.u32.u64 %0, t; }" : "=r"(a) : "l"(p));
    return a;
}
__device__ __forceinline__ float gelu_exact(float x) {
    return 0.5f * x * (1.0f + erff(x * 0.70710678118654752f));
}
__device__ __forceinline__ void split_bf(float y, bf16& b, bf16& s) {
    b = __float2bfloat16_rn(y);
    s = __float2bfloat16_rn(y - __bfloat162float(b));
}
__device__ __forceinline__ void split_h(float y, fp16& h, fp16& l) {
    h = __float2half_rn(y);
    l = __float2half_rn(y - __half2float(h));
}
__device__ __forceinline__ uint32_t pack_bf2(bf16 a, bf16 b) {
    __nv_bfloat162 t(a, b);
    return *reinterpret_cast<uint32_t*>(&t);
}

#define CP_ASYNC16(dst, src) \
    asm volatile("cp.async.cg.shared.global [%0], [%1], 16;" :: "r"(dst), "l"(src))
#define CP_COMMIT() asm volatile("cp.async.commit_group;")
#define CP_WAIT(n)  asm volatile("cp.async.wait_group %0;" :: "n"(n))

#define MMA_F16(d, a, b) \
    asm volatile("mma.sync.aligned.m16n8k16.row.col.f32.f16.f16.f32 " \
        "{%0,%1,%2,%3}, {%4,%5,%6,%7}, {%8,%9}, {%0,%1,%2,%3};" \
        : "+f"((d)[0]), "+f"((d)[1]), "+f"((d)[2]), "+f"((d)[3]) \
        : "r"((a)[0]), "r"((a)[1]), "r"((a)[2]), "r"((a)[3]), \
          "r"((b)[0]), "r"((b)[1]))

#define MMA_BF16(d, a, b) \
    asm volatile("mma.sync.aligned.m16n8k16.row.col.f32.bf16.bf16.f32 " \
        "{%0,%1,%2,%3}, {%4,%5,%6,%7}, {%8,%9}, {%0,%1,%2,%3};" \
        : "+f"((d)[0]), "+f"((d)[1]), "+f"((d)[2]), "+f"((d)[3]) \
        : "r"((a)[0]), "r"((a)[1]), "r"((a)[2]), "r"((a)[3]), \
          "r"((b)[0]), "r"((b)[1]))

#define LDSM_X4_T(r0, r1, r2, r3, addr) \
    asm volatile("ldmatrix.sync.aligned.m8n8.x4.trans.shared.b16 {%0,%1,%2,%3}, [%4];" \
        : "=r"(r0), "=r"(r1), "=r"(r2), "=r"(r3) : "r"(addr))

// ---------------- 2xFP16 GEMM: C = (Ah+Al)·Bh /64 + bias, CHUNK 64 --------
#define CHUNK 64
#define RSU   36                      // u32 per row (128B data + 16B pad)
#define ARR_U32 (128 * RSU)           // 4608
#define STG3_U32 (3 * ARR_U32)        // 13824 u32 = 55296 B
#define GSMEM_BYTES (2 * STG3_U32 * 4) // 110592

template<bool GELU, bool WPLAIN, bool WH, bool WB>
__global__ __launch_bounds__(256, 2) void gemm_mma(
    const fp16* __restrict__ Ah, const fp16* __restrict__ Al,
    const fp16* __restrict__ Bh,
    const float* __restrict__ bias,
    float* __restrict__ Cp, fp16* __restrict__ Ch, fp16* __restrict__ Cl,
    bf16* __restrict__ Cbb, bf16* __restrict__ Cbs,
    int K, int N)
{
    extern __shared__ uint32_t smem[];
    const int tid  = threadIdx.x;
    const int wid  = tid >> 5;
    const int lane = tid & 31;
    const int m0 = blockIdx.y * 128;
    const int n0 = blockIdx.x * 128;
    const int wm = wid & 1;
    const int wn = wid >> 1;
    const uint32_t sbase = smem_to_u32(smem);

    float acc[4][4][4];
#pragma unroll
    for (int i = 0; i < 4; i++)
#pragma unroll
        for (int j = 0; j < 4; j++)
#pragma unroll
            for (int r = 0; r < 4; r++) acc[i][j][r] = 0.0f;

    const int nch = K / CHUNK;

    // per array: 128 rows x 128B = 1024 16B-segs; 256 thr -> 4 each
    auto load_stage = [&](int stage, int kc) {
        const uint32_t st = sbase + (uint32_t)stage * STG3_U32 * 4;
#pragma unroll
        for (int t = 0; t < 4; t++) {
            const int seg = tid + t * 256;
            const int row = seg >> 3;
            const int q   = seg & 7;
            const uint32_t soff = (uint32_t)row * 144 + q * 16;
            const size_t  aofg = (size_t)(m0 + row) * K + kc + q * 8;
            const size_t  bofg = (size_t)(n0 + row) * K + kc + q * 8;
            CP_ASYNC16(st + soff,                   Ah + aofg);
            CP_ASYNC16(st + ARR_U32 * 4 + soff,     Al + aofg);
            CP_ASYNC16(st + 2 * ARR_U32 * 4 + soff, Bh + bofg);
        }
    };

    load_stage(0, 0);
    CP_COMMIT();

    const int lr = lane >> 2;
    const int lc = lane & 3;

    for (int c = 0; c < nch; c++) {
        if (c + 1 < nch) {
            load_stage((c + 1) & 1, (c + 1) * CHUNK);
            CP_COMMIT();
            CP_WAIT(1);
        } else {
            CP_WAIT(0);
        }
        __syncthreads();

        const uint32_t* sAh = smem + (size_t)(c & 1) * STG3_U32;
        const uint32_t* sAl = sAh + ARR_U32;
        const uint32_t* sBh = sAh + 2 * ARR_U32;

#pragma unroll
        for (int ks = 0; ks < 4; ks++) {
            const int kc = ks * 8;
            uint32_t ah[4][4], al[4][4];
#pragma unroll
            for (int i = 0; i < 4; i++) {
                const int base = (wm * 64 + i * 16 + lr) * RSU + kc + lc;
                ah[i][0] = sAh[base];
                ah[i][1] = sAh[base + 8 * RSU];
                ah[i][2] = sAh[base + 4];
                ah[i][3] = sAh[base + 8 * RSU + 4];
                al[i][0] = sAl[base];
                al[i][1] = sAl[base + 8 * RSU];
                al[i][2] = sAl[base + 4];
                al[i][3] = sAl[base + 8 * RSU + 4];
            }
            uint32_t bh[4][2];
#pragma unroll
            for (int j = 0; j < 4; j++) {
                const int base = (wn * 32 + j * 8 + lr) * RSU + kc + lc;
                bh[j][0] = sBh[base];
                bh[j][1] = sBh[base + 4];
            }
#pragma unroll
            for (int i = 0; i < 4; i++)
#pragma unroll
                for (int j = 0; j < 4; j++) {
                    MMA_F16(acc[i][j], ah[i], bh[j]);
                    MMA_F16(acc[i][j], al[i], bh[j]);
                }
        }
        __syncthreads();
    }

#pragma unroll
    for (int i = 0; i < 4; i++) {
#pragma unroll
        for (int j = 0; j < 4; j++) {
            const int gr = m0 + wm * 64 + i * 16 + lr;
            const int gc = n0 + wn * 32 + j * 8 + lc * 2;
            const float b0 = bias[gc], b1 = bias[gc + 1];
#pragma unroll
            for (int half = 0; half < 2; half++) {
                const int row = gr + half * 8;
                float y0 = acc[i][j][half * 2 + 0] * INVWS + b0;
                float y1 = acc[i][j][half * 2 + 1] * INVWS + b1;
                if (GELU) { y0 = gelu_exact(y0); y1 = gelu_exact(y1); }
                const size_t o = (size_t)row * N + gc;
                if (WPLAIN) *(float2*)&Cp[o] = make_float2(y0, y1);
                if (WH) {
                    fp16 h0, l0_, h1, l1_;
                    split_h(y0, h0, l0_);
                    split_h(y1, h1, l1_);
                    *(__half2*)&Ch[o] = __half2(h0, h1);
                    *(__half2*)&Cl[o] = __half2(l0_, l1_);
                }
                if (WB) {
                    bf16 hb0, hs0, hb1, hs1;
                    split_bf(y0, hb0, hs0);
                    split_bf(y1, hb1, hs1);
                    *(__nv_bfloat162*)&Cbb[o] = __nv_bfloat162(hb0, hb1);
                    *(__nv_bfloat162*)&Cbs[o] = __nv_bfloat162(hs0, hs1);
                }
            }
        }
    }
}

// ---------------- MMA flash attention (bf16 3-term, fp16 split out) -------
#define AT_SMEM 74240

__global__ __launch_bounds__(256, 2) void flash_mma(
    const bf16* __restrict__ qkvb, const bf16* __restrict__ qkvs,
    const float* __restrict__ w,
    fp16* __restrict__ oh, fp16* __restrict__ ol)
{
    extern __shared__ uint32_t smem[];
    const uint32_t sb = smem_to_u32(smem);
    const int tid = threadIdx.x, wid = tid >> 5, lane = tid & 31;
    const int lr = lane >> 2, lc = lane & 3;
    const int bidx = blockIdx.y >> 4;
    const int h    = blockIdx.y & 15;
    const int q0   = blockIdx.x * 128;
    const int hq = h * DK_;
    const int hk = D_ + h * DK_;
    const int hv = 2 * D_ + h * DK_;
    const size_t bm = (size_t)bidx * M_;

#pragma unroll
    for (int t = 0; t < 4; t++) {
        const int seg = tid + t * 256;
        const int row = seg >> 3, q8 = seg & 7;
        const size_t src = (bm + q0 + row) * QS_ + hq + q8 * 8;
        const uint32_t d = sb + (uint32_t)row * 144 + q8 * 16;
        CP_ASYNC16(d,         qkvb + src);
        CP_ASYNC16(d + 18432, qkvs + src);
    }
    CP_COMMIT();
    CP_WAIT(0);
    __syncthreads();

    uint32_t aqb[4][4], aqs[4][4];
#pragma unroll
    for (int ks = 0; ks < 4; ks++) {
        const int base = (wid * 16 + lr) * 36 + ks * 8 + lc;
        aqb[ks][0] = smem[base];
        aqb[ks][1] = smem[base + 288];
        aqb[ks][2] = smem[base + 4];
        aqb[ks][3] = smem[base + 292];
        aqs[ks][0] = smem[base + 4608];
        aqs[ks][1] = smem[base + 4608 + 288];
        aqs[ks][2] = smem[base + 4608 + 4];
        aqs[ks][3] = smem[base + 4608 + 292];
    }
    __syncthreads();

    auto load_kv = [&](int st, int kb0) {
#pragma unroll
        for (int t = 0; t < 2; t++) {
            const int seg = tid + t * 256;
            const int row = seg >> 3, q8 = seg & 7;
            const size_t srck = (bm + kb0 + row) * QS_ + hk + q8 * 8;
            const size_t srcv = (bm + kb0 + row) * QS_ + hv + q8 * 8;
            const uint32_t dk = sb + st * 18432 + (uint32_t)row * 144 + q8 * 16;
            const uint32_t dv = sb + 36864 + st * 18432 + (uint32_t)row * 144 + q8 * 16;
            CP_ASYNC16(dk,        qkvb + srck);
            CP_ASYNC16(dk + 9216, qkvs + srck);
            CP_ASYNC16(dv,        qkvb + srcv);
            CP_ASYNC16(dv + 9216, qkvs + srcv);
        }
        if (tid < 16)
            CP_ASYNC16(sb + 73728 + st * 256 + tid * 16, w + bm + kb0 + tid * 4);
    };
    load_kv(0, 0);
    CP_COMMIT();

    float oa[8][4];
    float m0v = -1e30f, m1v = -1e30f, l0 = 0.0f, l1 = 0.0f;
#pragma unroll
    for (int j = 0; j < 8; j++)
#pragma unroll
        for (int r = 0; r < 4; r++) oa[j][r] = 0.0f;

    for (int kb = 0; kb < 16; kb++) {
        const int st = kb & 1;
        if (kb + 1 < 16) {
            load_kv((kb + 1) & 1, (kb + 1) * 64);
            CP_COMMIT();
            CP_WAIT(1);
        } else {
            CP_WAIT(0);
        }
        __syncthreads();

        const uint32_t* skb = smem + st * 4608;
        const uint32_t* sks = skb + 2304;
        float s_[8][4];
#pragma unroll
        for (int j = 0; j < 8; j++)
#pragma unroll
            for (int r = 0; r < 4; r++) s_[j][r] = 0.0f;

#pragma unroll
        for (int ks = 0; ks < 4; ks++) {
            uint32_t kfb[8][2], kfs[8][2];
#pragma unroll
            for (int j = 0; j < 8; j++) {
                const int base = (j * 8 + lr) * 36 + ks * 8 + lc;
                kfb[j][0] = skb[base];
                kfb[j][1] = skb[base + 4];
                kfs[j][0] = sks[base];
                kfs[j][1] = sks[base + 4];
            }
#pragma unroll
            for (int j = 0; j < 8; j++) {
                MMA_BF16(s_[j], aqb[ks], kfb[j]);
                MMA_BF16(s_[j], aqb[ks], kfs[j]);
                MMA_BF16(s_[j], aqs[ks], kfb[j]);
            }
        }

        const float* sw = (const float*)smem + 18432 + st * 64;
        float rmax0 = -1e30f, rmax1 = -1e30f;
        float x[8][4];
#pragma unroll
        for (int j = 0; j < 8; j++) {
            const float2 wp = *(const float2*)(sw + j * 8 + 2 * lc);
            x[j][0] = s_[j][0] * 0.125f + wp.x;
            x[j][1] = s_[j][1] * 0.125f + wp.y;
            x[j][2] = s_[j][2] * 0.125f + wp.x;
            x[j][3] = s_[j][3] * 0.125f + wp.y;
            rmax0 = fmaxf(rmax0, fmaxf(x[j][0], x[j][1]));
            rmax1 = fmaxf(rmax1, fmaxf(x[j][2], x[j][3]));
        }
        rmax0 = fmaxf(rmax0, __shfl_xor_sync(0xffffffffu, rmax0, 1));
        rmax0 = fmaxf(rmax0, __shfl_xor_sync(0xffffffffu, rmax0, 2));
        rmax1 = fmaxf(rmax1, __shfl_xor_sync(0xffffffffu, rmax1, 1));
        rmax1 = fmaxf(rmax1, __shfl_xor_sync(0xffffffffu, rmax1, 2));
        const float mn0 = fmaxf(m0v, rmax0);
        const float mn1 = fmaxf(m1v, rmax1);
        const float c0 = __expf(m0v - mn0);
        const float c1 = __expf(m1v - mn1);
        float rs0 = 0.0f, rs1 = 0.0f;
        uint32_t pb01[8], pb23[8], ps01[8], ps23[8];
#pragma unroll
        for (int j = 0; j < 8; j++) {
            const float p0 = __expf(x[j][0] - mn0);
            const float p1 = __expf(x[j][1] - mn0);
            const float p2 = __expf(x[j][2] - mn1);
            const float p3 = __expf(x[j][3] - mn1);
            rs0 += p0 + p1;
            rs1 += p2 + p3;
            bf16 b0, sv0, b1, sv1, b2, sv2, b3, sv3;
            split_bf(p0, b0, sv0); split_bf(p1, b1, sv1);
            split_bf(p2, b2, sv2); split_bf(p3, b3, sv3);
            pb01[j] = pack_bf2(b0, b1);
            pb23[j] = pack_bf2(b2, b3);
            ps01[j] = pack_bf2(sv0, sv1);
            ps23[j] = pack_bf2(sv2, sv3);
        }
        rs0 += __shfl_xor_sync(0xffffffffu, rs0, 1);
        rs0 += __shfl_xor_sync(0xffffffffu, rs0, 2);
        rs1 += __shfl_xor_sync(0xffffffffu, rs1, 1);
        rs1 += __shfl_xor_sync(0xffffffffu, rs1, 2);
        l0 = l0 * c0 + rs0;
        l1 = l1 * c1 + rs1;
        m0v = mn0; m1v = mn1;
#pragma unroll
        for (int j = 0; j < 8; j++) {
            oa[j][0] *= c0; oa[j][1] *= c0;
            oa[j][2] *= c1; oa[j][3] *= c1;
        }

        const uint32_t vbase = sb + 36864 + st * 18432;
        const int lgrp = lane >> 3, l8 = lane & 7;
#pragma unroll
        for (int kp = 0; kp < 4; kp++) {
            const uint32_t apb[4] = { pb01[2*kp], pb23[2*kp], pb01[2*kp+1], pb23[2*kp+1] };
            const uint32_t aps[4] = { ps01[2*kp], ps23[2*kp], ps01[2*kp+1], ps23[2*kp+1] };
            const int vrow = kp * 16 + (lgrp & 1) * 8 + l8;
            const uint32_t va = vbase + (uint32_t)vrow * 144 + (lgrp >> 1) * 16;
            uint32_t vfb[8][2], vfs[8][2];
#pragma unroll
            for (int jn = 0; jn < 4; jn++) {
                LDSM_X4_T(vfb[2*jn][0], vfb[2*jn][1], vfb[2*jn+1][0], vfb[2*jn+1][1], va + jn * 32);
                LDSM_X4_T(vfs[2*jn][0], vfs[2*jn][1], vfs[2*jn+1][0], vfs[2*jn+1][1], va + 9216 + jn * 32);
            }
#pragma unroll
            for (int j2 = 0; j2 < 8; j2++) {
                MMA_BF16(oa[j2], apb, vfb[j2]);
                MMA_BF16(oa[j2], apb, vfs[j2]);
                MMA_BF16(oa[j2], aps, vfb[j2]);
            }
        }
        __syncthreads();
    }

    const float i0 = 1.0f / l0;
    const float i1 = 1.0f / l1;
    const int r0g = q0 + wid * 16 + lr;
#pragma unroll
    for (int j2 = 0; j2 < 8; j2++) {
        const size_t o0 = (bm + r0g) * D_ + h * DK_ + j2 * 8 + 2 * lc;
        const size_t o1 = o0 + 8 * D_;
        fp16 h0, l0_, h1, l1_;
        split_h(oa[j2][0] * i0, h0, l0_);
        split_h(oa[j2][1] * i0, h1, l1_);
        *(__half2*)&oh[o0] = __half2(h0, h1);
        *(__half2*)&ol[o0] = __half2(l0_, l1_);
        split_h(oa[j2][2] * i1, h0, l0_);
        split_h(oa[j2][3] * i1, h1, l1_);
        *(__half2*)&oh[o1] = __half2(h0, h1);
        *(__half2*)&ol[o1] = __half2(l0_, l1_);
    }
}

// ---------------- weight prep ----------------
__global__ __launch_bounds__(256) void wprep(
    const float* __restrict__ W, fp16* __restrict__ T,
    int K, int N, long out_ls)
{
    __shared__ float t[32][33];
    const int n0 = blockIdx.x * 32, k0 = blockIdx.y * 32;
    const size_t zin  = (size_t)blockIdx.z * K * N;
    const size_t zout = (size_t)blockIdx.z * out_ls;
    const int tx = threadIdx.x, ty = threadIdx.y;
#pragma unroll
    for (int r = ty; r < 32; r += 8)
        t[r][tx] = W[zin + (size_t)(k0 + r) * N + n0 + tx];
    __syncthreads();
#pragma unroll
    for (int r = ty; r < 32; r += 8)
        T[zout + (size_t)(n0 + r) * K + k0 + tx] =
            __float2half_rn(t[tx][r] * WSCALE);
}

__global__ __launch_bounds__(256) void catbias(
    const float* __restrict__ bq, const float* __restrict__ bk,
    const float* __restrict__ bv, float* __restrict__ out)
{
    const int i = blockIdx.x * 256 + threadIdx.x;
    const int l = i / QS_, c = i % QS_;
    float v;
    if (c < D_)          v = bq[l * D_ + c];
    else if (c < 2 * D_) v = bk[l * D_ + c - D_];
    else                 v = bv[l * D_ + c - 2 * D_];
    out[i] = v;
}

__global__ __launch_bounds__(1024) void split_x(
    const float* __restrict__ e, float* __restrict__ x,
    fp16* __restrict__ xh, fp16* __restrict__ xl)
{
    const size_t i = (size_t)blockIdx.x * 1024 + threadIdx.x;
    const float v = e[i];
    x[i] = v;
    fp16 h, l;
    split_h(v, h, l);
    xh[i] = h;
    xl[i] = l;
}

// ---------------- residual + LayerNorm (+fp16 split out) ------------------
__device__ __forceinline__ float block_sum256(float val, float* red) {
    const int lane = threadIdx.x & 31;
    const int wid  = threadIdx.x >> 5;
#pragma unroll
    for (int o = 16; o > 0; o >>= 1) val += __shfl_xor_sync(0xffffffffu, val, o);
    if (lane == 0) red[wid] = val;
    __syncthreads();
    float t = (threadIdx.x < 8) ? red[threadIdx.x] : 0.0f;
    if (wid == 0) {
#pragma unroll
        for (int o = 4; o > 0; o >>= 1) t += __shfl_xor_sync(0xffffffffu, t, o);
        if (lane == 0) red[0] = t;
    }
    __syncthreads();
    float r = red[0];
    __syncthreads();
    return r;
}

__global__ __launch_bounds__(256) void add_ln(
    const float* __restrict__ xin, const float* __restrict__ del,
    const float* __restrict__ g, const float* __restrict__ be,
    float* __restrict__ xout, fp16* __restrict__ xh, fp16* __restrict__ xl)
{
    __shared__ float red[8];
    const int row = blockIdx.x;
    const int c = threadIdx.x * 4;
    const size_t ro = (size_t)row * D_;

    const float4 xv = *(const float4*)&xin[ro + c];
    const float4 dv = *(const float4*)&del[ro + c];
    float v[4] = { xv.x + dv.x, xv.y + dv.y, xv.z + dv.z, xv.w + dv.w };
    const float mu = block_sum256(v[0] + v[1] + v[2] + v[3], red) * (1.0f / D_);
    float qs = 0.0f;
#pragma unroll
    for (int u = 0; u < 4; u++) {
        const float d = v[u] - mu;
        qs += d * d;
    }
    const float var = block_sum256(qs, red) * (1.0f / D_);
    const float rstd = rsqrtf(var + 1e-5f);

    const float4 gv = *(const float4*)&g[c];
    const float4 bv = *(const float4*)&be[c];
    float y[4];
    y[0] = (v[0] - mu) * rstd * gv.x + bv.x;
    y[1] = (v[1] - mu) * rstd * gv.y + bv.y;
    y[2] = (v[2] - mu) * rstd * gv.z + bv.z;
    y[3] = (v[3] - mu) * rstd * gv.w + bv.w;
    *(float4*)&xout[ro + c] = make_float4(y[0], y[1], y[2], y[3]);
    fp16 h0, l0, h1, l1;
    split_h(y[0], h0, l0); split_h(y[1], h1, l1);
    *(__half2*)&xh[ro + c] = __half2(h0, h1);
    *(__half2*)&xl[ro + c] = __half2(l0, l1);
    split_h(y[2], h0, l0); split_h(y[3], h1, l1);
    *(__half2*)&xh[ro + c + 2] = __half2(h0, h1);
    *(__half2*)&xl[ro + c + 2] = __half2(l0, l1);
}

// ---------------- host driver ----------------
extern "C" void kernel_launch(void* const* d_in, const int* in_sizes, int n_in,
                              void* d_out, int out_size) {
    const float* embeds  = (const float*)d_in[0];
    const float* weights = (const float*)d_in[1];
    const float* Wq = (const float*)d_in[2];
    const float* bq = (const float*)d_in[3];
    const float* Wk = (const float*)d_in[4];
    const float* bk = (const float*)d_in[5];
    const float* Wv = (const float*)d_in[6];
    const float* bv = (const float*)d_in[7];
    const float* Wo = (const float*)d_in[8];
    const float* bo = (const float*)d_in[9];
    const float* W1 = (const float*)d_in[10];
    const float* b1 = (const float*)d_in[11];
    const float* W2 = (const float*)d_in[12];
    const float* b2 = (const float*)d_in[13];
    const float* g1 = (const float*)d_in[14];
    const float* be1= (const float*)d_in[15];
    const float* g2 = (const float*)d_in[16];
    const float* be2= (const float*)d_in[17];

    float *px, *pres, *pbqkv;
    fp16 *pxh,*pxl,*poh,*pol,*pfh,*pfl,*pwqkv,*pwo,*pw1,*pw2;
    bf16 *pqkvb,*pqkvs;
    cudaGetSymbolAddress((void**)&px,   g_x);
    cudaGetSymbolAddress((void**)&pres, g_res);
    cudaGetSymbolAddress((void**)&pbqkv,g_bqkv);
    cudaGetSymbolAddress((void**)&pxh,  g_xh);
    cudaGetSymbolAddress((void**)&pxl,  g_xl);
    cudaGetSymbolAddress((void**)&pqkvb,g_qkvb);
    cudaGetSymbolAddress((void**)&pqkvs,g_qkvs);
    cudaGetSymbolAddress((void**)&poh,  g_oh);
    cudaGetSymbolAddress((void**)&pol,  g_ol);
    cudaGetSymbolAddress((void**)&pfh,  g_fh);
    cudaGetSymbolAddress((void**)&pfl,  g_fl);
    cudaGetSymbolAddress((void**)&pwqkv,g_wqkv);
    cudaGetSymbolAddress((void**)&pwo,  g_wo);
    cudaGetSymbolAddress((void**)&pw1,  g_w1);
    cudaGetSymbolAddress((void**)&pw2,  g_w2);

    cudaFuncSetAttribute(gemm_mma<false, false, false, true>,
                         cudaFuncAttributeMaxDynamicSharedMemorySize, GSMEM_BYTES);
    cudaFuncSetAttribute(gemm_mma<false, true, false, false>,
                         cudaFuncAttributeMaxDynamicSharedMemorySize, GSMEM_BYTES);
    cudaFuncSetAttribute(gemm_mma<true, false, true, false>,
                         cudaFuncAttributeMaxDynamicSharedMemorySize, GSMEM_BYTES);
    cudaFuncSetAttribute(flash_mma,
                         cudaFuncAttributeMaxDynamicSharedMemorySize, AT_SMEM);

    const long ls3 = (long)3 * D_ * D_;
    // exactly 5 launches before the first gemm_mma so ncu -s 5 -c 1 captures it
    catbias<<<NLAYERS * QS_ / 256, 256>>>(bq, bk, bv, pbqkv);
    split_x<<<ROWS * D_ / 1024, 1024>>>(embeds, px, pxh, pxl);
    wprep<<<dim3(D_/32, D_/32, NLAYERS), dim3(32, 8)>>>(Wq, pwqkv,           D_, D_, ls3);
    wprep<<<dim3(D_/32, D_/32, NLAYERS), dim3(32, 8)>>>(Wk, pwqkv + D_*D_,   D_, D_, ls3);
    wprep<<<dim3(D_/32, D_/32, NLAYERS), dim3(32, 8)>>>(Wv, pwqkv + 2*D_*D_, D_, D_, ls3);

    const dim3 gQKV(QS_ / 128, ROWS / 128);  // (24, 64)
    const dim3 gD(D_ / 128, ROWS / 128);     // (8, 64)
    const dim3 gF(F_ / 128, ROWS / 128);     // (32, 64)
    const dim3 gA(M_ / 128, B_ * H_);        // (8, 128)

    for (int l = 0; l < NLAYERS; l++) {
        gemm_mma<false, false, false, true><<<gQKV, 256, GSMEM_BYTES>>>(
            pxh, pxl, pwqkv + (size_t)l*ls3, pbqkv + (size_t)l*QS_,
            nullptr, nullptr, nullptr, pqkvb, pqkvs, D_, QS_);

        if (l == 0) {
            wprep<<<dim3(D_/32, D_/32, NLAYERS), dim3(32, 8)>>>(Wo, pwo, D_, D_, (long)D_*D_);
            wprep<<<dim3(F_/32, D_/32, NLAYERS), dim3(32, 8)>>>(W1, pw1, D_, F_, (long)D_*F_);
            wprep<<<dim3(D_/32, F_/32, NLAYERS), dim3(32, 8)>>>(W2, pw2, F_, D_, (long)F_*D_);
        }

        flash_mma<<<gA, 256, AT_SMEM>>>(pqkvb, pqkvs, weights, poh, pol);

        gemm_mma<false, true, false, false><<<gD, 256, GSMEM_BYTES>>>(
            poh, pol, pwo + (size_t)l*D_*D_, bo + (size_t)l*D_,
            pres, nullptr, nullptr, nullptr, nullptr, D_, D_);
        add_ln<<<ROWS, 256>>>(px, pres, g1 + (size_t)l*D_, be1 + (size_t)l*D_,
                              px, pxh, pxl);

        gemm_mma<true, false, true, false><<<gF, 256, GSMEM_BYTES>>>(
            pxh, pxl, pw1 + (size_t)l*D_*F_, b1 + (size_t)l*F_,
            nullptr, pfh, pfl, nullptr, nullptr, D_, F_);
        gemm_mma<false, true, false, false><<<gD, 256, GSMEM_BYTES>>>(
            pfh, pfl, pw2 + (size_t)l*F_*D_, b2 + (size_t)l*D_,
            pres, nullptr, nullptr, nullptr, nullptr, F_, D_);
        add_ln<<<ROWS, 256>>>(px, pres, g2 + (size_t)l*D_, be2 + (size_t)l*D_,
                              px, pxh, pxl);
    }

    cudaMemcpyAsync(d_out, px, sizeof(float) * (size_t)ROWS * D_,
                    cudaMemcpyDeviceToDevice);
}

// round 13
// speedup vs baseline: 1.4846x; 1.0057x over previous
#include <cuda_runtime.h>
#include <cuda_bf16.h>
#include <cuda_fp16.h>
#include <math.h>
#include <stdint.h>

#define B_ 8
#define M_ 1024
#define D_ 1024
#define H_ 16
#define F_ 4096
#define NLAYERS 4
#define DK_ 64
#define ROWS (B_*M_)
#define QS_ (3*D_)
#define WSCALE 64.0f
#define INVWS  0.015625f

typedef __nv_bfloat16 bf16;
typedef __half fp16;

// ---------------- device scratch ----------------
__device__ float g_x   [ROWS * D_];
__device__ float g_res [ROWS * D_];
__device__ float g_bqkv[NLAYERS * QS_];
__device__ fp16  g_xh  [ROWS * D_];
__device__ fp16  g_xl  [ROWS * D_];
__device__ bf16  g_qkvb[ROWS * QS_];
__device__ bf16  g_qkvs[ROWS * QS_];
__device__ fp16  g_oh  [ROWS * D_];
__device__ fp16  g_ol  [ROWS * D_];
__device__ fp16  g_fh  [ROWS * F_];
__device__ fp16  g_fl  [ROWS * F_];
__device__ fp16 g_wqkv[NLAYERS*3*D_*D_];
__device__ fp16 g_wo  [NLAYERS*D_*D_];
__device__ fp16 g_w1  [NLAYERS*D_*F_];
__device__ fp16 g_w2  [NLAYERS*F_*D_];

// ---------------- helpers ----------------
__device__ __forceinline__ uint32_t smem_to_u32(const void* p) {
    uint32_t a;
    asm("{ .reg .u64 t; cvta.to.shared.u64 t, %1; cvt.u32.u64 %0, t; }" : "=r"(a) : "l"(p));
    return a;
}
__device__ __forceinline__ float gelu_exact(float x) {
    return 0.5f * x * (1.0f + erff(x * 0.70710678118654752f));
}
__device__ __forceinline__ void split_bf(float y, bf16& b, bf16& s) {
    b = __float2bfloat16_rn(y);
    s = __float2bfloat16_rn(y - __bfloat162float(b));
}
__device__ __forceinline__ void split_h(float y, fp16& h, fp16& l) {
    h = __float2half_rn(y);
    l = __float2half_rn(y - __half2float(h));
}
__device__ __forceinline__ uint32_t pack_bf2(bf16 a, bf16 b) {
    __nv_bfloat162 t(a, b);
    return *reinterpret_cast<uint32_t*>(&t);
}

#define CP_ASYNC16(dst, src) \
    asm volatile("cp.async.cg.shared.global [%0], [%1], 16;" :: "r"(dst), "l"(src))
#define CP_COMMIT() asm volatile("cp.async.commit_group;")
#define CP_WAIT(n)  asm volatile("cp.async.wait_group %0;" :: "n"(n))

#define MMA_F16(d, a, b) \
    asm volatile("mma.sync.aligned.m16n8k16.row.col.f32.f16.f16.f32 " \
        "{%0,%1,%2,%3}, {%4,%5,%6,%7}, {%8,%9}, {%0,%1,%2,%3};" \
        : "+f"((d)[0]), "+f"((d)[1]), "+f"((d)[2]), "+f"((d)[3]) \
        : "r"((a)[0]), "r"((a)[1]), "r"((a)[2]), "r"((a)[3]), \
          "r"((b)[0]), "r"((b)[1]))

#define MMA_BF16(d, a, b) \
    asm volatile("mma.sync.aligned.m16n8k16.row.col.f32.bf16.bf16.f32 " \
        "{%0,%1,%2,%3}, {%4,%5,%6,%7}, {%8,%9}, {%0,%1,%2,%3};" \
        : "+f"((d)[0]), "+f"((d)[1]), "+f"((d)[2]), "+f"((d)[3]) \
        : "r"((a)[0]), "r"((a)[1]), "r"((a)[2]), "r"((a)[3]), \
          "r"((b)[0]), "r"((b)[1]))

#define LDSM_X4_T(r0, r1, r2, r3, addr) \
    asm volatile("ldmatrix.sync.aligned.m8n8.x4.trans.shared.b16 {%0,%1,%2,%3}, [%4];" \
        : "=r"(r0), "=r"(r1), "=r"(r2), "=r"(r3) : "r"(addr))

// ------------- 2xFP16 GEMM: CTA 128x256, warp 64x64, CHUNK 64 -------------
#define CHUNK 64
#define RSU   36                        // u32 per row (128B data + 16B pad)
#define A_U32 (128 * RSU)               // 4608 per A array
#define B_U32 (256 * RSU)               // 9216
#define STG_U32 (2 * A_U32 + B_U32)     // 18432 u32 = 73728 B
#define OFF_AL (A_U32)
#define OFF_B  (2 * A_U32)
#define GSMEM_BYTES (2 * STG_U32 * 4)   // 147456

template<bool GELU, bool WPLAIN, bool WH, bool WB>
__global__ __launch_bounds__(256, 1) void gemm_mma(
    const fp16* __restrict__ Ah, const fp16* __restrict__ Al,
    const fp16* __restrict__ Bh,
    const float* __restrict__ bias,
    float* __restrict__ Cp, fp16* __restrict__ Ch, fp16* __restrict__ Cl,
    bf16* __restrict__ Cbb, bf16* __restrict__ Cbs,
    int K, int N)
{
    extern __shared__ uint32_t smem[];
    const int tid  = threadIdx.x;
    const int wid  = tid >> 5;
    const int lane = tid & 31;
    const int m0 = blockIdx.y * 128;
    const int n0 = blockIdx.x * 256;
    const int wm = wid & 1;            // 64-row slab
    const int wn = wid >> 1;           // 64-col slab (4)
    const uint32_t sbase = smem_to_u32(smem);

    float acc[4][8][4];
#pragma unroll
    for (int i = 0; i < 4; i++)
#pragma unroll
        for (int j = 0; j < 8; j++)
#pragma unroll
            for (int r = 0; r < 4; r++) acc[i][j][r] = 0.0f;

    const int nch = K / CHUNK;

    // A: 128 rows x 8 segs x 2 arrays = 2048 segs; B: 256 x 8 = 2048 segs
    auto load_stage = [&](int stage, int kc) {
        const uint32_t st = sbase + (uint32_t)stage * STG_U32 * 4;
#pragma unroll
        for (int t = 0; t < 4; t++) {
            const int seg = tid + t * 256;
            const int row = seg >> 3;
            const int q   = seg & 7;
            const uint32_t soff = (uint32_t)row * 144 + q * 16;
            const size_t  aofg = (size_t)(m0 + row) * K + kc + q * 8;
            CP_ASYNC16(st + soff,                Ah + aofg);
            CP_ASYNC16(st + OFF_AL * 4 + soff,   Al + aofg);
        }
#pragma unroll
        for (int t = 0; t < 8; t++) {
            const int seg = tid + t * 256;
            const int row = seg >> 3;
            const int q   = seg & 7;
            const uint32_t soff = (uint32_t)row * 144 + q * 16;
            const size_t  bofg = (size_t)(n0 + row) * K + kc + q * 8;
            CP_ASYNC16(st + OFF_B * 4 + soff, Bh + bofg);
        }
    };

    load_stage(0, 0);
    CP_COMMIT();

    const int lr = lane >> 2;
    const int lc = lane & 3;

    for (int c = 0; c < nch; c++) {
        if (c + 1 < nch) {
            load_stage((c + 1) & 1, (c + 1) * CHUNK);
            CP_COMMIT();
            CP_WAIT(1);
        } else {
            CP_WAIT(0);
        }
        __syncthreads();

        const uint32_t* sAh = smem + (size_t)(c & 1) * STG_U32;
        const uint32_t* sAl = sAh + OFF_AL;
        const uint32_t* sBh = sAh + OFF_B;

#pragma unroll
        for (int ks = 0; ks < 4; ks++) {
            const int kc = ks * 8;
            uint32_t bh[8][2];
#pragma unroll
            for (int j = 0; j < 8; j++) {
                const int base = (wn * 64 + j * 8 + lr) * RSU + kc + lc;
                bh[j][0] = sBh[base];
                bh[j][1] = sBh[base + 4];
            }
            uint32_t ah[4][4], al[4][4];
#pragma unroll
            for (int i = 0; i < 4; i++) {
                const int base = (wm * 64 + i * 16 + lr) * RSU + kc + lc;
                ah[i][0] = sAh[base];
                ah[i][1] = sAh[base + 8 * RSU];
                ah[i][2] = sAh[base + 4];
                ah[i][3] = sAh[base + 8 * RSU + 4];
                al[i][0] = sAl[base];
                al[i][1] = sAl[base + 8 * RSU];
                al[i][2] = sAl[base + 4];
                al[i][3] = sAl[base + 8 * RSU + 4];
            }
            // term-major: consecutive MMAs hit independent accumulators
#pragma unroll
            for (int i = 0; i < 4; i++)
#pragma unroll
                for (int j = 0; j < 8; j++)
                    MMA_F16(acc[i][j], ah[i], bh[j]);
#pragma unroll
            for (int i = 0; i < 4; i++)
#pragma unroll
                for (int j = 0; j < 8; j++)
                    MMA_F16(acc[i][j], al[i], bh[j]);
        }
        __syncthreads();
    }

#pragma unroll
    for (int i = 0; i < 4; i++) {
#pragma unroll
        for (int j = 0; j < 8; j++) {
            const int gr = m0 + wm * 64 + i * 16 + lr;
            const int gc = n0 + wn * 64 + j * 8 + lc * 2;
            const float b0 = bias[gc], b1 = bias[gc + 1];
#pragma unroll
            for (int half = 0; half < 2; half++) {
                const int row = gr + half * 8;
                float y0 = acc[i][j][half * 2 + 0] * INVWS + b0;
                float y1 = acc[i][j][half * 2 + 1] * INVWS + b1;
                if (GELU) { y0 = gelu_exact(y0); y1 = gelu_exact(y1); }
                const size_t o = (size_t)row * N + gc;
                if (WPLAIN) *(float2*)&Cp[o] = make_float2(y0, y1);
                if (WH) {
                    fp16 h0, l0_, h1, l1_;
                    split_h(y0, h0, l0_);
                    split_h(y1, h1, l1_);
                    *(__half2*)&Ch[o] = __half2(h0, h1);
                    *(__half2*)&Cl[o] = __half2(l0_, l1_);
                }
                if (WB) {
                    bf16 hb0, hs0, hb1, hs1;
                    split_bf(y0, hb0, hs0);
                    split_bf(y1, hb1, hs1);
                    *(__nv_bfloat162*)&Cbb[o] = __nv_bfloat162(hb0, hb1);
                    *(__nv_bfloat162*)&Cbs[o] = __nv_bfloat162(hs0, hs1);
                }
            }
        }
    }
}

// ---------------- MMA flash attention (unchanged) -------------------------
#define AT_SMEM 74240

__global__ __launch_bounds__(256, 2) void flash_mma(
    const bf16* __restrict__ qkvb, const bf16* __restrict__ qkvs,
    const float* __restrict__ w,
    fp16* __restrict__ oh, fp16* __restrict__ ol)
{
    extern __shared__ uint32_t smem[];
    const uint32_t sb = smem_to_u32(smem);
    const int tid = threadIdx.x, wid = tid >> 5, lane = tid & 31;
    const int lr = lane >> 2, lc = lane & 3;
    const int bidx = blockIdx.y >> 4;
    const int h    = blockIdx.y & 15;
    const int q0   = blockIdx.x * 128;
    const int hq = h * DK_;
    const int hk = D_ + h * DK_;
    const int hv = 2 * D_ + h * DK_;
    const size_t bm = (size_t)bidx * M_;

#pragma unroll
    for (int t = 0; t < 4; t++) {
        const int seg = tid + t * 256;
        const int row = seg >> 3, q8 = seg & 7;
        const size_t src = (bm + q0 + row) * QS_ + hq + q8 * 8;
        const uint32_t d = sb + (uint32_t)row * 144 + q8 * 16;
        CP_ASYNC16(d,         qkvb + src);
        CP_ASYNC16(d + 18432, qkvs + src);
    }
    CP_COMMIT();
    CP_WAIT(0);
    __syncthreads();

    uint32_t aqb[4][4], aqs[4][4];
#pragma unroll
    for (int ks = 0; ks < 4; ks++) {
        const int base = (wid * 16 + lr) * 36 + ks * 8 + lc;
        aqb[ks][0] = smem[base];
        aqb[ks][1] = smem[base + 288];
        aqb[ks][2] = smem[base + 4];
        aqb[ks][3] = smem[base + 292];
        aqs[ks][0] = smem[base + 4608];
        aqs[ks][1] = smem[base + 4608 + 288];
        aqs[ks][2] = smem[base + 4608 + 4];
        aqs[ks][3] = smem[base + 4608 + 292];
    }
    __syncthreads();

    auto load_kv = [&](int st, int kb0) {
#pragma unroll
        for (int t = 0; t < 2; t++) {
            const int seg = tid + t * 256;
            const int row = seg >> 3, q8 = seg & 7;
            const size_t srck = (bm + kb0 + row) * QS_ + hk + q8 * 8;
            const size_t srcv = (bm + kb0 + row) * QS_ + hv + q8 * 8;
            const uint32_t dk = sb + st * 18432 + (uint32_t)row * 144 + q8 * 16;
            const uint32_t dv = sb + 36864 + st * 18432 + (uint32_t)row * 144 + q8 * 16;
            CP_ASYNC16(dk,        qkvb + srck);
            CP_ASYNC16(dk + 9216, qkvs + srck);
            CP_ASYNC16(dv,        qkvb + srcv);
            CP_ASYNC16(dv + 9216, qkvs + srcv);
        }
        if (tid < 16)
            CP_ASYNC16(sb + 73728 + st * 256 + tid * 16, w + bm + kb0 + tid * 4);
    };
    load_kv(0, 0);
    CP_COMMIT();

    float oa[8][4];
    float m0v = -1e30f, m1v = -1e30f, l0 = 0.0f, l1 = 0.0f;
#pragma unroll
    for (int j = 0; j < 8; j++)
#pragma unroll
        for (int r = 0; r < 4; r++) oa[j][r] = 0.0f;

    for (int kb = 0; kb < 16; kb++) {
        const int st = kb & 1;
        if (kb + 1 < 16) {
            load_kv((kb + 1) & 1, (kb + 1) * 64);
            CP_COMMIT();
            CP_WAIT(1);
        } else {
            CP_WAIT(0);
        }
        __syncthreads();

        const uint32_t* skb = smem + st * 4608;
        const uint32_t* sks = skb + 2304;
        float s_[8][4];
#pragma unroll
        for (int j = 0; j < 8; j++)
#pragma unroll
            for (int r = 0; r < 4; r++) s_[j][r] = 0.0f;

#pragma unroll
        for (int ks = 0; ks < 4; ks++) {
            uint32_t kfb[8][2], kfs[8][2];
#pragma unroll
            for (int j = 0; j < 8; j++) {
                const int base = (j * 8 + lr) * 36 + ks * 8 + lc;
                kfb[j][0] = skb[base];
                kfb[j][1] = skb[base + 4];
                kfs[j][0] = sks[base];
                kfs[j][1] = sks[base + 4];
            }
#pragma unroll
            for (int j = 0; j < 8; j++) {
                MMA_BF16(s_[j], aqb[ks], kfb[j]);
                MMA_BF16(s_[j], aqb[ks], kfs[j]);
                MMA_BF16(s_[j], aqs[ks], kfb[j]);
            }
        }

        const float* sw = (const float*)smem + 18432 + st * 64;
        float rmax0 = -1e30f, rmax1 = -1e30f;
        float x[8][4];
#pragma unroll
        for (int j = 0; j < 8; j++) {
            const float2 wp = *(const float2*)(sw + j * 8 + 2 * lc);
            x[j][0] = s_[j][0] * 0.125f + wp.x;
            x[j][1] = s_[j][1] * 0.125f + wp.y;
            x[j][2] = s_[j][2] * 0.125f + wp.x;
            x[j][3] = s_[j][3] * 0.125f + wp.y;
            rmax0 = fmaxf(rmax0, fmaxf(x[j][0], x[j][1]));
            rmax1 = fmaxf(rmax1, fmaxf(x[j][2], x[j][3]));
        }
        rmax0 = fmaxf(rmax0, __shfl_xor_sync(0xffffffffu, rmax0, 1));
        rmax0 = fmaxf(rmax0, __shfl_xor_sync(0xffffffffu, rmax0, 2));
        rmax1 = fmaxf(rmax1, __shfl_xor_sync(0xffffffffu, rmax1, 1));
        rmax1 = fmaxf(rmax1, __shfl_xor_sync(0xffffffffu, rmax1, 2));
        const float mn0 = fmaxf(m0v, rmax0);
        const float mn1 = fmaxf(m1v, rmax1);
        const float c0 = __expf(m0v - mn0);
        const float c1 = __expf(m1v - mn1);
        float rs0 = 0.0f, rs1 = 0.0f;
        uint32_t pb01[8], pb23[8], ps01[8], ps23[8];
#pragma unroll
        for (int j = 0; j < 8; j++) {
            const float p0 = __expf(x[j][0] - mn0);
            const float p1 = __expf(x[j][1] - mn0);
            const float p2 = __expf(x[j][2] - mn1);
            const float p3 = __expf(x[j][3] - mn1);
            rs0 += p0 + p1;
            rs1 += p2 + p3;
            bf16 b0, sv0, b1, sv1, b2, sv2, b3, sv3;
            split_bf(p0, b0, sv0); split_bf(p1, b1, sv1);
            split_bf(p2, b2, sv2); split_bf(p3, b3, sv3);
            pb01[j] = pack_bf2(b0, b1);
            pb23[j] = pack_bf2(b2, b3);
            ps01[j] = pack_bf2(sv0, sv1);
            ps23[j] = pack_bf2(sv2, sv3);
        }
        rs0 += __shfl_xor_sync(0xffffffffu, rs0, 1);
        rs0 += __shfl_xor_sync(0xffffffffu, rs0, 2);
        rs1 += __shfl_xor_sync(0xffffffffu, rs1, 1);
        rs1 += __shfl_xor_sync(0xffffffffu, rs1, 2);
        l0 = l0 * c0 + rs0;
        l1 = l1 * c1 + rs1;
        m0v = mn0; m1v = mn1;
#pragma unroll
        for (int j = 0; j < 8; j++) {
            oa[j][0] *= c0; oa[j][1] *= c0;
            oa[j][2] *= c1; oa[j][3] *= c1;
        }

        const uint32_t vbase = sb + 36864 + st * 18432;
        const int lgrp = lane >> 3, l8 = lane & 7;
#pragma unroll
        for (int kp = 0; kp < 4; kp++) {
            const uint32_t apb[4] = { pb01[2*kp], pb23[2*kp], pb01[2*kp+1], pb23[2*kp+1] };
            const uint32_t aps[4] = { ps01[2*kp], ps23[2*kp], ps01[2*kp+1], ps23[2*kp+1] };
            const int vrow = kp * 16 + (lgrp & 1) * 8 + l8;
            const uint32_t va = vbase + (uint32_t)vrow * 144 + (lgrp >> 1) * 16;
            uint32_t vfb[8][2], vfs[8][2];
#pragma unroll
            for (int jn = 0; jn < 4; jn++) {
                LDSM_X4_T(vfb[2*jn][0], vfb[2*jn][1], vfb[2*jn+1][0], vfb[2*jn+1][1], va + jn * 32);
                LDSM_X4_T(vfs[2*jn][0], vfs[2*jn][1], vfs[2*jn+1][0], vfs[2*jn+1][1], va + 9216 + jn * 32);
            }
#pragma unroll
            for (int j2 = 0; j2 < 8; j2++) {
                MMA_BF16(oa[j2], apb, vfb[j2]);
                MMA_BF16(oa[j2], apb, vfs[j2]);
                MMA_BF16(oa[j2], aps, vfb[j2]);
            }
        }
        __syncthreads();
    }

    const float i0 = 1.0f / l0;
    const float i1 = 1.0f / l1;
    const int r0g = q0 + wid * 16 + lr;
#pragma unroll
    for (int j2 = 0; j2 < 8; j2++) {
        const size_t o0 = (bm + r0g) * D_ + h * DK_ + j2 * 8 + 2 * lc;
        const size_t o1 = o0 + 8 * D_;
        fp16 h0, l0_, h1, l1_;
        split_h(oa[j2][0] * i0, h0, l0_);
        split_h(oa[j2][1] * i0, h1, l1_);
        *(__half2*)&oh[o0] = __half2(h0, h1);
        *(__half2*)&ol[o0] = __half2(l0_, l1_);
        split_h(oa[j2][2] * i1, h0, l0_);
        split_h(oa[j2][3] * i1, h1, l1_);
        *(__half2*)&oh[o1] = __half2(h0, h1);
        *(__half2*)&ol[o1] = __half2(l0_, l1_);
    }
}

// ---------------- weight prep ----------------
__global__ __launch_bounds__(256) void wprep(
    const float* __restrict__ W, fp16* __restrict__ T,
    int K, int N, long out_ls)
{
    __shared__ float t[32][33];
    const int n0 = blockIdx.x * 32, k0 = blockIdx.y * 32;
    const size_t zin  = (size_t)blockIdx.z * K * N;
    const size_t zout = (size_t)blockIdx.z * out_ls;
    const int tx = threadIdx.x, ty = threadIdx.y;
#pragma unroll
    for (int r = ty; r < 32; r += 8)
        t[r][tx] = W[zin + (size_t)(k0 + r) * N + n0 + tx];
    __syncthreads();
#pragma unroll
    for (int r = ty; r < 32; r += 8)
        T[zout + (size_t)(n0 + r) * K + k0 + tx] =
            __float2half_rn(t[tx][r] * WSCALE);
}

__global__ __launch_bounds__(256) void catbias(
    const float* __restrict__ bq, const float* __restrict__ bk,
    const float* __restrict__ bv, float* __restrict__ out)
{
    const int i = blockIdx.x * 256 + threadIdx.x;
    const int l = i / QS_, c = i % QS_;
    float v;
    if (c < D_)          v = bq[l * D_ + c];
    else if (c < 2 * D_) v = bk[l * D_ + c - D_];
    else                 v = bv[l * D_ + c - 2 * D_];
    out[i] = v;
}

__global__ __launch_bounds__(1024) void split_x(
    const float* __restrict__ e, float* __restrict__ x,
    fp16* __restrict__ xh, fp16* __restrict__ xl)
{
    const size_t i = (size_t)blockIdx.x * 1024 + threadIdx.x;
    const float v = e[i];
    x[i] = v;
    fp16 h, l;
    split_h(v, h, l);
    xh[i] = h;
    xl[i] = l;
}

// ---------------- residual + LayerNorm (+fp16 split out) ------------------
__device__ __forceinline__ float block_sum256(float val, float* red) {
    const int lane = threadIdx.x & 31;
    const int wid  = threadIdx.x >> 5;
#pragma unroll
    for (int o = 16; o > 0; o >>= 1) val += __shfl_xor_sync(0xffffffffu, val, o);
    if (lane == 0) red[wid] = val;
    __syncthreads();
    float t = (threadIdx.x < 8) ? red[threadIdx.x] : 0.0f;
    if (wid == 0) {
#pragma unroll
        for (int o = 4; o > 0; o >>= 1) t += __shfl_xor_sync(0xffffffffu, t, o);
        if (lane == 0) red[0] = t;
    }
    __syncthreads();
    float r = red[0];
    __syncthreads();
    return r;
}

__global__ __launch_bounds__(256) void add_ln(
    const float* __restrict__ xin, const float* __restrict__ del,
    const float* __restrict__ g, const float* __restrict__ be,
    float* __restrict__ xout, fp16* __restrict__ xh, fp16* __restrict__ xl)
{
    __shared__ float red[8];
    const int row = blockIdx.x;
    const int c = threadIdx.x * 4;
    const size_t ro = (size_t)row * D_;

    const float4 xv = *(const float4*)&xin[ro + c];
    const float4 dv = *(const float4*)&del[ro + c];
    float v[4] = { xv.x + dv.x, xv.y + dv.y, xv.z + dv.z, xv.w + dv.w };
    const float mu = block_sum256(v[0] + v[1] + v[2] + v[3], red) * (1.0f / D_);
    float qs = 0.0f;
#pragma unroll
    for (int u = 0; u < 4; u++) {
        const float d = v[u] - mu;
        qs += d * d;
    }
    const float var = block_sum256(qs, red) * (1.0f / D_);
    const float rstd = rsqrtf(var + 1e-5f);

    const float4 gv = *(const float4*)&g[c];
    const float4 bv = *(const float4*)&be[c];
    float y[4];
    y[0] = (v[0] - mu) * rstd * gv.x + bv.x;
    y[1] = (v[1] - mu) * rstd * gv.y + bv.y;
    y[2] = (v[2] - mu) * rstd * gv.z + bv.z;
    y[3] = (v[3] - mu) * rstd * gv.w + bv.w;
    *(float4*)&xout[ro + c] = make_float4(y[0], y[1], y[2], y[3]);
    fp16 h0, l0, h1, l1;
    split_h(y[0], h0, l0); split_h(y[1], h1, l1);
    *(__half2*)&xh[ro + c] = __half2(h0, h1);
    *(__half2*)&xl[ro + c] = __half2(l0, l1);
    split_h(y[2], h0, l0); split_h(y[3], h1, l1);
    *(__half2*)&xh[ro + c + 2] = __half2(h0, h1);
    *(__half2*)&xl[ro + c + 2] = __half2(l0, l1);
}

// ---------------- host driver ----------------
extern "C" void kernel_launch(void* const* d_in, const int* in_sizes, int n_in,
                              void* d_out, int out_size) {
    const float* embeds  = (const float*)d_in[0];
    const float* weights = (const float*)d_in[1];
    const float* Wq = (const float*)d_in[2];
    const float* bq = (const float*)d_in[3];
    const float* Wk = (const float*)d_in[4];
    const float* bk = (const float*)d_in[5];
    const float* Wv = (const float*)d_in[6];
    const float* bv = (const float*)d_in[7];
    const float* Wo = (const float*)d_in[8];
    const float* bo = (const float*)d_in[9];
    const float* W1 = (const float*)d_in[10];
    const float* b1 = (const float*)d_in[11];
    const float* W2 = (const float*)d_in[12];
    const float* b2 = (const float*)d_in[13];
    const float* g1 = (const float*)d_in[14];
    const float* be1= (const float*)d_in[15];
    const float* g2 = (const float*)d_in[16];
    const float* be2= (const float*)d_in[17];

    float *px, *pres, *pbqkv;
    fp16 *pxh,*pxl,*poh,*pol,*pfh,*pfl,*pwqkv,*pwo,*pw1,*pw2;
    bf16 *pqkvb,*pqkvs;
    cudaGetSymbolAddress((void**)&px,   g_x);
    cudaGetSymbolAddress((void**)&pres, g_res);
    cudaGetSymbolAddress((void**)&pbqkv,g_bqkv);
    cudaGetSymbolAddress((void**)&pxh,  g_xh);
    cudaGetSymbolAddress((void**)&pxl,  g_xl);
    cudaGetSymbolAddress((void**)&pqkvb,g_qkvb);
    cudaGetSymbolAddress((void**)&pqkvs,g_qkvs);
    cudaGetSymbolAddress((void**)&poh,  g_oh);
    cudaGetSymbolAddress((void**)&pol,  g_ol);
    cudaGetSymbolAddress((void**)&pfh,  g_fh);
    cudaGetSymbolAddress((void**)&pfl,  g_fl);
    cudaGetSymbolAddress((void**)&pwqkv,g_wqkv);
    cudaGetSymbolAddress((void**)&pwo,  g_wo);
    cudaGetSymbolAddress((void**)&pw1,  g_w1);
    cudaGetSymbolAddress((void**)&pw2,  g_w2);

    cudaFuncSetAttribute(gemm_mma<false, false, false, true>,
                         cudaFuncAttributeMaxDynamicSharedMemorySize, GSMEM_BYTES);
    cudaFuncSetAttribute(gemm_mma<false, true, false, false>,
                         cudaFuncAttributeMaxDynamicSharedMemorySize, GSMEM_BYTES);
    cudaFuncSetAttribute(gemm_mma<true, false, true, false>,
                         cudaFuncAttributeMaxDynamicSharedMemorySize, GSMEM_BYTES);
    cudaFuncSetAttribute(flash_mma,
                         cudaFuncAttributeMaxDynamicSharedMemorySize, AT_SMEM);

    const long ls3 = (long)3 * D_ * D_;
    catbias<<<NLAYERS * QS_ / 256, 256>>>(bq, bk, bv, pbqkv);
    split_x<<<ROWS * D_ / 1024, 1024>>>(embeds, px, pxh, pxl);
    wprep<<<dim3(D_/32, D_/32, NLAYERS), dim3(32, 8)>>>(Wq, pwqkv,           D_, D_, ls3);
    wprep<<<dim3(D_/32, D_/32, NLAYERS), dim3(32, 8)>>>(Wk, pwqkv + D_*D_,   D_, D_, ls3);
    wprep<<<dim3(D_/32, D_/32, NLAYERS), dim3(32, 8)>>>(Wv, pwqkv + 2*D_*D_, D_, D_, ls3);

    const dim3 gQKV(QS_ / 256, ROWS / 128);  // (12, 64)
    const dim3 gD(D_ / 256, ROWS / 128);     // (4, 64)
    const dim3 gF(F_ / 256, ROWS / 128);     // (16, 64)
    const dim3 gA(M_ / 128, B_ * H_);        // (8, 128)

    for (int l = 0; l < NLAYERS; l++) {
        gemm_mma<false, false, false, true><<<gQKV, 256, GSMEM_BYTES>>>(
            pxh, pxl, pwqkv + (size_t)l*ls3, pbqkv + (size_t)l*QS_,
            nullptr, nullptr, nullptr, pqkvb, pqkvs, D_, QS_);

        if (l == 0) {
            wprep<<<dim3(D_/32, D_/32, NLAYERS), dim3(32, 8)>>>(Wo, pwo, D_, D_, (long)D_*D_);
            wprep<<<dim3(F_/32, D_/32, NLAYERS), dim3(32, 8)>>>(W1, pw1, D_, F_, (long)D_*F_);
            wprep<<<dim3(D_/32, F_/32, NLAYERS), dim3(32, 8)>>>(W2, pw2, F_, D_, (long)F_*D_);
        }

        flash_mma<<<gA, 256, AT_SMEM>>>(pqkvb, pqkvs, weights, poh, pol);

        gemm_mma<false, true, false, false><<<gD, 256, GSMEM_BYTES>>>(
            poh, pol, pwo + (size_t)l*D_*D_, bo + (size_t)l*D_,
            pres, nullptr, nullptr, nullptr, nullptr, D_, D_);
        add_ln<<<ROWS, 256>>>(px, pres, g1 + (size_t)l*D_, be1 + (size_t)l*D_,
                              px, pxh, pxl);

        gemm_mma<true, false, true, false><<<gF, 256, GSMEM_BYTES>>>(
            pxh, pxl, pw1 + (size_t)l*D_*F_, b1 + (size_t)l*F_,
            nullptr, pfh, pfl, nullptr, nullptr, D_, F_);
        gemm_mma<false, true, false, false><<<gD, 256, GSMEM_BYTES>>>(
            pfh, pfl, pw2 + (size_t)l*F_*D_, b2 + (size_t)l*D_,
            pres, nullptr, nullptr, nullptr, nullptr, F_, D_);
        add_ln<<<ROWS, 256>>>(px, pres, g2 + (size_t)l*D_, be2 + (size_t)l*D_,
                              px, pxh, pxl);
    }

    cudaMemcpyAsync(d_out, px, sizeof(float) * (size_t)ROWS * D_,
                    cudaMemcpyDeviceToDevice);
}

// round 14
// speedup vs baseline: 2.2095x; 1.4883x over previous
#include <cuda_runtime.h>
#include <cuda_bf16.h>
#include <cuda_fp16.h>
#include <math.h>
#include <stdint.h>

#define B_ 8
#define M_ 1024
#define D_ 1024
#define H_ 16
#define F_ 4096
#define NLAYERS 4
#define DK_ 64
#define ROWS (B_*M_)
#define QS_ (3*D_)
#define WSCALE 64.0f
#define INVWS  0.015625f

typedef __nv_bfloat16 bf16;
typedef __half fp16;

// ---------------- device scratch ----------------
__device__ float g_x   [ROWS * D_];
__device__ float g_res [ROWS * D_];
__device__ float g_bqkv[NLAYERS * QS_];
__device__ fp16  g_xh  [ROWS * D_];
__device__ bf16  g_qkvb[ROWS * QS_];
__device__ bf16  g_qkvs[ROWS * QS_];
__device__ fp16  g_oh  [ROWS * D_];
__device__ fp16  g_fh  [ROWS * F_];
__device__ fp16 g_wqkv[NLAYERS*3*D_*D_];
__device__ fp16 g_wo  [NLAYERS*D_*D_];
__device__ fp16 g_w1  [NLAYERS*D_*F_];
__device__ fp16 g_w2  [NLAYERS*F_*D_];

// ---------------- helpers ----------------
__device__ __forceinline__ uint32_t smem_to_u32(const void* p) {
    uint32_t a;
    asm("{ .reg .u64 t; cvta.to.shared.u64 t, %1; cvt.u32.u64 %0, t; }" : "=r"(a) : "l"(p));
    return a;
}
__device__ __forceinline__ float gelu_exact(float x) {
    return 0.5f * x * (1.0f + erff(x * 0.70710678118654752f));
}
__device__ __forceinline__ void split_bf(float y, bf16& b, bf16& s) {
    b = __float2bfloat16_rn(y);
    s = __float2bfloat16_rn(y - __bfloat162float(b));
}
__device__ __forceinline__ uint32_t pack_bf2(bf16 a, bf16 b) {
    __nv_bfloat162 t(a, b);
    return *reinterpret_cast<uint32_t*>(&t);
}

#define CP_ASYNC16(dst, src) \
    asm volatile("cp.async.cg.shared.global [%0], [%1], 16;" :: "r"(dst), "l"(src))
#define CP_COMMIT() asm volatile("cp.async.commit_group;")
#define CP_WAIT(n)  asm volatile("cp.async.wait_group %0;" :: "n"(n))

#define MMA_F16(d, a, b) \
    asm volatile("mma.sync.aligned.m16n8k16.row.col.f32.f16.f16.f32 " \
        "{%0,%1,%2,%3}, {%4,%5,%6,%7}, {%8,%9}, {%0,%1,%2,%3};" \
        : "+f"((d)[0]), "+f"((d)[1]), "+f"((d)[2]), "+f"((d)[3]) \
        : "r"((a)[0]), "r"((a)[1]), "r"((a)[2]), "r"((a)[3]), \
          "r"((b)[0]), "r"((b)[1]))

#define MMA_BF16(d, a, b) \
    asm volatile("mma.sync.aligned.m16n8k16.row.col.f32.bf16.bf16.f32 " \
        "{%0,%1,%2,%3}, {%4,%5,%6,%7}, {%8,%9}, {%0,%1,%2,%3};" \
        : "+f"((d)[0]), "+f"((d)[1]), "+f"((d)[2]), "+f"((d)[3]) \
        : "r"((a)[0]), "r"((a)[1]), "r"((a)[2]), "r"((a)[3]), \
          "r"((b)[0]), "r"((b)[1]))

#define LDSM_X4_T(r0, r1, r2, r3, addr) \
    asm volatile("ldmatrix.sync.aligned.m8n8.x4.trans.shared.b16 {%0,%1,%2,%3}, [%4];" \
        : "=r"(r0), "=r"(r1), "=r"(r2), "=r"(r3) : "r"(addr))

// -------- 1xFP16 GEMM: C = Ah·Bh/64 + bias, 128x128, CHUNK 64, 2 CTA/SM ---
#define CHUNK 64
#define RSU   36                       // u32 per row (128B data + 16B pad)
#define ARR_U32 (128 * RSU)            // 4608
#define STG_U32 (2 * ARR_U32)          // 9216 u32 = 36864 B
#define GSMEM_BYTES (2 * STG_U32 * 4)  // 73728

template<bool GELU, bool WPLAIN, bool WH, bool WB>
__global__ __launch_bounds__(256, 2) void gemm_mma(
    const fp16* __restrict__ Ah, const fp16* __restrict__ Bh,
    const float* __restrict__ bias,
    float* __restrict__ Cp, fp16* __restrict__ Ch,
    bf16* __restrict__ Cbb, bf16* __restrict__ Cbs,
    int K, int N)
{
    extern __shared__ uint32_t smem[];
    const int tid  = threadIdx.x;
    const int wid  = tid >> 5;
    const int lane = tid & 31;
    const int m0 = blockIdx.y * 128;
    const int n0 = blockIdx.x * 128;
    const int wm = wid & 1;
    const int wn = wid >> 1;
    const uint32_t sbase = smem_to_u32(smem);

    float acc[4][4][4];
#pragma unroll
    for (int i = 0; i < 4; i++)
#pragma unroll
        for (int j = 0; j < 4; j++)
#pragma unroll
            for (int r = 0; r < 4; r++) acc[i][j][r] = 0.0f;

    const int nch = K / CHUNK;

    // per array: 128 rows x 128B = 1024 16B-segs; 256 thr -> 4 each
    auto load_stage = [&](int stage, int kc) {
        const uint32_t st = sbase + (uint32_t)stage * STG_U32 * 4;
#pragma unroll
        for (int t = 0; t < 4; t++) {
            const int seg = tid + t * 256;
            const int row = seg >> 3;
            const int q   = seg & 7;
            const uint32_t soff = (uint32_t)row * 144 + q * 16;
            const size_t  aofg = (size_t)(m0 + row) * K + kc + q * 8;
            const size_t  bofg = (size_t)(n0 + row) * K + kc + q * 8;
            CP_ASYNC16(st + soff,               Ah + aofg);
            CP_ASYNC16(st + ARR_U32 * 4 + soff, Bh + bofg);
        }
    };

    load_stage(0, 0);
    CP_COMMIT();

    const int lr = lane >> 2;
    const int lc = lane & 3;

    for (int c = 0; c < nch; c++) {
        if (c + 1 < nch) {
            load_stage((c + 1) & 1, (c + 1) * CHUNK);
            CP_COMMIT();
            CP_WAIT(1);
        } else {
            CP_WAIT(0);
        }
        __syncthreads();

        const uint32_t* sAh = smem + (size_t)(c & 1) * STG_U32;
        const uint32_t* sBh = sAh + ARR_U32;

#pragma unroll
        for (int ks = 0; ks < 4; ks++) {
            const int kc = ks * 8;
            uint32_t ah[4][4];
#pragma unroll
            for (int i = 0; i < 4; i++) {
                const int base = (wm * 64 + i * 16 + lr) * RSU + kc + lc;
                ah[i][0] = sAh[base];
                ah[i][1] = sAh[base + 8 * RSU];
                ah[i][2] = sAh[base + 4];
                ah[i][3] = sAh[base + 8 * RSU + 4];
            }
            uint32_t bh[4][2];
#pragma unroll
            for (int j = 0; j < 4; j++) {
                const int base = (wn * 32 + j * 8 + lr) * RSU + kc + lc;
                bh[j][0] = sBh[base];
                bh[j][1] = sBh[base + 4];
            }
#pragma unroll
            for (int i = 0; i < 4; i++)
#pragma unroll
                for (int j = 0; j < 4; j++)
                    MMA_F16(acc[i][j], ah[i], bh[j]);
        }
        __syncthreads();
    }

#pragma unroll
    for (int i = 0; i < 4; i++) {
#pragma unroll
        for (int j = 0; j < 4; j++) {
            const int gr = m0 + wm * 64 + i * 16 + lr;
            const int gc = n0 + wn * 32 + j * 8 + lc * 2;
            const float b0 = bias[gc], b1 = bias[gc + 1];
#pragma unroll
            for (int half = 0; half < 2; half++) {
                const int row = gr + half * 8;
                float y0 = acc[i][j][half * 2 + 0] * INVWS + b0;
                float y1 = acc[i][j][half * 2 + 1] * INVWS + b1;
                if (GELU) { y0 = gelu_exact(y0); y1 = gelu_exact(y1); }
                const size_t o = (size_t)row * N + gc;
                if (WPLAIN) *(float2*)&Cp[o] = make_float2(y0, y1);
                if (WH)
                    *(__half2*)&Ch[o] = __half2(__float2half_rn(y0),
                                                __float2half_rn(y1));
                if (WB) {
                    bf16 hb0, hs0, hb1, hs1;
                    split_bf(y0, hb0, hs0);
                    split_bf(y1, hb1, hs1);
                    *(__nv_bfloat162*)&Cbb[o] = __nv_bfloat162(hb0, hb1);
                    *(__nv_bfloat162*)&Cbs[o] = __nv_bfloat162(hs0, hs1);
                }
            }
        }
    }
}

// ---------------- MMA flash attention (bf16 3-term, fp16 out) -------------
#define AT_SMEM 74240

__global__ __launch_bounds__(256, 2) void flash_mma(
    const bf16* __restrict__ qkvb, const bf16* __restrict__ qkvs,
    const float* __restrict__ w,
    fp16* __restrict__ oh)
{
    extern __shared__ uint32_t smem[];
    const uint32_t sb = smem_to_u32(smem);
    const int tid = threadIdx.x, wid = tid >> 5, lane = tid & 31;
    const int lr = lane >> 2, lc = lane & 3;
    const int bidx = blockIdx.y >> 4;
    const int h    = blockIdx.y & 15;
    const int q0   = blockIdx.x * 128;
    const int hq = h * DK_;
    const int hk = D_ + h * DK_;
    const int hv = 2 * D_ + h * DK_;
    const size_t bm = (size_t)bidx * M_;

#pragma unroll
    for (int t = 0; t < 4; t++) {
        const int seg = tid + t * 256;
        const int row = seg >> 3, q8 = seg & 7;
        const size_t src = (bm + q0 + row) * QS_ + hq + q8 * 8;
        const uint32_t d = sb + (uint32_t)row * 144 + q8 * 16;
        CP_ASYNC16(d,         qkvb + src);
        CP_ASYNC16(d + 18432, qkvs + src);
    }
    CP_COMMIT();
    CP_WAIT(0);
    __syncthreads();

    uint32_t aqb[4][4], aqs[4][4];
#pragma unroll
    for (int ks = 0; ks < 4; ks++) {
        const int base = (wid * 16 + lr) * 36 + ks * 8 + lc;
        aqb[ks][0] = smem[base];
        aqb[ks][1] = smem[base + 288];
        aqb[ks][2] = smem[base + 4];
        aqb[ks][3] = smem[base + 292];
        aqs[ks][0] = smem[base + 4608];
        aqs[ks][1] = smem[base + 4608 + 288];
        aqs[ks][2] = smem[base + 4608 + 4];
        aqs[ks][3] = smem[base + 4608 + 292];
    }
    __syncthreads();

    auto load_kv = [&](int st, int kb0) {
#pragma unroll
        for (int t = 0; t < 2; t++) {
            const int seg = tid + t * 256;
            const int row = seg >> 3, q8 = seg & 7;
            const size_t srck = (bm + kb0 + row) * QS_ + hk + q8 * 8;
            const size_t srcv = (bm + kb0 + row) * QS_ + hv + q8 * 8;
            const uint32_t dk = sb + st * 18432 + (uint32_t)row * 144 + q8 * 16;
            const uint32_t dv = sb + 36864 + st * 18432 + (uint32_t)row * 144 + q8 * 16;
            CP_ASYNC16(dk,        qkvb + srck);
            CP_ASYNC16(dk + 9216, qkvs + srck);
            CP_ASYNC16(dv,        qkvb + srcv);
            CP_ASYNC16(dv + 9216, qkvs + srcv);
        }
        if (tid < 16)
            CP_ASYNC16(sb + 73728 + st * 256 + tid * 16, w + bm + kb0 + tid * 4);
    };
    load_kv(0, 0);
    CP_COMMIT();

    float oa[8][4];
    float m0v = -1e30f, m1v = -1e30f, l0 = 0.0f, l1 = 0.0f;
#pragma unroll
    for (int j = 0; j < 8; j++)
#pragma unroll
        for (int r = 0; r < 4; r++) oa[j][r] = 0.0f;

    for (int kb = 0; kb < 16; kb++) {
        const int st = kb & 1;
        if (kb + 1 < 16) {
            load_kv((kb + 1) & 1, (kb + 1) * 64);
            CP_COMMIT();
            CP_WAIT(1);
        } else {
            CP_WAIT(0);
        }
        __syncthreads();

        const uint32_t* skb = smem + st * 4608;
        const uint32_t* sks = skb + 2304;
        float s_[8][4];
#pragma unroll
        for (int j = 0; j < 8; j++)
#pragma unroll
            for (int r = 0; r < 4; r++) s_[j][r] = 0.0f;

#pragma unroll
        for (int ks = 0; ks < 4; ks++) {
            uint32_t kfb[8][2], kfs[8][2];
#pragma unroll
            for (int j = 0; j < 8; j++) {
                const int base = (j * 8 + lr) * 36 + ks * 8 + lc;
                kfb[j][0] = skb[base];
                kfb[j][1] = skb[base + 4];
                kfs[j][0] = sks[base];
                kfs[j][1] = sks[base + 4];
            }
#pragma unroll
            for (int j = 0; j < 8; j++) {
                MMA_BF16(s_[j], aqb[ks], kfb[j]);
                MMA_BF16(s_[j], aqb[ks], kfs[j]);
                MMA_BF16(s_[j], aqs[ks], kfb[j]);
            }
        }

        const float* sw = (const float*)smem + 18432 + st * 64;
        float rmax0 = -1e30f, rmax1 = -1e30f;
        float x[8][4];
#pragma unroll
        for (int j = 0; j < 8; j++) {
            const float2 wp = *(const float2*)(sw + j * 8 + 2 * lc);
            x[j][0] = s_[j][0] * 0.125f + wp.x;
            x[j][1] = s_[j][1] * 0.125f + wp.y;
            x[j][2] = s_[j][2] * 0.125f + wp.x;
            x[j][3] = s_[j][3] * 0.125f + wp.y;
            rmax0 = fmaxf(rmax0, fmaxf(x[j][0], x[j][1]));
            rmax1 = fmaxf(rmax1, fmaxf(x[j][2], x[j][3]));
        }
        rmax0 = fmaxf(rmax0, __shfl_xor_sync(0xffffffffu, rmax0, 1));
        rmax0 = fmaxf(rmax0, __shfl_xor_sync(0xffffffffu, rmax0, 2));
        rmax1 = fmaxf(rmax1, __shfl_xor_sync(0xffffffffu, rmax1, 1));
        rmax1 = fmaxf(rmax1, __shfl_xor_sync(0xffffffffu, rmax1, 2));
        const float mn0 = fmaxf(m0v, rmax0);
        const float mn1 = fmaxf(m1v, rmax1);
        const float c0 = __expf(m0v - mn0);
        const float c1 = __expf(m1v - mn1);
        float rs0 = 0.0f, rs1 = 0.0f;
        uint32_t pb01[8], pb23[8], ps01[8], ps23[8];
#pragma unroll
        for (int j = 0; j < 8; j++) {
            const float p0 = __expf(x[j][0] - mn0);
            const float p1 = __expf(x[j][1] - mn0);
            const float p2 = __expf(x[j][2] - mn1);
            const float p3 = __expf(x[j][3] - mn1);
            rs0 += p0 + p1;
            rs1 += p2 + p3;
            bf16 b0, sv0, b1, sv1, b2, sv2, b3, sv3;
            split_bf(p0, b0, sv0); split_bf(p1, b1, sv1);
            split_bf(p2, b2, sv2); split_bf(p3, b3, sv3);
            pb01[j] = pack_bf2(b0, b1);
            pb23[j] = pack_bf2(b2, b3);
            ps01[j] = pack_bf2(sv0, sv1);
            ps23[j] = pack_bf2(sv2, sv3);
        }
        rs0 += __shfl_xor_sync(0xffffffffu, rs0, 1);
        rs0 += __shfl_xor_sync(0xffffffffu, rs0, 2);
        rs1 += __shfl_xor_sync(0xffffffffu, rs1, 1);
        rs1 += __shfl_xor_sync(0xffffffffu, rs1, 2);
        l0 = l0 * c0 + rs0;
        l1 = l1 * c1 + rs1;
        m0v = mn0; m1v = mn1;
#pragma unroll
        for (int j = 0; j < 8; j++) {
            oa[j][0] *= c0; oa[j][1] *= c0;
            oa[j][2] *= c1; oa[j][3] *= c1;
        }

        const uint32_t vbase = sb + 36864 + st * 18432;
        const int lgrp = lane >> 3, l8 = lane & 7;
#pragma unroll
        for (int kp = 0; kp < 4; kp++) {
            const uint32_t apb[4] = { pb01[2*kp], pb23[2*kp], pb01[2*kp+1], pb23[2*kp+1] };
            const uint32_t aps[4] = { ps01[2*kp], ps23[2*kp], ps01[2*kp+1], ps23[2*kp+1] };
            const int vrow = kp * 16 + (lgrp & 1) * 8 + l8;
            const uint32_t va = vbase + (uint32_t)vrow * 144 + (lgrp >> 1) * 16;
            uint32_t vfb[8][2], vfs[8][2];
#pragma unroll
            for (int jn = 0; jn < 4; jn++) {
                LDSM_X4_T(vfb[2*jn][0], vfb[2*jn][1], vfb[2*jn+1][0], vfb[2*jn+1][1], va + jn * 32);
                LDSM_X4_T(vfs[2*jn][0], vfs[2*jn][1], vfs[2*jn+1][0], vfs[2*jn+1][1], va + 9216 + jn * 32);
            }
#pragma unroll
            for (int j2 = 0; j2 < 8; j2++) {
                MMA_BF16(oa[j2], apb, vfb[j2]);
                MMA_BF16(oa[j2], apb, vfs[j2]);
                MMA_BF16(oa[j2], aps, vfb[j2]);
            }
        }
        __syncthreads();
    }

    const float i0 = 1.0f / l0;
    const float i1 = 1.0f / l1;
    const int r0g = q0 + wid * 16 + lr;
#pragma unroll
    for (int j2 = 0; j2 < 8; j2++) {
        const size_t o0 = (bm + r0g) * D_ + h * DK_ + j2 * 8 + 2 * lc;
        const size_t o1 = o0 + 8 * D_;
        *(__half2*)&oh[o0] = __half2(__float2half_rn(oa[j2][0] * i0),
                                     __float2half_rn(oa[j2][1] * i0));
        *(__half2*)&oh[o1] = __half2(__float2half_rn(oa[j2][2] * i1),
                                     __float2half_rn(oa[j2][3] * i1));
    }
}

// ---------------- weight prep ----------------
__global__ __launch_bounds__(256) void wprep(
    const float* __restrict__ W, fp16* __restrict__ T,
    int K, int N, long out_ls)
{
    __shared__ float t[32][33];
    const int n0 = blockIdx.x * 32, k0 = blockIdx.y * 32;
    const size_t zin  = (size_t)blockIdx.z * K * N;
    const size_t zout = (size_t)blockIdx.z * out_ls;
    const int tx = threadIdx.x, ty = threadIdx.y;
#pragma unroll
    for (int r = ty; r < 32; r += 8)
        t[r][tx] = W[zin + (size_t)(k0 + r) * N + n0 + tx];
    __syncthreads();
#pragma unroll
    for (int r = ty; r < 32; r += 8)
        T[zout + (size_t)(n0 + r) * K + k0 + tx] =
            __float2half_rn(t[tx][r] * WSCALE);
}

__global__ __launch_bounds__(256) void catbias(
    const float* __restrict__ bq, const float* __restrict__ bk,
    const float* __restrict__ bv, float* __restrict__ out)
{
    const int i = blockIdx.x * 256 + threadIdx.x;
    const int l = i / QS_, c = i % QS_;
    float v;
    if (c < D_)          v = bq[l * D_ + c];
    else if (c < 2 * D_) v = bk[l * D_ + c - D_];
    else                 v = bv[l * D_ + c - 2 * D_];
    out[i] = v;
}

__global__ __launch_bounds__(1024) void split_x(
    const float* __restrict__ e, float* __restrict__ x, fp16* __restrict__ xh)
{
    const size_t i = (size_t)blockIdx.x * 1024 + threadIdx.x;
    const float v = e[i];
    x[i] = v;
    xh[i] = __float2half_rn(v);
}

// ---------------- residual + LayerNorm (+fp16 out) ------------------------
__device__ __forceinline__ float block_sum256(float val, float* red) {
    const int lane = threadIdx.x & 31;
    const int wid  = threadIdx.x >> 5;
#pragma unroll
    for (int o = 16; o > 0; o >>= 1) val += __shfl_xor_sync(0xffffffffu, val, o);
    if (lane == 0) red[wid] = val;
    __syncthreads();
    float t = (threadIdx.x < 8) ? red[threadIdx.x] : 0.0f;
    if (wid == 0) {
#pragma unroll
        for (int o = 4; o > 0; o >>= 1) t += __shfl_xor_sync(0xffffffffu, t, o);
        if (lane == 0) red[0] = t;
    }
    __syncthreads();
    float r = red[0];
    __syncthreads();
    return r;
}

__global__ __launch_bounds__(256) void add_ln(
    const float* __restrict__ xin, const float* __restrict__ del,
    const float* __restrict__ g, const float* __restrict__ be,
    float* __restrict__ xout, fp16* __restrict__ xh)
{
    __shared__ float red[8];
    const int row = blockIdx.x;
    const int c = threadIdx.x * 4;
    const size_t ro = (size_t)row * D_;

    const float4 xv = *(const float4*)&xin[ro + c];
    const float4 dv = *(const float4*)&del[ro + c];
    float v[4] = { xv.x + dv.x, xv.y + dv.y, xv.z + dv.z, xv.w + dv.w };
    const float mu = block_sum256(v[0] + v[1] + v[2] + v[3], red) * (1.0f / D_);
    float qs = 0.0f;
#pragma unroll
    for (int u = 0; u < 4; u++) {
        const float d = v[u] - mu;
        qs += d * d;
    }
    const float var = block_sum256(qs, red) * (1.0f / D_);
    const float rstd = rsqrtf(var + 1e-5f);

    const float4 gv = *(const float4*)&g[c];
    const float4 bv = *(const float4*)&be[c];
    float y[4];
    y[0] = (v[0] - mu) * rstd * gv.x + bv.x;
    y[1] = (v[1] - mu) * rstd * gv.y + bv.y;
    y[2] = (v[2] - mu) * rstd * gv.z + bv.z;
    y[3] = (v[3] - mu) * rstd * gv.w + bv.w;
    *(float4*)&xout[ro + c] = make_float4(y[0], y[1], y[2], y[3]);
    *(__half2*)&xh[ro + c]     = __half2(__float2half_rn(y[0]), __float2half_rn(y[1]));
    *(__half2*)&xh[ro + c + 2] = __half2(__float2half_rn(y[2]), __float2half_rn(y[3]));
}

// ---------------- host driver ----------------
extern "C" void kernel_launch(void* const* d_in, const int* in_sizes, int n_in,
                              void* d_out, int out_size) {
    const float* embeds  = (const float*)d_in[0];
    const float* weights = (const float*)d_in[1];
    const float* Wq = (const float*)d_in[2];
    const float* bq = (const float*)d_in[3];
    const float* Wk = (const float*)d_in[4];
    const float* bk = (const float*)d_in[5];
    const float* Wv = (const float*)d_in[6];
    const float* bv = (const float*)d_in[7];
    const float* Wo = (const float*)d_in[8];
    const float* bo = (const float*)d_in[9];
    const float* W1 = (const float*)d_in[10];
    const float* b1 = (const float*)d_in[11];
    const float* W2 = (const float*)d_in[12];
    const float* b2 = (const float*)d_in[13];
    const float* g1 = (const float*)d_in[14];
    const float* be1= (const float*)d_in[15];
    const float* g2 = (const float*)d_in[16];
    const float* be2= (const float*)d_in[17];

    float *px, *pres, *pbqkv;
    fp16 *pxh,*poh,*pfh,*pwqkv,*pwo,*pw1,*pw2;
    bf16 *pqkvb,*pqkvs;
    cudaGetSymbolAddress((void**)&px,   g_x);
    cudaGetSymbolAddress((void**)&pres, g_res);
    cudaGetSymbolAddress((void**)&pbqkv,g_bqkv);
    cudaGetSymbolAddress((void**)&pxh,  g_xh);
    cudaGetSymbolAddress((void**)&pqkvb,g_qkvb);
    cudaGetSymbolAddress((void**)&pqkvs,g_qkvs);
    cudaGetSymbolAddress((void**)&poh,  g_oh);
    cudaGetSymbolAddress((void**)&pfh,  g_fh);
    cudaGetSymbolAddress((void**)&pwqkv,g_wqkv);
    cudaGetSymbolAddress((void**)&pwo,  g_wo);
    cudaGetSymbolAddress((void**)&pw1,  g_w1);
    cudaGetSymbolAddress((void**)&pw2,  g_w2);

    cudaFuncSetAttribute(gemm_mma<false, false, false, true>,
                         cudaFuncAttributeMaxDynamicSharedMemorySize, GSMEM_BYTES);
    cudaFuncSetAttribute(gemm_mma<false, true, false, false>,
                         cudaFuncAttributeMaxDynamicSharedMemorySize, GSMEM_BYTES);
    cudaFuncSetAttribute(gemm_mma<true, false, true, false>,
                         cudaFuncAttributeMaxDynamicSharedMemorySize, GSMEM_BYTES);
    cudaFuncSetAttribute(flash_mma,
                         cudaFuncAttributeMaxDynamicSharedMemorySize, AT_SMEM);

    const long ls3 = (long)3 * D_ * D_;
    catbias<<<NLAYERS * QS_ / 256, 256>>>(bq, bk, bv, pbqkv);
    split_x<<<ROWS * D_ / 1024, 1024>>>(embeds, px, pxh);
    wprep<<<dim3(D_/32, D_/32, NLAYERS), dim3(32, 8)>>>(Wq, pwqkv,           D_, D_, ls3);
    wprep<<<dim3(D_/32, D_/32, NLAYERS), dim3(32, 8)>>>(Wk, pwqkv + D_*D_,   D_, D_, ls3);
    wprep<<<dim3(D_/32, D_/32, NLAYERS), dim3(32, 8)>>>(Wv, pwqkv + 2*D_*D_, D_, D_, ls3);

    const dim3 gQKV(QS_ / 128, ROWS / 128);  // (24, 64)
    const dim3 gD(D_ / 128, ROWS / 128);     // (8, 64)
    const dim3 gF(F_ / 128, ROWS / 128);     // (32, 64)
    const dim3 gA(M_ / 128, B_ * H_);        // (8, 128)

    for (int l = 0; l < NLAYERS; l++) {
        gemm_mma<false, false, false, true><<<gQKV, 256, GSMEM_BYTES>>>(
            pxh, pwqkv + (size_t)l*ls3, pbqkv + (size_t)l*QS_,
            nullptr, nullptr, pqkvb, pqkvs, D_, QS_);

        if (l == 0) {
            wprep<<<dim3(D_/32, D_/32, NLAYERS), dim3(32, 8)>>>(Wo, pwo, D_, D_, (long)D_*D_);
            wprep<<<dim3(F_/32, D_/32, NLAYERS), dim3(32, 8)>>>(W1, pw1, D_, F_, (long)D_*F_);
            wprep<<<dim3(D_/32, F_/32, NLAYERS), dim3(32, 8)>>>(W2, pw2, F_, D_, (long)F_*D_);
        }

        flash_mma<<<gA, 256, AT_SMEM>>>(pqkvb, pqkvs, weights, poh);

        gemm_mma<false, true, false, false><<<gD, 256, GSMEM_BYTES>>>(
            poh, pwo + (size_t)l*D_*D_, bo + (size_t)l*D_,
            pres, nullptr, nullptr, nullptr, D_, D_);
        add_ln<<<ROWS, 256>>>(px, pres, g1 + (size_t)l*D_, be1 + (size_t)l*D_,
                              px, pxh);

        gemm_mma<true, false, true, false><<<gF, 256, GSMEM_BYTES>>>(
            pxh, pw1 + (size_t)l*D_*F_, b1 + (size_t)l*F_,
            nullptr, pfh, nullptr, nullptr, D_, F_);
        gemm_mma<false, true, false, false><<<gD, 256, GSMEM_BYTES>>>(
            pfh, pw2 + (size_t)l*F_*D_, b2 + (size_t)l*D_,
            pres, nullptr, nullptr, nullptr, F_, D_);
        add_ln<<<ROWS, 256>>>(px, pres, g2 + (size_t)l*D_, be2 + (size_t)l*D_,
                              px, pxh);
    }

    cudaMemcpyAsync(d_out, px, sizeof(float) * (size_t)ROWS * D_,
                    cudaMemcpyDeviceToDevice);
}

// round 15
// speedup vs baseline: 2.3756x; 1.0752x over previous
#include <cuda_runtime.h>
#include <cuda_fp16.h>
#include <math.h>
#include <stdint.h>

#define B_ 8
#define M_ 1024
#define D_ 1024
#define H_ 16
#define F_ 4096
#define NLAYERS 4
#define DK_ 64
#define ROWS (B_*M_)
#define QS_ (3*D_)
#define WSCALE 64.0f
#define INVWS  0.015625f

typedef __half fp16;

// ---------------- device scratch ----------------
__device__ float g_x   [ROWS * D_];
__device__ float g_res [ROWS * D_];
__device__ float g_bqkv[NLAYERS * QS_];
__device__ fp16  g_xh  [ROWS * D_];
__device__ fp16  g_qkvh[ROWS * QS_];
__device__ fp16  g_qkvl[ROWS * QS_];
__device__ fp16  g_oh  [ROWS * D_];
__device__ fp16  g_fh  [ROWS * F_];
__device__ fp16 g_wqkv[NLAYERS*3*D_*D_];
__device__ fp16 g_wo  [NLAYERS*D_*D_];
__device__ fp16 g_w1  [NLAYERS*D_*F_];
__device__ fp16 g_w2  [NLAYERS*F_*D_];

// ---------------- helpers ----------------
__device__ __forceinline__ uint32_t smem_to_u32(const void* p) {
    uint32_t a;
    asm("{ .reg .u64 t; cvta.to.shared.u64 t, %1; cvt.u32.u64 %0, t; }" : "=r"(a) : "l"(p));
    return a;
}
__device__ __forceinline__ float gelu_exact(float x) {
    return 0.5f * x * (1.0f + erff(x * 0.70710678118654752f));
}
__device__ __forceinline__ void split_h(float y, fp16& h, fp16& l) {
    h = __float2half_rn(y);
    l = __float2half_rn(y - __half2float(h));
}
__device__ __forceinline__ uint32_t pack_h2(fp16 a, fp16 b) {
    __half2 t(a, b);
    return *reinterpret_cast<uint32_t*>(&t);
}

#define CP_ASYNC16(dst, src) \
    asm volatile("cp.async.cg.shared.global [%0], [%1], 16;" :: "r"(dst), "l"(src))
#define CP_COMMIT() asm volatile("cp.async.commit_group;")
#define CP_WAIT(n)  asm volatile("cp.async.wait_group %0;" :: "n"(n))

#define MMA_F16(d, a, b) \
    asm volatile("mma.sync.aligned.m16n8k16.row.col.f32.f16.f16.f32 " \
        "{%0,%1,%2,%3}, {%4,%5,%6,%7}, {%8,%9}, {%0,%1,%2,%3};" \
        : "+f"((d)[0]), "+f"((d)[1]), "+f"((d)[2]), "+f"((d)[3]) \
        : "r"((a)[0]), "r"((a)[1]), "r"((a)[2]), "r"((a)[3]), \
          "r"((b)[0]), "r"((b)[1]))

#define LDSM_X4_T(r0, r1, r2, r3, addr) \
    asm volatile("ldmatrix.sync.aligned.m8n8.x4.trans.shared.b16 {%0,%1,%2,%3}, [%4];" \
        : "=r"(r0), "=r"(r1), "=r"(r2), "=r"(r3) : "r"(addr))

// -------- 1xFP16 GEMM: C = Ah·Bh/64 + bias, 128x128, CHUNK 64, 2 CTA/SM ---
#define CHUNK 64
#define RSU   36
#define ARR_U32 (128 * RSU)
#define STG_U32 (2 * ARR_U32)
#define GSMEM_BYTES (2 * STG_U32 * 4)  // 73728

template<bool GELU, bool WPLAIN, bool WH, bool WHL>
__global__ __launch_bounds__(256, 2) void gemm_mma(
    const fp16* __restrict__ Ah, const fp16* __restrict__ Bh,
    const float* __restrict__ bias,
    float* __restrict__ Cp, fp16* __restrict__ Ch, fp16* __restrict__ Cl,
    int K, int N)
{
    extern __shared__ uint32_t smem[];
    const int tid  = threadIdx.x;
    const int wid  = tid >> 5;
    const int lane = tid & 31;
    const int m0 = blockIdx.y * 128;
    const int n0 = blockIdx.x * 128;
    const int wm = wid & 1;
    const int wn = wid >> 1;
    const uint32_t sbase = smem_to_u32(smem);

    float acc[4][4][4];
#pragma unroll
    for (int i = 0; i < 4; i++)
#pragma unroll
        for (int j = 0; j < 4; j++)
#pragma unroll
            for (int r = 0; r < 4; r++) acc[i][j][r] = 0.0f;

    const int nch = K / CHUNK;

    auto load_stage = [&](int stage, int kc) {
        const uint32_t st = sbase + (uint32_t)stage * STG_U32 * 4;
#pragma unroll
        for (int t = 0; t < 4; t++) {
            const int seg = tid + t * 256;
            const int row = seg >> 3;
            const int q   = seg & 7;
            const uint32_t soff = (uint32_t)row * 144 + q * 16;
            const size_t  aofg = (size_t)(m0 + row) * K + kc + q * 8;
            const size_t  bofg = (size_t)(n0 + row) * K + kc + q * 8;
            CP_ASYNC16(st + soff,               Ah + aofg);
            CP_ASYNC16(st + ARR_U32 * 4 + soff, Bh + bofg);
        }
    };

    load_stage(0, 0);
    CP_COMMIT();

    const int lr = lane >> 2;
    const int lc = lane & 3;

    for (int c = 0; c < nch; c++) {
        if (c + 1 < nch) {
            load_stage((c + 1) & 1, (c + 1) * CHUNK);
            CP_COMMIT();
            CP_WAIT(1);
        } else {
            CP_WAIT(0);
        }
        __syncthreads();

        const uint32_t* sAh = smem + (size_t)(c & 1) * STG_U32;
        const uint32_t* sBh = sAh + ARR_U32;

#pragma unroll
        for (int ks = 0; ks < 4; ks++) {
            const int kc = ks * 8;
            uint32_t ah[4][4];
#pragma unroll
            for (int i = 0; i < 4; i++) {
                const int base = (wm * 64 + i * 16 + lr) * RSU + kc + lc;
                ah[i][0] = sAh[base];
                ah[i][1] = sAh[base + 8 * RSU];
                ah[i][2] = sAh[base + 4];
                ah[i][3] = sAh[base + 8 * RSU + 4];
            }
            uint32_t bh[4][2];
#pragma unroll
            for (int j = 0; j < 4; j++) {
                const int base = (wn * 32 + j * 8 + lr) * RSU + kc + lc;
                bh[j][0] = sBh[base];
                bh[j][1] = sBh[base + 4];
            }
#pragma unroll
            for (int i = 0; i < 4; i++)
#pragma unroll
                for (int j = 0; j < 4; j++)
                    MMA_F16(acc[i][j], ah[i], bh[j]);
        }
        __syncthreads();
    }

#pragma unroll
    for (int i = 0; i < 4; i++) {
#pragma unroll
        for (int j = 0; j < 4; j++) {
            const int gr = m0 + wm * 64 + i * 16 + lr;
            const int gc = n0 + wn * 32 + j * 8 + lc * 2;
            const float b0 = bias[gc], b1 = bias[gc + 1];
#pragma unroll
            for (int half = 0; half < 2; half++) {
                const int row = gr + half * 8;
                float y0 = acc[i][j][half * 2 + 0] * INVWS + b0;
                float y1 = acc[i][j][half * 2 + 1] * INVWS + b1;
                if (GELU) { y0 = gelu_exact(y0); y1 = gelu_exact(y1); }
                const size_t o = (size_t)row * N + gc;
                if (WPLAIN) *(float2*)&Cp[o] = make_float2(y0, y1);
                if (WH)
                    *(__half2*)&Ch[o] = __half2(__float2half_rn(y0),
                                                __float2half_rn(y1));
                if (WHL) {
                    fp16 h0, l0_, h1, l1_;
                    split_h(y0, h0, l0_);
                    split_h(y1, h1, l1_);
                    *(__half2*)&Ch[o] = __half2(h0, h1);
                    *(__half2*)&Cl[o] = __half2(l0_, l1_);
                }
            }
        }
    }
}

// ---------------- MMA flash attention (fp16 2-term) -----------------------
// smem bytes: K st: st*9216; V st: 18432+st*9216; w: 36864+st*256.
// Q staged: Qh -> K-st0 area, Ql -> V-st0 area; extracted before load_kv.
#define AT_SMEM 37376

__global__ __launch_bounds__(256, 2) void flash_mma(
    const fp16* __restrict__ qkvh, const fp16* __restrict__ qkvl,
    const float* __restrict__ w,
    fp16* __restrict__ oh)
{
    extern __shared__ uint32_t smem[];
    const uint32_t sb = smem_to_u32(smem);
    const int tid = threadIdx.x, wid = tid >> 5, lane = tid & 31;
    const int lr = lane >> 2, lc = lane & 3;
    const int bidx = blockIdx.y >> 4;
    const int h    = blockIdx.y & 15;
    const int q0   = blockIdx.x * 128;
    const int hq = h * DK_;
    const int hk = D_ + h * DK_;
    const int hv = 2 * D_ + h * DK_;
    const size_t bm = (size_t)bidx * M_;

    // Q: Qh -> bytes [0,9216) (K st0), Ql -> [18432,27648) (V st0)
#pragma unroll
    for (int t = 0; t < 4; t++) {
        const int seg = tid + t * 256;
        const int row = seg >> 3, q8 = seg & 7;
        const size_t src = (bm + q0 + row) * QS_ + hq + q8 * 8;
        const uint32_t d = sb + (uint32_t)row * 144 + q8 * 16;
        CP_ASYNC16(d,         qkvh + src);
        CP_ASYNC16(d + 18432, qkvl + src);
    }
    CP_COMMIT();
    CP_WAIT(0);
    __syncthreads();

    uint32_t aqh[4][4], aql[4][4];
#pragma unroll
    for (int ks = 0; ks < 4; ks++) {
        const int base = (wid * 16 + lr) * 36 + ks * 8 + lc;
        aqh[ks][0] = smem[base];
        aqh[ks][1] = smem[base + 288];
        aqh[ks][2] = smem[base + 4];
        aqh[ks][3] = smem[base + 292];
        aql[ks][0] = smem[4608 + base];
        aql[ks][1] = smem[4608 + base + 288];
        aql[ks][2] = smem[4608 + base + 4];
        aql[ks][3] = smem[4608 + base + 292];
    }
    __syncthreads();

    auto load_kv = [&](int st, int kb0) {
#pragma unroll
        for (int t = 0; t < 2; t++) {
            const int seg = tid + t * 256;
            const int row = seg >> 3, q8 = seg & 7;
            const size_t srck = (bm + kb0 + row) * QS_ + hk + q8 * 8;
            const size_t srcv = (bm + kb0 + row) * QS_ + hv + q8 * 8;
            const uint32_t off = (uint32_t)row * 144 + q8 * 16;
            CP_ASYNC16(sb + st * 9216 + off,         qkvh + srck);
            CP_ASYNC16(sb + 18432 + st * 9216 + off, qkvh + srcv);
        }
        if (tid < 16)
            CP_ASYNC16(sb + 36864 + st * 256 + tid * 16, w + bm + kb0 + tid * 4);
    };
    load_kv(0, 0);
    CP_COMMIT();

    float oa[8][4];
    float m0v = -1e30f, m1v = -1e30f, l0 = 0.0f, l1 = 0.0f;
#pragma unroll
    for (int j = 0; j < 8; j++)
#pragma unroll
        for (int r = 0; r < 4; r++) oa[j][r] = 0.0f;

    for (int kb = 0; kb < 16; kb++) {
        const int st = kb & 1;
        if (kb + 1 < 16) {
            load_kv((kb + 1) & 1, (kb + 1) * 64);
            CP_COMMIT();
            CP_WAIT(1);
        } else {
            CP_WAIT(0);
        }
        __syncthreads();

        const uint32_t* skh = smem + st * 2304;
        float s_[8][4];
#pragma unroll
        for (int j = 0; j < 8; j++)
#pragma unroll
            for (int r = 0; r < 4; r++) s_[j][r] = 0.0f;

#pragma unroll
        for (int ks = 0; ks < 4; ks++) {
            uint32_t kfh[8][2];
#pragma unroll
            for (int j = 0; j < 8; j++) {
                const int base = (j * 8 + lr) * 36 + ks * 8 + lc;
                kfh[j][0] = skh[base];
                kfh[j][1] = skh[base + 4];
            }
#pragma unroll
            for (int j = 0; j < 8; j++) {
                MMA_F16(s_[j], aqh[ks], kfh[j]);
                MMA_F16(s_[j], aql[ks], kfh[j]);
            }
        }

        const float* sw = (const float*)smem + 9216 + st * 64;
        float rmax0 = -1e30f, rmax1 = -1e30f;
        float x[8][4];
#pragma unroll
        for (int j = 0; j < 8; j++) {
            const float2 wp = *(const float2*)(sw + j * 8 + 2 * lc);
            x[j][0] = s_[j][0] * 0.125f + wp.x;
            x[j][1] = s_[j][1] * 0.125f + wp.y;
            x[j][2] = s_[j][2] * 0.125f + wp.x;
            x[j][3] = s_[j][3] * 0.125f + wp.y;
            rmax0 = fmaxf(rmax0, fmaxf(x[j][0], x[j][1]));
            rmax1 = fmaxf(rmax1, fmaxf(x[j][2], x[j][3]));
        }
        rmax0 = fmaxf(rmax0, __shfl_xor_sync(0xffffffffu, rmax0, 1));
        rmax0 = fmaxf(rmax0, __shfl_xor_sync(0xffffffffu, rmax0, 2));
        rmax1 = fmaxf(rmax1, __shfl_xor_sync(0xffffffffu, rmax1, 1));
        rmax1 = fmaxf(rmax1, __shfl_xor_sync(0xffffffffu, rmax1, 2));
        const float mn0 = fmaxf(m0v, rmax0);
        const float mn1 = fmaxf(m1v, rmax1);
        const float c0 = __expf(m0v - mn0);
        const float c1 = __expf(m1v - mn1);
        float rs0 = 0.0f, rs1 = 0.0f;
        uint32_t ph01[8], ph23[8], pl01[8], pl23[8];
#pragma unroll
        for (int j = 0; j < 8; j++) {
            const float p0 = __expf(x[j][0] - mn0);
            const float p1 = __expf(x[j][1] - mn0);
            const float p2 = __expf(x[j][2] - mn1);
            const float p3 = __expf(x[j][3] - mn1);
            rs0 += p0 + p1;
            rs1 += p2 + p3;
            fp16 h0, l0_, h1, l1_, h2, l2_, h3, l3_;
            split_h(p0, h0, l0_); split_h(p1, h1, l1_);
            split_h(p2, h2, l2_); split_h(p3, h3, l3_);
            ph01[j] = pack_h2(h0, h1);
            ph23[j] = pack_h2(h2, h3);
            pl01[j] = pack_h2(l0_, l1_);
            pl23[j] = pack_h2(l2_, l3_);
        }
        rs0 += __shfl_xor_sync(0xffffffffu, rs0, 1);
        rs0 += __shfl_xor_sync(0xffffffffu, rs0, 2);
        rs1 += __shfl_xor_sync(0xffffffffu, rs1, 1);
        rs1 += __shfl_xor_sync(0xffffffffu, rs1, 2);
        l0 = l0 * c0 + rs0;
        l1 = l1 * c1 + rs1;
        m0v = mn0; m1v = mn1;
#pragma unroll
        for (int j = 0; j < 8; j++) {
            oa[j][0] *= c0; oa[j][1] *= c0;
            oa[j][2] *= c1; oa[j][3] *= c1;
        }

        const uint32_t vbase = sb + 18432 + st * 9216;
        const int lgrp = lane >> 3, l8 = lane & 7;
#pragma unroll
        for (int kp = 0; kp < 4; kp++) {
            const uint32_t aph[4] = { ph01[2*kp], ph23[2*kp], ph01[2*kp+1], ph23[2*kp+1] };
            const uint32_t apl[4] = { pl01[2*kp], pl23[2*kp], pl01[2*kp+1], pl23[2*kp+1] };
            const int vrow = kp * 16 + (lgrp & 1) * 8 + l8;
            const uint32_t va = vbase + (uint32_t)vrow * 144 + (lgrp >> 1) * 16;
            uint32_t vfh[8][2];
#pragma unroll
            for (int jn = 0; jn < 4; jn++)
                LDSM_X4_T(vfh[2*jn][0], vfh[2*jn][1], vfh[2*jn+1][0], vfh[2*jn+1][1],
                          va + jn * 32);
#pragma unroll
            for (int j2 = 0; j2 < 8; j2++) {
                MMA_F16(oa[j2], aph, vfh[j2]);
                MMA_F16(oa[j2], apl, vfh[j2]);
            }
        }
        __syncthreads();
    }

    const float i0 = 1.0f / l0;
    const float i1 = 1.0f / l1;
    const int r0g = q0 + wid * 16 + lr;
#pragma unroll
    for (int j2 = 0; j2 < 8; j2++) {
        const size_t o0 = (bm + r0g) * D_ + h * DK_ + j2 * 8 + 2 * lc;
        const size_t o1 = o0 + 8 * D_;
        *(__half2*)&oh[o0] = __half2(__float2half_rn(oa[j2][0] * i0),
                                     __float2half_rn(oa[j2][1] * i0));
        *(__half2*)&oh[o1] = __half2(__float2half_rn(oa[j2][2] * i1),
                                     __float2half_rn(oa[j2][3] * i1));
    }
}

// ---------------- weight prep ----------------
__global__ __launch_bounds__(256) void wprep(
    const float* __restrict__ W, fp16* __restrict__ T,
    int K, int N, long out_ls)
{
    __shared__ float t[32][33];
    const int n0 = blockIdx.x * 32, k0 = blockIdx.y * 32;
    const size_t zin  = (size_t)blockIdx.z * K * N;
    const size_t zout = (size_t)blockIdx.z * out_ls;
    const int tx = threadIdx.x, ty = threadIdx.y;
#pragma unroll
    for (int r = ty; r < 32; r += 8)
        t[r][tx] = W[zin + (size_t)(k0 + r) * N + n0 + tx];
    __syncthreads();
#pragma unroll
    for (int r = ty; r < 32; r += 8)
        T[zout + (size_t)(n0 + r) * K + k0 + tx] =
            __float2half_rn(t[tx][r] * WSCALE);
}

__global__ __launch_bounds__(256) void catbias(
    const float* __restrict__ bq, const float* __restrict__ bk,
    const float* __restrict__ bv, float* __restrict__ out)
{
    const int i = blockIdx.x * 256 + threadIdx.x;
    const int l = i / QS_, c = i % QS_;
    float v;
    if (c < D_)          v = bq[l * D_ + c];
    else if (c < 2 * D_) v = bk[l * D_ + c - D_];
    else                 v = bv[l * D_ + c - 2 * D_];
    out[i] = v;
}

__global__ __launch_bounds__(1024) void split_x(
    const float* __restrict__ e, float* __restrict__ x, fp16* __restrict__ xh)
{
    const size_t i = (size_t)blockIdx.x * 1024 + threadIdx.x;
    const float v = e[i];
    x[i] = v;
    xh[i] = __float2half_rn(v);
}

// ---------------- residual + LayerNorm (+fp16 out) ------------------------
__device__ __forceinline__ float block_sum256(float val, float* red) {
    const int lane = threadIdx.x & 31;
    const int wid  = threadIdx.x >> 5;
#pragma unroll
    for (int o = 16; o > 0; o >>= 1) val += __shfl_xor_sync(0xffffffffu, val, o);
    if (lane == 0) red[wid] = val;
    __syncthreads();
    float t = (threadIdx.x < 8) ? red[threadIdx.x] : 0.0f;
    if (wid == 0) {
#pragma unroll
        for (int o = 4; o > 0; o >>= 1) t += __shfl_xor_sync(0xffffffffu, t, o);
        if (lane == 0) red[0] = t;
    }
    __syncthreads();
    float r = red[0];
    __syncthreads();
    return r;
}

__global__ __launch_bounds__(256) void add_ln(
    const float* __restrict__ xin, const float* __restrict__ del,
    const float* __restrict__ g, const float* __restrict__ be,
    float* __restrict__ xout, fp16* __restrict__ xh)
{
    __shared__ float red[8];
    const int row = blockIdx.x;
    const int c = threadIdx.x * 4;
    const size_t ro = (size_t)row * D_;

    const float4 xv = *(const float4*)&xin[ro + c];
    const float4 dv = *(const float4*)&del[ro + c];
    float v[4] = { xv.x + dv.x, xv.y + dv.y, xv.z + dv.z, xv.w + dv.w };
    const float mu = block_sum256(v[0] + v[1] + v[2] + v[3], red) * (1.0f / D_);
    float qs = 0.0f;
#pragma unroll
    for (int u = 0; u < 4; u++) {
        const float d = v[u] - mu;
        qs += d * d;
    }
    const float var = block_sum256(qs, red) * (1.0f / D_);
    const float rstd = rsqrtf(var + 1e-5f);

    const float4 gv = *(const float4*)&g[c];
    const float4 bv = *(const float4*)&be[c];
    float y[4];
    y[0] = (v[0] - mu) * rstd * gv.x + bv.x;
    y[1] = (v[1] - mu) * rstd * gv.y + bv.y;
    y[2] = (v[2] - mu) * rstd * gv.z + bv.z;
    y[3] = (v[3] - mu) * rstd * gv.w + bv.w;
    *(float4*)&xout[ro + c] = make_float4(y[0], y[1], y[2], y[3]);
    *(__half2*)&xh[ro + c]     = __half2(__float2half_rn(y[0]), __float2half_rn(y[1]));
    *(__half2*)&xh[ro + c + 2] = __half2(__float2half_rn(y[2]), __float2half_rn(y[3]));
}

// ---------------- host driver ----------------
extern "C" void kernel_launch(void* const* d_in, const int* in_sizes, int n_in,
                              void* d_out, int out_size) {
    const float* embeds  = (const float*)d_in[0];
    const float* weights = (const float*)d_in[1];
    const float* Wq = (const float*)d_in[2];
    const float* bq = (const float*)d_in[3];
    const float* Wk = (const float*)d_in[4];
    const float* bk = (const float*)d_in[5];
    const float* Wv = (const float*)d_in[6];
    const float* bv = (const float*)d_in[7];
    const float* Wo = (const float*)d_in[8];
    const float* bo = (const float*)d_in[9];
    const float* W1 = (const float*)d_in[10];
    const float* b1 = (const float*)d_in[11];
    const float* W2 = (const float*)d_in[12];
    const float* b2 = (const float*)d_in[13];
    const float* g1 = (const float*)d_in[14];
    const float* be1= (const float*)d_in[15];
    const float* g2 = (const float*)d_in[16];
    const float* be2= (const float*)d_in[17];

    float *px, *pres, *pbqkv;
    fp16 *pxh,*pqkvh,*pqkvl,*poh,*pfh,*pwqkv,*pwo,*pw1,*pw2;
    cudaGetSymbolAddress((void**)&px,   g_x);
    cudaGetSymbolAddress((void**)&pres, g_res);
    cudaGetSymbolAddress((void**)&pbqkv,g_bqkv);
    cudaGetSymbolAddress((void**)&pxh,  g_xh);
    cudaGetSymbolAddress((void**)&pqkvh,g_qkvh);
    cudaGetSymbolAddress((void**)&pqkvl,g_qkvl);
    cudaGetSymbolAddress((void**)&poh,  g_oh);
    cudaGetSymbolAddress((void**)&pfh,  g_fh);
    cudaGetSymbolAddress((void**)&pwqkv,g_wqkv);
    cudaGetSymbolAddress((void**)&pwo,  g_wo);
    cudaGetSymbolAddress((void**)&pw1,  g_w1);
    cudaGetSymbolAddress((void**)&pw2,  g_w2);

    cudaFuncSetAttribute(gemm_mma<false, false, false, true>,
                         cudaFuncAttributeMaxDynamicSharedMemorySize, GSMEM_BYTES);
    cudaFuncSetAttribute(gemm_mma<false, true, false, false>,
                         cudaFuncAttributeMaxDynamicSharedMemorySize, GSMEM_BYTES);
    cudaFuncSetAttribute(gemm_mma<true, false, true, false>,
                         cudaFuncAttributeMaxDynamicSharedMemorySize, GSMEM_BYTES);
    cudaFuncSetAttribute(flash_mma,
                         cudaFuncAttributeMaxDynamicSharedMemorySize, AT_SMEM);

    const long ls3 = (long)3 * D_ * D_;
    catbias<<<NLAYERS * QS_ / 256, 256>>>(bq, bk, bv, pbqkv);
    split_x<<<ROWS * D_ / 1024, 1024>>>(embeds, px, pxh);
    wprep<<<dim3(D_/32, D_/32, NLAYERS), dim3(32, 8)>>>(Wq, pwqkv,           D_, D_, ls3);
    wprep<<<dim3(D_/32, D_/32, NLAYERS), dim3(32, 8)>>>(Wk, pwqkv + D_*D_,   D_, D_, ls3);
    wprep<<<dim3(D_/32, D_/32, NLAYERS), dim3(32, 8)>>>(Wv, pwqkv + 2*D_*D_, D_, D_, ls3);

    const dim3 gQKV(QS_ / 128, ROWS / 128);  // (24, 64)
    const dim3 gD(D_ / 128, ROWS / 128);     // (8, 64)
    const dim3 gF(F_ / 128, ROWS / 128);     // (32, 64)
    const dim3 gA(M_ / 128, B_ * H_);        // (8, 128)

    for (int l = 0; l < NLAYERS; l++) {
        gemm_mma<false, false, false, true><<<gQKV, 256, GSMEM_BYTES>>>(
            pxh, pwqkv + (size_t)l*ls3, pbqkv + (size_t)l*QS_,
            nullptr, pqkvh, pqkvl, D_, QS_);

        if (l == 0) {
            wprep<<<dim3(D_/32, D_/32, NLAYERS), dim3(32, 8)>>>(Wo, pwo, D_, D_, (long)D_*D_);
            wprep<<<dim3(F_/32, D_/32, NLAYERS), dim3(32, 8)>>>(W1, pw1, D_, F_, (long)D_*F_);
            wprep<<<dim3(D_/32, F_/32, NLAYERS), dim3(32, 8)>>>(W2, pw2, F_, D_, (long)F_*D_);
        }

        flash_mma<<<gA, 256, AT_SMEM>>>(pqkvh, pqkvl, weights, poh);

        gemm_mma<false, true, false, false><<<gD, 256, GSMEM_BYTES>>>(
            poh, pwo + (size_t)l*D_*D_, bo + (size_t)l*D_,
            pres, nullptr, nullptr, D_, D_);
        add_ln<<<ROWS, 256>>>(px, pres, g1 + (size_t)l*D_, be1 + (size_t)l*D_,
                              px, pxh);

        gemm_mma<true, false, true, false><<<gF, 256, GSMEM_BYTES>>>(
            pxh, pw1 + (size_t)l*D_*F_, b1 + (size_t)l*F_,
            nullptr, pfh, nullptr, D_, F_);
        gemm_mma<false, true, false, false><<<gD, 256, GSMEM_BYTES>>>(
            pfh, pw2 + (size_t)l*F_*D_, b2 + (size_t)l*D_,
            pres, nullptr, nullptr, F_, D_);
        add_ln<<<ROWS, 256>>>(px, pres, g2 + (size_t)l*D_, be2 + (size_t)l*D_,
                              px, pxh);
    }

    cudaMemcpyAsync(d_out, px, sizeof(float) * (size_t)ROWS * D_,
                    cudaMemcpyDeviceToDevice);
}

// round 16
// speedup vs baseline: 2.4186x; 1.0181x over previous
#include <cuda_runtime.h>
#include <cuda_fp16.h>
#include <math.h>
#include <stdint.h>

#define B_ 8
#define M_ 1024
#define D_ 1024
#define H_ 16
#define F_ 4096
#define NLAYERS 4
#define DK_ 64
#define ROWS (B_*M_)
#define QS_ (3*D_)
#define WSCALE 64.0f
#define INVWS  0.015625f

typedef __half fp16;

// ---------------- device scratch ----------------
__device__ float g_x   [ROWS * D_];
__device__ float g_res [ROWS * D_];
__device__ float g_bqkv[NLAYERS * QS_];
__device__ fp16  g_xh  [ROWS * D_];
__device__ fp16  g_qkvh[ROWS * QS_];
__device__ fp16  g_qkvl[ROWS * QS_];
__device__ fp16  g_oh  [ROWS * D_];
__device__ fp16  g_fh  [ROWS * F_];
__device__ fp16 g_wqkv[NLAYERS*3*D_*D_];
__device__ fp16 g_wo  [NLAYERS*D_*D_];
__device__ fp16 g_w1  [NLAYERS*D_*F_];
__device__ fp16 g_w2  [NLAYERS*F_*D_];

// ---------------- helpers ----------------
__device__ __forceinline__ uint32_t smem_to_u32(const void* p) {
    uint32_t a;
    asm("{ .reg .u64 t; cvta.to.shared.u64 t, %1; cvt.u32.u64 %0, t; }" : "=r"(a) : "l"(p));
    return a;
}
__device__ __forceinline__ float gelu_exact(float x) {
    return 0.5f * x * (1.0f + erff(x * 0.70710678118654752f));
}
__device__ __forceinline__ void split_h(float y, fp16& h, fp16& l) {
    h = __float2half_rn(y);
    l = __float2half_rn(y - __half2float(h));
}
__device__ __forceinline__ uint32_t pack_h2(fp16 a, fp16 b) {
    __half2 t(a, b);
    return *reinterpret_cast<uint32_t*>(&t);
}

#define CP_ASYNC16(dst, src) \
    asm volatile("cp.async.cg.shared.global [%0], [%1], 16;" :: "r"(dst), "l"(src))
#define CP_COMMIT() asm volatile("cp.async.commit_group;")
#define CP_WAIT(n)  asm volatile("cp.async.wait_group %0;" :: "n"(n))

#define MMA_F16(d, a, b) \
    asm volatile("mma.sync.aligned.m16n8k16.row.col.f32.f16.f16.f32 " \
        "{%0,%1,%2,%3}, {%4,%5,%6,%7}, {%8,%9}, {%0,%1,%2,%3};" \
        : "+f"((d)[0]), "+f"((d)[1]), "+f"((d)[2]), "+f"((d)[3]) \
        : "r"((a)[0]), "r"((a)[1]), "r"((a)[2]), "r"((a)[3]), \
          "r"((b)[0]), "r"((b)[1]))

#define LDSM_X4_T(r0, r1, r2, r3, addr) \
    asm volatile("ldmatrix.sync.aligned.m8n8.x4.trans.shared.b16 {%0,%1,%2,%3}, [%4];" \
        : "=r"(r0), "=r"(r1), "=r"(r2), "=r"(r3) : "r"(addr))

// -------- 1xFP16 GEMM: C = Ah·Bh/64 + bias, 128x128, CHUNK 64, 3-stage ----
#define CHUNK 64
#define RSU   36
#define ARR_U32 (128 * RSU)
#define STG_U32 (2 * ARR_U32)          // 9216 u32 = 36864 B per stage
#define GSMEM_BYTES (3 * STG_U32 * 4)  // 110592

template<bool GELU, bool WPLAIN, bool WH, bool WHL>
__global__ __launch_bounds__(256, 2) void gemm_mma(
    const fp16* __restrict__ Ah, const fp16* __restrict__ Bh,
    const float* __restrict__ bias,
    float* __restrict__ Cp, fp16* __restrict__ Ch, fp16* __restrict__ Cl,
    int K, int N, int lcols)
{
    extern __shared__ uint32_t smem[];
    const int tid  = threadIdx.x;
    const int wid  = tid >> 5;
    const int lane = tid & 31;
    const int m0 = blockIdx.y * 128;
    const int n0 = blockIdx.x * 128;
    const int wm = wid & 1;
    const int wn = wid >> 1;
    const uint32_t sbase = smem_to_u32(smem);

    float acc[4][4][4];
#pragma unroll
    for (int i = 0; i < 4; i++)
#pragma unroll
        for (int j = 0; j < 4; j++)
#pragma unroll
            for (int r = 0; r < 4; r++) acc[i][j][r] = 0.0f;

    const int nch = K / CHUNK;

    auto load_stage = [&](int stage, int kc) {
        const uint32_t st = sbase + (uint32_t)stage * STG_U32 * 4;
#pragma unroll
        for (int t = 0; t < 4; t++) {
            const int seg = tid + t * 256;
            const int row = seg >> 3;
            const int q   = seg & 7;
            const uint32_t soff = (uint32_t)row * 144 + q * 16;
            const size_t  aofg = (size_t)(m0 + row) * K + kc + q * 8;
            const size_t  bofg = (size_t)(n0 + row) * K + kc + q * 8;
            CP_ASYNC16(st + soff,               Ah + aofg);
            CP_ASYNC16(st + ARR_U32 * 4 + soff, Bh + bofg);
        }
    };

    load_stage(0, 0);
    CP_COMMIT();
    load_stage(1, CHUNK);
    CP_COMMIT();

    const int lr = lane >> 2;
    const int lc = lane & 3;
    int stage = 0;

    for (int c = 0; c < nch; c++) {
        if (c + 2 < nch) {
            const int ns = (stage + 2 >= 3) ? stage - 1 : stage + 2;
            load_stage(ns, (c + 2) * CHUNK);
            CP_COMMIT();
            CP_WAIT(2);
        } else if (c + 1 < nch) {
            CP_WAIT(1);
        } else {
            CP_WAIT(0);
        }
        __syncthreads();

        const uint32_t* sAh = smem + (size_t)stage * STG_U32;
        const uint32_t* sBh = sAh + ARR_U32;

#pragma unroll
        for (int ks = 0; ks < 4; ks++) {
            const int kc = ks * 8;
            uint32_t ah[4][4];
#pragma unroll
            for (int i = 0; i < 4; i++) {
                const int base = (wm * 64 + i * 16 + lr) * RSU + kc + lc;
                ah[i][0] = sAh[base];
                ah[i][1] = sAh[base + 8 * RSU];
                ah[i][2] = sAh[base + 4];
                ah[i][3] = sAh[base + 8 * RSU + 4];
            }
            uint32_t bh[4][2];
#pragma unroll
            for (int j = 0; j < 4; j++) {
                const int base = (wn * 32 + j * 8 + lr) * RSU + kc + lc;
                bh[j][0] = sBh[base];
                bh[j][1] = sBh[base + 4];
            }
#pragma unroll
            for (int i = 0; i < 4; i++)
#pragma unroll
                for (int j = 0; j < 4; j++)
                    MMA_F16(acc[i][j], ah[i], bh[j]);
        }
        __syncthreads();
        stage = (stage + 1 == 3) ? 0 : stage + 1;
    }

#pragma unroll
    for (int i = 0; i < 4; i++) {
#pragma unroll
        for (int j = 0; j < 4; j++) {
            const int gr = m0 + wm * 64 + i * 16 + lr;
            const int gc = n0 + wn * 32 + j * 8 + lc * 2;
            const float b0 = bias[gc], b1 = bias[gc + 1];
#pragma unroll
            for (int half = 0; half < 2; half++) {
                const int row = gr + half * 8;
                float y0 = acc[i][j][half * 2 + 0] * INVWS + b0;
                float y1 = acc[i][j][half * 2 + 1] * INVWS + b1;
                if (GELU) { y0 = gelu_exact(y0); y1 = gelu_exact(y1); }
                const size_t o = (size_t)row * N + gc;
                if (WPLAIN) *(float2*)&Cp[o] = make_float2(y0, y1);
                if (WH)
                    *(__half2*)&Ch[o] = __half2(__float2half_rn(y0),
                                                __float2half_rn(y1));
                if (WHL) {
                    fp16 h0, l0_, h1, l1_;
                    split_h(y0, h0, l0_);
                    split_h(y1, h1, l1_);
                    *(__half2*)&Ch[o] = __half2(h0, h1);
                    if (gc < lcols)
                        *(__half2*)&Cl[o] = __half2(l0_, l1_);
                }
            }
        }
    }
}

// ---------------- MMA flash attention (fp16 2-term) -----------------------
#define AT_SMEM 37376

__global__ __launch_bounds__(256, 2) void flash_mma(
    const fp16* __restrict__ qkvh, const fp16* __restrict__ qkvl,
    const float* __restrict__ w,
    fp16* __restrict__ oh)
{
    extern __shared__ uint32_t smem[];
    const uint32_t sb = smem_to_u32(smem);
    const int tid = threadIdx.x, wid = tid >> 5, lane = tid & 31;
    const int lr = lane >> 2, lc = lane & 3;
    const int bidx = blockIdx.y >> 4;
    const int h    = blockIdx.y & 15;
    const int q0   = blockIdx.x * 128;
    const int hq = h * DK_;
    const int hk = D_ + h * DK_;
    const int hv = 2 * D_ + h * DK_;
    const size_t bm = (size_t)bidx * M_;

#pragma unroll
    for (int t = 0; t < 4; t++) {
        const int seg = tid + t * 256;
        const int row = seg >> 3, q8 = seg & 7;
        const size_t src = (bm + q0 + row) * QS_ + hq + q8 * 8;
        const uint32_t d = sb + (uint32_t)row * 144 + q8 * 16;
        CP_ASYNC16(d,         qkvh + src);
        CP_ASYNC16(d + 18432, qkvl + src);
    }
    CP_COMMIT();
    CP_WAIT(0);
    __syncthreads();

    uint32_t aqh[4][4], aql[4][4];
#pragma unroll
    for (int ks = 0; ks < 4; ks++) {
        const int base = (wid * 16 + lr) * 36 + ks * 8 + lc;
        aqh[ks][0] = smem[base];
        aqh[ks][1] = smem[base + 288];
        aqh[ks][2] = smem[base + 4];
        aqh[ks][3] = smem[base + 292];
        aql[ks][0] = smem[4608 + base];
        aql[ks][1] = smem[4608 + base + 288];
        aql[ks][2] = smem[4608 + base + 4];
        aql[ks][3] = smem[4608 + base + 292];
    }
    __syncthreads();

    auto load_kv = [&](int st, int kb0) {
#pragma unroll
        for (int t = 0; t < 2; t++) {
            const int seg = tid + t * 256;
            const int row = seg >> 3, q8 = seg & 7;
            const size_t srck = (bm + kb0 + row) * QS_ + hk + q8 * 8;
            const size_t srcv = (bm + kb0 + row) * QS_ + hv + q8 * 8;
            const uint32_t off = (uint32_t)row * 144 + q8 * 16;
            CP_ASYNC16(sb + st * 9216 + off,         qkvh + srck);
            CP_ASYNC16(sb + 18432 + st * 9216 + off, qkvh + srcv);
        }
        if (tid < 16)
            CP_ASYNC16(sb + 36864 + st * 256 + tid * 16, w + bm + kb0 + tid * 4);
    };
    load_kv(0, 0);
    CP_COMMIT();

    float oa[8][4];
    float m0v = -1e30f, m1v = -1e30f, l0 = 0.0f, l1 = 0.0f;
#pragma unroll
    for (int j = 0; j < 8; j++)
#pragma unroll
        for (int r = 0; r < 4; r++) oa[j][r] = 0.0f;

    for (int kb = 0; kb < 16; kb++) {
        const int st = kb & 1;
        if (kb + 1 < 16) {
            load_kv((kb + 1) & 1, (kb + 1) * 64);
            CP_COMMIT();
            CP_WAIT(1);
        } else {
            CP_WAIT(0);
        }
        __syncthreads();

        const uint32_t* skh = smem + st * 2304;
        float s_[8][4];
#pragma unroll
        for (int j = 0; j < 8; j++)
#pragma unroll
            for (int r = 0; r < 4; r++) s_[j][r] = 0.0f;

#pragma unroll
        for (int ks = 0; ks < 4; ks++) {
            uint32_t kfh[8][2];
#pragma unroll
            for (int j = 0; j < 8; j++) {
                const int base = (j * 8 + lr) * 36 + ks * 8 + lc;
                kfh[j][0] = skh[base];
                kfh[j][1] = skh[base + 4];
            }
#pragma unroll
            for (int j = 0; j < 8; j++) {
                MMA_F16(s_[j], aqh[ks], kfh[j]);
                MMA_F16(s_[j], aql[ks], kfh[j]);
            }
        }

        const float* sw = (const float*)smem + 9216 + st * 64;
        float rmax0 = -1e30f, rmax1 = -1e30f;
        float x[8][4];
#pragma unroll
        for (int j = 0; j < 8; j++) {
            const float2 wp = *(const float2*)(sw + j * 8 + 2 * lc);
            x[j][0] = s_[j][0] * 0.125f + wp.x;
            x[j][1] = s_[j][1] * 0.125f + wp.y;
            x[j][2] = s_[j][2] * 0.125f + wp.x;
            x[j][3] = s_[j][3] * 0.125f + wp.y;
            rmax0 = fmaxf(rmax0, fmaxf(x[j][0], x[j][1]));
            rmax1 = fmaxf(rmax1, fmaxf(x[j][2], x[j][3]));
        }
        rmax0 = fmaxf(rmax0, __shfl_xor_sync(0xffffffffu, rmax0, 1));
        rmax0 = fmaxf(rmax0, __shfl_xor_sync(0xffffffffu, rmax0, 2));
        rmax1 = fmaxf(rmax1, __shfl_xor_sync(0xffffffffu, rmax1, 1));
        rmax1 = fmaxf(rmax1, __shfl_xor_sync(0xffffffffu, rmax1, 2));
        const float mn0 = fmaxf(m0v, rmax0);
        const float mn1 = fmaxf(m1v, rmax1);
        const float c0 = __expf(m0v - mn0);
        const float c1 = __expf(m1v - mn1);
        float rs0 = 0.0f, rs1 = 0.0f;
        uint32_t ph01[8], ph23[8], pl01[8], pl23[8];
#pragma unroll
        for (int j = 0; j < 8; j++) {
            const float p0 = __expf(x[j][0] - mn0);
            const float p1 = __expf(x[j][1] - mn0);
            const float p2 = __expf(x[j][2] - mn1);
            const float p3 = __expf(x[j][3] - mn1);
            rs0 += p0 + p1;
            rs1 += p2 + p3;
            fp16 h0, l0_, h1, l1_, h2, l2_, h3, l3_;
            split_h(p0, h0, l0_); split_h(p1, h1, l1_);
            split_h(p2, h2, l2_); split_h(p3, h3, l3_);
            ph01[j] = pack_h2(h0, h1);
            ph23[j] = pack_h2(h2, h3);
            pl01[j] = pack_h2(l0_, l1_);
            pl23[j] = pack_h2(l2_, l3_);
        }
        rs0 += __shfl_xor_sync(0xffffffffu, rs0, 1);
        rs0 += __shfl_xor_sync(0xffffffffu, rs0, 2);
        rs1 += __shfl_xor_sync(0xffffffffu, rs1, 1);
        rs1 += __shfl_xor_sync(0xffffffffu, rs1, 2);
        l0 = l0 * c0 + rs0;
        l1 = l1 * c1 + rs1;
        m0v = mn0; m1v = mn1;
#pragma unroll
        for (int j = 0; j < 8; j++) {
            oa[j][0] *= c0; oa[j][1] *= c0;
            oa[j][2] *= c1; oa[j][3] *= c1;
        }

        const uint32_t vbase = sb + 18432 + st * 9216;
        const int lgrp = lane >> 3, l8 = lane & 7;
#pragma unroll
        for (int kp = 0; kp < 4; kp++) {
            const uint32_t aph[4] = { ph01[2*kp], ph23[2*kp], ph01[2*kp+1], ph23[2*kp+1] };
            const uint32_t apl[4] = { pl01[2*kp], pl23[2*kp], pl01[2*kp+1], pl23[2*kp+1] };
            const int vrow = kp * 16 + (lgrp & 1) * 8 + l8;
            const uint32_t va = vbase + (uint32_t)vrow * 144 + (lgrp >> 1) * 16;
            uint32_t vfh[8][2];
#pragma unroll
            for (int jn = 0; jn < 4; jn++)
                LDSM_X4_T(vfh[2*jn][0], vfh[2*jn][1], vfh[2*jn+1][0], vfh[2*jn+1][1],
                          va + jn * 32);
#pragma unroll
            for (int j2 = 0; j2 < 8; j2++) {
                MMA_F16(oa[j2], aph, vfh[j2]);
                MMA_F16(oa[j2], apl, vfh[j2]);
            }
        }
        __syncthreads();
    }

    const float i0 = 1.0f / l0;
    const float i1 = 1.0f / l1;
    const int r0g = q0 + wid * 16 + lr;
#pragma unroll
    for (int j2 = 0; j2 < 8; j2++) {
        const size_t o0 = (bm + r0g) * D_ + h * DK_ + j2 * 8 + 2 * lc;
        const size_t o1 = o0 + 8 * D_;
        *(__half2*)&oh[o0] = __half2(__float2half_rn(oa[j2][0] * i0),
                                     __float2half_rn(oa[j2][1] * i0));
        *(__half2*)&oh[o1] = __half2(__float2half_rn(oa[j2][2] * i1),
                                     __float2half_rn(oa[j2][3] * i1));
    }
}

// ---------------- weight prep ----------------
__global__ __launch_bounds__(256) void wprep(
    const float* __restrict__ W, fp16* __restrict__ T,
    int K, int N, long out_ls)
{
    __shared__ float t[32][33];
    const int n0 = blockIdx.x * 32, k0 = blockIdx.y * 32;
    const size_t zin  = (size_t)blockIdx.z * K * N;
    const size_t zout = (size_t)blockIdx.z * out_ls;
    const int tx = threadIdx.x, ty = threadIdx.y;
#pragma unroll
    for (int r = ty; r < 32; r += 8)
        t[r][tx] = W[zin + (size_t)(k0 + r) * N + n0 + tx];
    __syncthreads();
#pragma unroll
    for (int r = ty; r < 32; r += 8)
        T[zout + (size_t)(n0 + r) * K + k0 + tx] =
            __float2half_rn(t[tx][r] * WSCALE);
}

__global__ __launch_bounds__(256) void catbias(
    const float* __restrict__ bq, const float* __restrict__ bk,
    const float* __restrict__ bv, float* __restrict__ out)
{
    const int i = blockIdx.x * 256 + threadIdx.x;
    const int l = i / QS_, c = i % QS_;
    float v;
    if (c < D_)          v = bq[l * D_ + c];
    else if (c < 2 * D_) v = bk[l * D_ + c - D_];
    else                 v = bv[l * D_ + c - 2 * D_];
    out[i] = v;
}

__global__ __launch_bounds__(1024) void split_x(
    const float* __restrict__ e, float* __restrict__ x, fp16* __restrict__ xh)
{
    const size_t i = (size_t)blockIdx.x * 1024 + threadIdx.x;
    const float v = e[i];
    x[i] = v;
    xh[i] = __float2half_rn(v);
}

// ---------------- residual + LayerNorm (+fp16 out) ------------------------
__device__ __forceinline__ float block_sum256(float val, float* red) {
    const int lane = threadIdx.x & 31;
    const int wid  = threadIdx.x >> 5;
#pragma unroll
    for (int o = 16; o > 0; o >>= 1) val += __shfl_xor_sync(0xffffffffu, val, o);
    if (lane == 0) red[wid] = val;
    __syncthreads();
    float t = (threadIdx.x < 8) ? red[threadIdx.x] : 0.0f;
    if (wid == 0) {
#pragma unroll
        for (int o = 4; o > 0; o >>= 1) t += __shfl_xor_sync(0xffffffffu, t, o);
        if (lane == 0) red[0] = t;
    }
    __syncthreads();
    float r = red[0];
    __syncthreads();
    return r;
}

__global__ __launch_bounds__(256) void add_ln(
    const float* __restrict__ xin, const float* __restrict__ del,
    const float* __restrict__ g, const float* __restrict__ be,
    float* __restrict__ xout, fp16* __restrict__ xh)
{
    __shared__ float red[8];
    const int row = blockIdx.x;
    const int c = threadIdx.x * 4;
    const size_t ro = (size_t)row * D_;

    const float4 xv = *(const float4*)&xin[ro + c];
    const float4 dv = *(const float4*)&del[ro + c];
    float v[4] = { xv.x + dv.x, xv.y + dv.y, xv.z + dv.z, xv.w + dv.w };
    const float mu = block_sum256(v[0] + v[1] + v[2] + v[3], red) * (1.0f / D_);
    float qs = 0.0f;
#pragma unroll
    for (int u = 0; u < 4; u++) {
        const float d = v[u] - mu;
        qs += d * d;
    }
    const float var = block_sum256(qs, red) * (1.0f / D_);
    const float rstd = rsqrtf(var + 1e-5f);

    const float4 gv = *(const float4*)&g[c];
    const float4 bv = *(const float4*)&be[c];
    float y[4];
    y[0] = (v[0] - mu) * rstd * gv.x + bv.x;
    y[1] = (v[1] - mu) * rstd * gv.y + bv.y;
    y[2] = (v[2] - mu) * rstd * gv.z + bv.z;
    y[3] = (v[3] - mu) * rstd * gv.w + bv.w;
    *(float4*)&xout[ro + c] = make_float4(y[0], y[1], y[2], y[3]);
    *(__half2*)&xh[ro + c]     = __half2(__float2half_rn(y[0]), __float2half_rn(y[1]));
    *(__half2*)&xh[ro + c + 2] = __half2(__float2half_rn(y[2]), __float2half_rn(y[3]));
}

// ---------------- host driver ----------------
extern "C" void kernel_launch(void* const* d_in, const int* in_sizes, int n_in,
                              void* d_out, int out_size) {
    const float* embeds  = (const float*)d_in[0];
    const float* weights = (const float*)d_in[1];
    const float* Wq = (const float*)d_in[2];
    const float* bq = (const float*)d_in[3];
    const float* Wk = (const float*)d_in[4];
    const float* bk = (const float*)d_in[5];
    const float* Wv = (const float*)d_in[6];
    const float* bv = (const float*)d_in[7];
    const float* Wo = (const float*)d_in[8];
    const float* bo = (const float*)d_in[9];
    const float* W1 = (const float*)d_in[10];
    const float* b1 = (const float*)d_in[11];
    const float* W2 = (const float*)d_in[12];
    const float* b2 = (const float*)d_in[13];
    const float* g1 = (const float*)d_in[14];
    const float* be1= (const float*)d_in[15];
    const float* g2 = (const float*)d_in[16];
    const float* be2= (const float*)d_in[17];

    float *px, *pres, *pbqkv;
    fp16 *pxh,*pqkvh,*pqkvl,*poh,*pfh,*pwqkv,*pwo,*pw1,*pw2;
    cudaGetSymbolAddress((void**)&px,   g_x);
    cudaGetSymbolAddress((void**)&pres, g_res);
    cudaGetSymbolAddress((void**)&pbqkv,g_bqkv);
    cudaGetSymbolAddress((void**)&pxh,  g_xh);
    cudaGetSymbolAddress((void**)&pqkvh,g_qkvh);
    cudaGetSymbolAddress((void**)&pqkvl,g_qkvl);
    cudaGetSymbolAddress((void**)&poh,  g_oh);
    cudaGetSymbolAddress((void**)&pfh,  g_fh);
    cudaGetSymbolAddress((void**)&pwqkv,g_wqkv);
    cudaGetSymbolAddress((void**)&pwo,  g_wo);
    cudaGetSymbolAddress((void**)&pw1,  g_w1);
    cudaGetSymbolAddress((void**)&pw2,  g_w2);

    cudaFuncSetAttribute(gemm_mma<false, false, false, true>,
                         cudaFuncAttributeMaxDynamicSharedMemorySize, GSMEM_BYTES);
    cudaFuncSetAttribute(gemm_mma<false, true, false, false>,
                         cudaFuncAttributeMaxDynamicSharedMemorySize, GSMEM_BYTES);
    cudaFuncSetAttribute(gemm_mma<true, false, true, false>,
                         cudaFuncAttributeMaxDynamicSharedMemorySize, GSMEM_BYTES);
    cudaFuncSetAttribute(flash_mma,
                         cudaFuncAttributeMaxDynamicSharedMemorySize, AT_SMEM);

    const long ls3 = (long)3 * D_ * D_;
    catbias<<<NLAYERS * QS_ / 256, 256>>>(bq, bk, bv, pbqkv);
    split_x<<<ROWS * D_ / 1024, 1024>>>(embeds, px, pxh);
    wprep<<<dim3(D_/32, D_/32, NLAYERS), dim3(32, 8)>>>(Wq, pwqkv,           D_, D_, ls3);
    wprep<<<dim3(D_/32, D_/32, NLAYERS), dim3(32, 8)>>>(Wk, pwqkv + D_*D_,   D_, D_, ls3);
    wprep<<<dim3(D_/32, D_/32, NLAYERS), dim3(32, 8)>>>(Wv, pwqkv + 2*D_*D_, D_, D_, ls3);

    const dim3 gQKV(QS_ / 128, ROWS / 128);  // (24, 64)
    const dim3 gD(D_ / 128, ROWS / 128);     // (8, 64)
    const dim3 gF(F_ / 128, ROWS / 128);     // (32, 64)
    const dim3 gA(M_ / 128, B_ * H_);        // (8, 128)

    for (int l = 0; l < NLAYERS; l++) {
        gemm_mma<false, false, false, true><<<gQKV, 256, GSMEM_BYTES>>>(
            pxh, pwqkv + (size_t)l*ls3, pbqkv + (size_t)l*QS_,
            nullptr, pqkvh, pqkvl, D_, QS_, D_);

        if (l == 0) {
            wprep<<<dim3(D_/32, D_/32, NLAYERS), dim3(32, 8)>>>(Wo, pwo, D_, D_, (long)D_*D_);
            wprep<<<dim3(F_/32, D_/32, NLAYERS), dim3(32, 8)>>>(W1, pw1, D_, F_, (long)D_*F_);
            wprep<<<dim3(D_/32, F_/32, NLAYERS), dim3(32, 8)>>>(W2, pw2, F_, D_, (long)F_*D_);
        }

        flash_mma<<<gA, 256, AT_SMEM>>>(pqkvh, pqkvl, weights, poh);

        gemm_mma<false, true, false, false><<<gD, 256, GSMEM_BYTES>>>(
            poh, pwo + (size_t)l*D_*D_, bo + (size_t)l*D_,
            pres, nullptr, nullptr, D_, D_, 0);
        add_ln<<<ROWS, 256>>>(px, pres, g1 + (size_t)l*D_, be1 + (size_t)l*D_,
                              px, pxh);

        gemm_mma<true, false, true, false><<<gF, 256, GSMEM_BYTES>>>(
            pxh, pw1 + (size_t)l*D_*F_, b1 + (size_t)l*F_,
            nullptr, pfh, nullptr, D_, F_, 0);
        gemm_mma<false, true, false, false><<<gD, 256, GSMEM_BYTES>>>(
            pfh, pw2 + (size_t)l*F_*D_, b2 + (size_t)l*D_,
            pres, nullptr, nullptr, F_, D_, 0);
        // last layer: write LN result straight into d_out (skip final memcpy)
        float* xo = (l == NLAYERS - 1) ? (float*)d_out : px;
        add_ln<<<ROWS, 256>>>(px, pres, g2 + (size_t)l*D_, be2 + (size_t)l*D_,
                              xo, pxh);
    }
}

// round 17
// speedup vs baseline: 2.6361x; 1.0900x over previous
#include <cuda_runtime.h>
#include <cuda_fp16.h>
#include <math.h>
#include <stdint.h>

#define B_ 8
#define M_ 1024
#define D_ 1024
#define H_ 16
#define F_ 4096
#define NLAYERS 4
#define DK_ 64
#define ROWS (B_*M_)
#define QS_ (3*D_)
#define WSCALE 64.0f
#define INVWS  0.015625f

typedef __half fp16;

// ---------------- device scratch ----------------
__device__ float g_x   [ROWS * D_];
__device__ float g_res [ROWS * D_];
__device__ float g_bqkv[NLAYERS * QS_];
__device__ fp16  g_xh  [ROWS * D_];
__device__ fp16  g_qkvh[ROWS * QS_];
__device__ fp16  g_oh  [ROWS * D_];
__device__ fp16  g_fh  [ROWS * F_];
__device__ fp16 g_wqkv[NLAYERS*3*D_*D_];
__device__ fp16 g_wo  [NLAYERS*D_*D_];
__device__ fp16 g_w1  [NLAYERS*D_*F_];
__device__ fp16 g_w2  [NLAYERS*F_*D_];

// ---------------- helpers ----------------
__device__ __forceinline__ uint32_t smem_to_u32(const void* p) {
    uint32_t a;
    asm("{ .reg .u64 t; cvta.to.shared.u64 t, %1; cvt.u32.u64 %0, t; }" : "=r"(a) : "l"(p));
    return a;
}
__device__ __forceinline__ float gelu_exact(float x) {
    return 0.5f * x * (1.0f + erff(x * 0.70710678118654752f));
}
__device__ __forceinline__ uint32_t pack_h2(fp16 a, fp16 b) {
    __half2 t(a, b);
    return *reinterpret_cast<uint32_t*>(&t);
}

#define CP_ASYNC16(dst, src) \
    asm volatile("cp.async.cg.shared.global [%0], [%1], 16;" :: "r"(dst), "l"(src))
#define CP_COMMIT() asm volatile("cp.async.commit_group;")
#define CP_WAIT(n)  asm volatile("cp.async.wait_group %0;" :: "n"(n))

#define MMA_F16(d, a, b) \
    asm volatile("mma.sync.aligned.m16n8k16.row.col.f32.f16.f16.f32 " \
        "{%0,%1,%2,%3}, {%4,%5,%6,%7}, {%8,%9}, {%0,%1,%2,%3};" \
        : "+f"((d)[0]), "+f"((d)[1]), "+f"((d)[2]), "+f"((d)[3]) \
        : "r"((a)[0]), "r"((a)[1]), "r"((a)[2]), "r"((a)[3]), \
          "r"((b)[0]), "r"((b)[1]))

#define LDSM_X4_T(r0, r1, r2, r3, addr) \
    asm volatile("ldmatrix.sync.aligned.m8n8.x4.trans.shared.b16 {%0,%1,%2,%3}, [%4];" \
        : "=r"(r0), "=r"(r1), "=r"(r2), "=r"(r3) : "r"(addr))

// -------- 1xFP16 GEMM: C = Ah·Bh/64 + bias, 128x128, CHUNK 64, 3-stage ----
#define CHUNK 64
#define RSU   36
#define ARR_U32 (128 * RSU)
#define STG_U32 (2 * ARR_U32)          // 36864 B per stage
#define GSMEM_BYTES (3 * STG_U32 * 4)  // 110592

template<bool GELU, bool WPLAIN, bool WH>
__global__ __launch_bounds__(256, 2) void gemm_mma(
    const fp16* __restrict__ Ah, const fp16* __restrict__ Bh,
    const float* __restrict__ bias,
    float* __restrict__ Cp, fp16* __restrict__ Ch,
    int K, int N)
{
    extern __shared__ uint32_t smem[];
    const int tid  = threadIdx.x;
    const int wid  = tid >> 5;
    const int lane = tid & 31;
    const int m0 = blockIdx.y * 128;
    const int n0 = blockIdx.x * 128;
    const int wm = wid & 1;
    const int wn = wid >> 1;
    const uint32_t sbase = smem_to_u32(smem);

    float acc[4][4][4];
#pragma unroll
    for (int i = 0; i < 4; i++)
#pragma unroll
        for (int j = 0; j < 4; j++)
#pragma unroll
            for (int r = 0; r < 4; r++) acc[i][j][r] = 0.0f;

    const int nch = K / CHUNK;

    auto load_stage = [&](int stage, int kc) {
        const uint32_t st = sbase + (uint32_t)stage * STG_U32 * 4;
#pragma unroll
        for (int t = 0; t < 4; t++) {
            const int seg = tid + t * 256;
            const int row = seg >> 3;
            const int q   = seg & 7;
            const uint32_t soff = (uint32_t)row * 144 + q * 16;
            const size_t  aofg = (size_t)(m0 + row) * K + kc + q * 8;
            const size_t  bofg = (size_t)(n0 + row) * K + kc + q * 8;
            CP_ASYNC16(st + soff,               Ah + aofg);
            CP_ASYNC16(st + ARR_U32 * 4 + soff, Bh + bofg);
        }
    };

    load_stage(0, 0);
    CP_COMMIT();
    load_stage(1, CHUNK);
    CP_COMMIT();

    const int lr = lane >> 2;
    const int lc = lane & 3;
    int stage = 0;

    for (int c = 0; c < nch; c++) {
        if (c + 2 < nch) {
            const int ns = (stage + 2 >= 3) ? stage - 1 : stage + 2;
            load_stage(ns, (c + 2) * CHUNK);
            CP_COMMIT();
            CP_WAIT(2);
        } else if (c + 1 < nch) {
            CP_WAIT(1);
        } else {
            CP_WAIT(0);
        }
        __syncthreads();

        const uint32_t* sAh = smem + (size_t)stage * STG_U32;
        const uint32_t* sBh = sAh + ARR_U32;

#pragma unroll
        for (int ks = 0; ks < 4; ks++) {
            const int kc = ks * 8;
            uint32_t ah[4][4];
#pragma unroll
            for (int i = 0; i < 4; i++) {
                const int base = (wm * 64 + i * 16 + lr) * RSU + kc + lc;
                ah[i][0] = sAh[base];
                ah[i][1] = sAh[base + 8 * RSU];
                ah[i][2] = sAh[base + 4];
                ah[i][3] = sAh[base + 8 * RSU + 4];
            }
            uint32_t bh[4][2];
#pragma unroll
            for (int j = 0; j < 4; j++) {
                const int base = (wn * 32 + j * 8 + lr) * RSU + kc + lc;
                bh[j][0] = sBh[base];
                bh[j][1] = sBh[base + 4];
            }
#pragma unroll
            for (int i = 0; i < 4; i++)
#pragma unroll
                for (int j = 0; j < 4; j++)
                    MMA_F16(acc[i][j], ah[i], bh[j]);
        }
        __syncthreads();
        stage = (stage + 1 == 3) ? 0 : stage + 1;
    }

#pragma unroll
    for (int i = 0; i < 4; i++) {
#pragma unroll
        for (int j = 0; j < 4; j++) {
            const int gr = m0 + wm * 64 + i * 16 + lr;
            const int gc = n0 + wn * 32 + j * 8 + lc * 2;
            const float b0 = bias[gc], b1 = bias[gc + 1];
#pragma unroll
            for (int half = 0; half < 2; half++) {
                const int row = gr + half * 8;
                float y0 = acc[i][j][half * 2 + 0] * INVWS + b0;
                float y1 = acc[i][j][half * 2 + 1] * INVWS + b1;
                if (GELU) { y0 = gelu_exact(y0); y1 = gelu_exact(y1); }
                const size_t o = (size_t)row * N + gc;
                if (WPLAIN) *(float2*)&Cp[o] = make_float2(y0, y1);
                if (WH)
                    *(__half2*)&Ch[o] = __half2(__float2half_rn(y0),
                                                __float2half_rn(y1));
            }
        }
    }
}

// ---------------- MMA flash attention (fp16 1-term) -----------------------
// smem bytes: K st: st*9216; V st: 18432+st*9216; w: 36864+st*256.
// Q staged through K-st0 area once.
#define AT_SMEM 37376

__global__ __launch_bounds__(256, 2) void flash_mma(
    const fp16* __restrict__ qkvh,
    const float* __restrict__ w,
    fp16* __restrict__ oh)
{
    extern __shared__ uint32_t smem[];
    const uint32_t sb = smem_to_u32(smem);
    const int tid = threadIdx.x, wid = tid >> 5, lane = tid & 31;
    const int lr = lane >> 2, lc = lane & 3;
    const int bidx = blockIdx.y >> 4;
    const int h    = blockIdx.y & 15;
    const int q0   = blockIdx.x * 128;
    const int hq = h * DK_;
    const int hk = D_ + h * DK_;
    const int hv = 2 * D_ + h * DK_;
    const size_t bm = (size_t)bidx * M_;

    // Q -> K-st0 area
#pragma unroll
    for (int t = 0; t < 4; t++) {
        const int seg = tid + t * 256;
        const int row = seg >> 3, q8 = seg & 7;
        const size_t src = (bm + q0 + row) * QS_ + hq + q8 * 8;
        CP_ASYNC16(sb + (uint32_t)row * 144 + q8 * 16, qkvh + src);
    }
    CP_COMMIT();
    CP_WAIT(0);
    __syncthreads();

    uint32_t aqh[4][4];
#pragma unroll
    for (int ks = 0; ks < 4; ks++) {
        const int base = (wid * 16 + lr) * 36 + ks * 8 + lc;
        aqh[ks][0] = smem[base];
        aqh[ks][1] = smem[base + 288];
        aqh[ks][2] = smem[base + 4];
        aqh[ks][3] = smem[base + 292];
    }
    __syncthreads();

    auto load_kv = [&](int st, int kb0) {
#pragma unroll
        for (int t = 0; t < 2; t++) {
            const int seg = tid + t * 256;
            const int row = seg >> 3, q8 = seg & 7;
            const size_t srck = (bm + kb0 + row) * QS_ + hk + q8 * 8;
            const size_t srcv = (bm + kb0 + row) * QS_ + hv + q8 * 8;
            const uint32_t off = (uint32_t)row * 144 + q8 * 16;
            CP_ASYNC16(sb + st * 9216 + off,         qkvh + srck);
            CP_ASYNC16(sb + 18432 + st * 9216 + off, qkvh + srcv);
        }
        if (tid < 16)
            CP_ASYNC16(sb + 36864 + st * 256 + tid * 16, w + bm + kb0 + tid * 4);
    };
    load_kv(0, 0);
    CP_COMMIT();

    float oa[8][4];
    float m0v = -1e30f, m1v = -1e30f, l0 = 0.0f, l1 = 0.0f;
#pragma unroll
    for (int j = 0; j < 8; j++)
#pragma unroll
        for (int r = 0; r < 4; r++) oa[j][r] = 0.0f;

    for (int kb = 0; kb < 16; kb++) {
        const int st = kb & 1;
        if (kb + 1 < 16) {
            load_kv((kb + 1) & 1, (kb + 1) * 64);
            CP_COMMIT();
            CP_WAIT(1);
        } else {
            CP_WAIT(0);
        }
        __syncthreads();

        const uint32_t* skh = smem + st * 2304;
        float s_[8][4];
#pragma unroll
        for (int j = 0; j < 8; j++)
#pragma unroll
            for (int r = 0; r < 4; r++) s_[j][r] = 0.0f;

#pragma unroll
        for (int ks = 0; ks < 4; ks++) {
            uint32_t kfh[8][2];
#pragma unroll
            for (int j = 0; j < 8; j++) {
                const int base = (j * 8 + lr) * 36 + ks * 8 + lc;
                kfh[j][0] = skh[base];
                kfh[j][1] = skh[base + 4];
            }
#pragma unroll
            for (int j = 0; j < 8; j++)
                MMA_F16(s_[j], aqh[ks], kfh[j]);
        }

        const float* sw = (const float*)smem + 9216 + st * 64;
        float rmax0 = -1e30f, rmax1 = -1e30f;
        float x[8][4];
#pragma unroll
        for (int j = 0; j < 8; j++) {
            const float2 wp = *(const float2*)(sw + j * 8 + 2 * lc);
            x[j][0] = s_[j][0] * 0.125f + wp.x;
            x[j][1] = s_[j][1] * 0.125f + wp.y;
            x[j][2] = s_[j][2] * 0.125f + wp.x;
            x[j][3] = s_[j][3] * 0.125f + wp.y;
            rmax0 = fmaxf(rmax0, fmaxf(x[j][0], x[j][1]));
            rmax1 = fmaxf(rmax1, fmaxf(x[j][2], x[j][3]));
        }
        rmax0 = fmaxf(rmax0, __shfl_xor_sync(0xffffffffu, rmax0, 1));
        rmax0 = fmaxf(rmax0, __shfl_xor_sync(0xffffffffu, rmax0, 2));
        rmax1 = fmaxf(rmax1, __shfl_xor_sync(0xffffffffu, rmax1, 1));
        rmax1 = fmaxf(rmax1, __shfl_xor_sync(0xffffffffu, rmax1, 2));
        const float mn0 = fmaxf(m0v, rmax0);
        const float mn1 = fmaxf(m1v, rmax1);
        const float c0 = __expf(m0v - mn0);
        const float c1 = __expf(m1v - mn1);
        float rs0 = 0.0f, rs1 = 0.0f;
        uint32_t ph01[8], ph23[8];
#pragma unroll
        for (int j = 0; j < 8; j++) {
            const float p0 = __expf(x[j][0] - mn0);
            const float p1 = __expf(x[j][1] - mn0);
            const float p2 = __expf(x[j][2] - mn1);
            const float p3 = __expf(x[j][3] - mn1);
            rs0 += p0 + p1;
            rs1 += p2 + p3;
            ph01[j] = pack_h2(__float2half_rn(p0), __float2half_rn(p1));
            ph23[j] = pack_h2(__float2half_rn(p2), __float2half_rn(p3));
        }
        rs0 += __shfl_xor_sync(0xffffffffu, rs0, 1);
        rs0 += __shfl_xor_sync(0xffffffffu, rs0, 2);
        rs1 += __shfl_xor_sync(0xffffffffu, rs1, 1);
        rs1 += __shfl_xor_sync(0xffffffffu, rs1, 2);
        l0 = l0 * c0 + rs0;
        l1 = l1 * c1 + rs1;
        m0v = mn0; m1v = mn1;
#pragma unroll
        for (int j = 0; j < 8; j++) {
            oa[j][0] *= c0; oa[j][1] *= c0;
            oa[j][2] *= c1; oa[j][3] *= c1;
        }

        const uint32_t vbase = sb + 18432 + st * 9216;
        const int lgrp = lane >> 3, l8 = lane & 7;
#pragma unroll
        for (int kp = 0; kp < 4; kp++) {
            const uint32_t aph[4] = { ph01[2*kp], ph23[2*kp], ph01[2*kp+1], ph23[2*kp+1] };
            const int vrow = kp * 16 + (lgrp & 1) * 8 + l8;
            const uint32_t va = vbase + (uint32_t)vrow * 144 + (lgrp >> 1) * 16;
            uint32_t vfh[8][2];
#pragma unroll
            for (int jn = 0; jn < 4; jn++)
                LDSM_X4_T(vfh[2*jn][0], vfh[2*jn][1], vfh[2*jn+1][0], vfh[2*jn+1][1],
                          va + jn * 32);
#pragma unroll
            for (int j2 = 0; j2 < 8; j2++)
                MMA_F16(oa[j2], aph, vfh[j2]);
        }
        __syncthreads();
    }

    const float i0 = 1.0f / l0;
    const float i1 = 1.0f / l1;
    const int r0g = q0 + wid * 16 + lr;
#pragma unroll
    for (int j2 = 0; j2 < 8; j2++) {
        const size_t o0 = (bm + r0g) * D_ + h * DK_ + j2 * 8 + 2 * lc;
        const size_t o1 = o0 + 8 * D_;
        *(__half2*)&oh[o0] = __half2(__float2half_rn(oa[j2][0] * i0),
                                     __float2half_rn(oa[j2][1] * i0));
        *(__half2*)&oh[o1] = __half2(__float2half_rn(oa[j2][2] * i1),
                                     __float2half_rn(oa[j2][3] * i1));
    }
}

// ---------------- weight prep ----------------
__global__ __launch_bounds__(256) void wprep(
    const float* __restrict__ W, fp16* __restrict__ T,
    int K, int N, long out_ls)
{
    __shared__ float t[32][33];
    const int n0 = blockIdx.x * 32, k0 = blockIdx.y * 32;
    const size_t zin  = (size_t)blockIdx.z * K * N;
    const size_t zout = (size_t)blockIdx.z * out_ls;
    const int tx = threadIdx.x, ty = threadIdx.y;
#pragma unroll
    for (int r = ty; r < 32; r += 8)
        t[r][tx] = W[zin + (size_t)(k0 + r) * N + n0 + tx];
    __syncthreads();
#pragma unroll
    for (int r = ty; r < 32; r += 8)
        T[zout + (size_t)(n0 + r) * K + k0 + tx] =
            __float2half_rn(t[tx][r] * WSCALE);
}

__global__ __launch_bounds__(256) void catbias(
    const float* __restrict__ bq, const float* __restrict__ bk,
    const float* __restrict__ bv, float* __restrict__ out)
{
    const int i = blockIdx.x * 256 + threadIdx.x;
    const int l = i / QS_, c = i % QS_;
    float v;
    if (c < D_)          v = bq[l * D_ + c];
    else if (c < 2 * D_) v = bk[l * D_ + c - D_];
    else                 v = bv[l * D_ + c - 2 * D_];
    out[i] = v;
}

__global__ __launch_bounds__(1024) void split_x(
    const float* __restrict__ e, float* __restrict__ x, fp16* __restrict__ xh)
{
    const size_t i = (size_t)blockIdx.x * 1024 + threadIdx.x;
    const float v = e[i];
    x[i] = v;
    xh[i] = __float2half_rn(v);
}

// ---------------- residual + LayerNorm (+fp16 out) ------------------------
__device__ __forceinline__ float block_sum256(float val, float* red) {
    const int lane = threadIdx.x & 31;
    const int wid  = threadIdx.x >> 5;
#pragma unroll
    for (int o = 16; o > 0; o >>= 1) val += __shfl_xor_sync(0xffffffffu, val, o);
    if (lane == 0) red[wid] = val;
    __syncthreads();
    float t = (threadIdx.x < 8) ? red[threadIdx.x] : 0.0f;
    if (wid == 0) {
#pragma unroll
        for (int o = 4; o > 0; o >>= 1) t += __shfl_xor_sync(0xffffffffu, t, o);
        if (lane == 0) red[0] = t;
    }
    __syncthreads();
    float r = red[0];
    __syncthreads();
    return r;
}

__global__ __launch_bounds__(256) void add_ln(
    const float* __restrict__ xin, const float* __restrict__ del,
    const float* __restrict__ g, const float* __restrict__ be,
    float* __restrict__ xout, fp16* __restrict__ xh)
{
    __shared__ float red[8];
    const int row = blockIdx.x;
    const int c = threadIdx.x * 4;
    const size_t ro = (size_t)row * D_;

    const float4 xv = *(const float4*)&xin[ro + c];
    const float4 dv = *(const float4*)&del[ro + c];
    float v[4] = { xv.x + dv.x, xv.y + dv.y, xv.z + dv.z, xv.w + dv.w };
    const float mu = block_sum256(v[0] + v[1] + v[2] + v[3], red) * (1.0f / D_);
    float qs = 0.0f;
#pragma unroll
    for (int u = 0; u < 4; u++) {
        const float d = v[u] - mu;
        qs += d * d;
    }
    const float var = block_sum256(qs, red) * (1.0f / D_);
    const float rstd = rsqrtf(var + 1e-5f);

    const float4 gv = *(const float4*)&g[c];
    const float4 bv = *(const float4*)&be[c];
    float y[4];
    y[0] = (v[0] - mu) * rstd * gv.x + bv.x;
    y[1] = (v[1] - mu) * rstd * gv.y + bv.y;
    y[2] = (v[2] - mu) * rstd * gv.z + bv.z;
    y[3] = (v[3] - mu) * rstd * gv.w + bv.w;
    *(float4*)&xout[ro + c] = make_float4(y[0], y[1], y[2], y[3]);
    *(__half2*)&xh[ro + c]     = __half2(__float2half_rn(y[0]), __float2half_rn(y[1]));
    *(__half2*)&xh[ro + c + 2] = __half2(__float2half_rn(y[2]), __float2half_rn(y[3]));
}

// ---------------- host driver ----------------
extern "C" void kernel_launch(void* const* d_in, const int* in_sizes, int n_in,
                              void* d_out, int out_size) {
    const float* embeds  = (const float*)d_in[0];
    const float* weights = (const float*)d_in[1];
    const float* Wq = (const float*)d_in[2];
    const float* bq = (const float*)d_in[3];
    const float* Wk = (const float*)d_in[4];
    const float* bk = (const float*)d_in[5];
    const float* Wv = (const float*)d_in[6];
    const float* bv = (const float*)d_in[7];
    const float* Wo = (const float*)d_in[8];
    const float* bo = (const float*)d_in[9];
    const float* W1 = (const float*)d_in[10];
    const float* b1 = (const float*)d_in[11];
    const float* W2 = (const float*)d_in[12];
    const float* b2 = (const float*)d_in[13];
    const float* g1 = (const float*)d_in[14];
    const float* be1= (const float*)d_in[15];
    const float* g2 = (const float*)d_in[16];
    const float* be2= (const float*)d_in[17];

    float *px, *pres, *pbqkv;
    fp16 *pxh,*pqkvh,*poh,*pfh,*pwqkv,*pwo,*pw1,*pw2;
    cudaGetSymbolAddress((void**)&px,   g_x);
    cudaGetSymbolAddress((void**)&pres, g_res);
    cudaGetSymbolAddress((void**)&pbqkv,g_bqkv);
    cudaGetSymbolAddress((void**)&pxh,  g_xh);
    cudaGetSymbolAddress((void**)&pqkvh,g_qkvh);
    cudaGetSymbolAddress((void**)&poh,  g_oh);
    cudaGetSymbolAddress((void**)&pfh,  g_fh);
    cudaGetSymbolAddress((void**)&pwqkv,g_wqkv);
    cudaGetSymbolAddress((void**)&pwo,  g_wo);
    cudaGetSymbolAddress((void**)&pw1,  g_w1);
    cudaGetSymbolAddress((void**)&pw2,  g_w2);

    cudaFuncSetAttribute(gemm_mma<false, false, true>,
                         cudaFuncAttributeMaxDynamicSharedMemorySize, GSMEM_BYTES);
    cudaFuncSetAttribute(gemm_mma<false, true, false>,
                         cudaFuncAttributeMaxDynamicSharedMemorySize, GSMEM_BYTES);
    cudaFuncSetAttribute(gemm_mma<true, false, true>,
                         cudaFuncAttributeMaxDynamicSharedMemorySize, GSMEM_BYTES);
    cudaFuncSetAttribute(flash_mma,
                         cudaFuncAttributeMaxDynamicSharedMemorySize, AT_SMEM);

    const long ls3 = (long)3 * D_ * D_;
    catbias<<<NLAYERS * QS_ / 256, 256>>>(bq, bk, bv, pbqkv);
    split_x<<<ROWS * D_ / 1024, 1024>>>(embeds, px, pxh);
    wprep<<<dim3(D_/32, D_/32, NLAYERS), dim3(32, 8)>>>(Wq, pwqkv,           D_, D_, ls3);
    wprep<<<dim3(D_/32, D_/32, NLAYERS), dim3(32, 8)>>>(Wk, pwqkv + D_*D_,   D_, D_, ls3);
    wprep<<<dim3(D_/32, D_/32, NLAYERS), dim3(32, 8)>>>(Wv, pwqkv + 2*D_*D_, D_, D_, ls3);

    const dim3 gQKV(QS_ / 128, ROWS / 128);  // (24, 64)
    const dim3 gD(D_ / 128, ROWS / 128);     // (8, 64)
    const dim3 gF(F_ / 128, ROWS / 128);     // (32, 64)
    const dim3 gA(M_ / 128, B_ * H_);        // (8, 128)

    for (int l = 0; l < NLAYERS; l++) {
        gemm_mma<false, false, true><<<gQKV, 256, GSMEM_BYTES>>>(
            pxh, pwqkv + (size_t)l*ls3, pbqkv + (size_t)l*QS_,
            nullptr, pqkvh, D_, QS_);

        if (l == 0) {
            wprep<<<dim3(D_/32, D_/32, NLAYERS), dim3(32, 8)>>>(Wo, pwo, D_, D_, (long)D_*D_);
            wprep<<<dim3(F_/32, D_/32, NLAYERS), dim3(32, 8)>>>(W1, pw1, D_, F_, (long)D_*F_);
            wprep<<<dim3(D_/32, F_/32, NLAYERS), dim3(32, 8)>>>(W2, pw2, F_, D_, (long)F_*D_);
        }

        flash_mma<<<gA, 256, AT_SMEM>>>(pqkvh, weights, poh);

        gemm_mma<false, true, false><<<gD, 256, GSMEM_BYTES>>>(
            poh, pwo + (size_t)l*D_*D_, bo + (size_t)l*D_,
            pres, nullptr, D_, D_);
        add_ln<<<ROWS, 256>>>(px, pres, g1 + (size_t)l*D_, be1 + (size_t)l*D_,
                              px, pxh);

        gemm_mma<true, false, true><<<gF, 256, GSMEM_BYTES>>>(
            pxh, pw1 + (size_t)l*D_*F_, b1 + (size_t)l*F_,
            nullptr, pfh, D_, F_);
        gemm_mma<false, true, false><<<gD, 256, GSMEM_BYTES>>>(
            pfh, pw2 + (size_t)l*F_*D_, b2 + (size_t)l*D_,
            pres, nullptr, F_, D_);
        float* xo = (l == NLAYERS - 1) ? (float*)d_out : px;
        add_ln<<<ROWS, 256>>>(px, pres, g2 + (size_t)l*D_, be2 + (size_t)l*D_,
                              xo, pxh);
    }
}